// round 1
// baseline (speedup 1.0000x reference)
#include <cuda_runtime.h>
#include <math.h>

#define Bv   1024
#define Tv   128
#define Dv   128
#define Hv   4
#define HDv  32
#define FFv  512
#define BT   (Bv*Tv)          // 131072 tokens
#define SCALE 0.08838834764831845f   // 128^-0.5 (full embed dim, per reference)

// ---------------- scratch (device globals; no allocation allowed) ----------
__device__ float g_h   [BT*Dv];
__device__ float g_q   [BT*Dv];
__device__ float g_k   [BT*Dv];
__device__ float g_v   [BT*Dv];
__device__ float g_attn[BT*Dv];
__device__ float g_x2  [BT*Dv];
__device__ float g_h2  [BT*Dv];
__device__ float g_ff1 [BT*FFv];

// ---------------- LayerNorm: one block per token, 128 threads --------------
__global__ __launch_bounds__(128) void ln_kernel(
    const float* __restrict__ x, const float* __restrict__ g,
    const float* __restrict__ b, float* __restrict__ out)
{
    int row = blockIdx.x;
    int tid = threadIdx.x;
    float v = x[(size_t)row * Dv + tid];

    __shared__ float ws[4], ws2[4];
    int w = tid >> 5, l = tid & 31;

    float s = v;
    #pragma unroll
    for (int o = 16; o > 0; o >>= 1) s += __shfl_xor_sync(0xffffffffu, s, o);
    if (l == 0) ws[w] = s;
    __syncthreads();
    float mean = (ws[0] + ws[1] + ws[2] + ws[3]) * (1.0f / Dv);

    float d = v - mean;
    float s2 = d * d;
    #pragma unroll
    for (int o = 16; o > 0; o >>= 1) s2 += __shfl_xor_sync(0xffffffffu, s2, o);
    if (l == 0) ws2[w] = s2;
    __syncthreads();
    float var = (ws2[0] + ws2[1] + ws2[2] + ws2[3]) * (1.0f / Dv);

    float r = rsqrtf(var + 1e-5f);
    out[(size_t)row * Dv + tid] = d * r * g[tid] + b[tid];
}

// ---------------- SGEMM: C[M,N] = A[M,K] @ W[N,K]^T (+bias)(+res)(relu) ----
// BM=BN=128, BK=16, 256 threads, 8x8 microtile per thread.
// All problem dims here are multiples of the tiles (M=131072, N in {128,512},
// K in {128,512}) so no bounds checks.
template<bool BIAS, bool RES, bool RELU>
__global__ __launch_bounds__(256) void gemm_kernel(
    const float* __restrict__ A, const float* __restrict__ W,
    const float* __restrict__ bias, const float* __restrict__ res,
    float* __restrict__ C, int M, int N, int K)
{
    const int BM = 128, BN = 128, BK = 16;
    __shared__ float As[BK][BM + 4];   // stride 132 floats (528B, 16B aligned)
    __shared__ float Ws[BK][BN + 4];

    int tid = threadIdx.x;
    int rowBase = blockIdx.y * BM;
    int colBase = blockIdx.x * BN;
    int tm = tid >> 4;     // 0..15
    int tn = tid & 15;     // 0..15

    float acc[8][8];
    #pragma unroll
    for (int i = 0; i < 8; i++)
        #pragma unroll
        for (int j = 0; j < 8; j++) acc[i][j] = 0.f;

    for (int k0 = 0; k0 < K; k0 += BK) {
        // load A tile 128x16 (512 float4, 2 per thread), store transposed
        #pragma unroll
        for (int i = 0; i < 2; i++) {
            int idx4 = tid + i * 256;
            int m  = idx4 >> 2;
            int kq = idx4 & 3;
            float4 a = *(const float4*)(A + (size_t)(rowBase + m) * K + k0 + kq * 4);
            As[kq*4+0][m] = a.x; As[kq*4+1][m] = a.y;
            As[kq*4+2][m] = a.z; As[kq*4+3][m] = a.w;
        }
        // load W tile 128x16
        #pragma unroll
        for (int i = 0; i < 2; i++) {
            int idx4 = tid + i * 256;
            int n  = idx4 >> 2;
            int kq = idx4 & 3;
            float4 w = *(const float4*)(W + (size_t)(colBase + n) * K + k0 + kq * 4);
            Ws[kq*4+0][n] = w.x; Ws[kq*4+1][n] = w.y;
            Ws[kq*4+2][n] = w.z; Ws[kq*4+3][n] = w.w;
        }
        __syncthreads();

        #pragma unroll
        for (int kk = 0; kk < BK; kk++) {
            float a[8], b[8];
            *(float4*)&a[0] = *(const float4*)&As[kk][tm * 8];
            *(float4*)&a[4] = *(const float4*)&As[kk][tm * 8 + 4];
            *(float4*)&b[0] = *(const float4*)&Ws[kk][tn * 8];
            *(float4*)&b[4] = *(const float4*)&Ws[kk][tn * 8 + 4];
            #pragma unroll
            for (int i = 0; i < 8; i++)
                #pragma unroll
                for (int j = 0; j < 8; j++)
                    acc[i][j] += a[i] * b[j];
        }
        __syncthreads();
    }

    // epilogue
    #pragma unroll
    for (int i = 0; i < 8; i++) {
        int r = rowBase + tm * 8 + i;
        #pragma unroll
        for (int j = 0; j < 8; j += 4) {
            int c = colBase + tn * 8 + j;
            float4 v;
            v.x = acc[i][j]; v.y = acc[i][j+1]; v.z = acc[i][j+2]; v.w = acc[i][j+3];
            if (BIAS) {
                v.x += bias[c];   v.y += bias[c+1];
                v.z += bias[c+2]; v.w += bias[c+3];
            }
            if (RES) {
                float4 rr = *(const float4*)(res + (size_t)r * N + c);
                v.x += rr.x; v.y += rr.y; v.z += rr.z; v.w += rr.w;
            }
            if (RELU) {
                v.x = fmaxf(v.x, 0.f); v.y = fmaxf(v.y, 0.f);
                v.z = fmaxf(v.z, 0.f); v.w = fmaxf(v.w, 0.f);
            }
            *(float4*)(C + (size_t)r * N + c) = v;
        }
    }
}

// ---------------- Fused causal attention: 1 block per (b,head) -------------
// 128 threads, thread t owns query row t. K/V tile (128x32 each) in smem,
// online softmax with registers (32-wide accumulator).
__global__ __launch_bounds__(128) void attn_kernel(
    const float* __restrict__ q, const float* __restrict__ k,
    const float* __restrict__ v, float* __restrict__ o)
{
    int bh  = blockIdx.x;
    int b   = bh >> 2;        // H = 4
    int hh  = bh & 3;
    int tid = threadIdx.x;

    __shared__ float Ks[Tv][HDv];   // 16KB
    __shared__ float Vs[Tv][HDv];   // 16KB

    const float* kb = k + (size_t)b * Tv * Dv + hh * HDv;
    const float* vb = v + (size_t)b * Tv * Dv + hh * HDv;

    // cooperative load of K,V tiles: 1024 float4 each, 8 per thread
    #pragma unroll
    for (int i = 0; i < 8; i++) {
        int idx4 = tid + i * 128;
        int row  = idx4 >> 3;
        int cq   = idx4 & 7;
        *(float4*)&Ks[row][cq * 4] = *(const float4*)(kb + (size_t)row * Dv + cq * 4);
        *(float4*)&Vs[row][cq * 4] = *(const float4*)(vb + (size_t)row * Dv + cq * 4);
    }
    __syncthreads();

    int t = tid;
    float qr[32];
    const float* qp = q + ((size_t)(b * Tv) + t) * Dv + hh * HDv;
    #pragma unroll
    for (int i = 0; i < 8; i++) *(float4*)&qr[i * 4] = *(const float4*)(qp + i * 4);

    float m = -1e30f, l = 0.f;
    float acc[32];
    #pragma unroll
    for (int i = 0; i < 32; i++) acc[i] = 0.f;

    for (int s = 0; s <= t; s++) {
        const float4* kr = (const float4*)&Ks[s][0];
        float dot = 0.f;
        #pragma unroll
        for (int j4 = 0; j4 < 8; j4++) {
            float4 kv = kr[j4];
            dot += qr[j4*4+0] * kv.x + qr[j4*4+1] * kv.y
                 + qr[j4*4+2] * kv.z + qr[j4*4+3] * kv.w;
        }
        dot *= SCALE;
        if (dot > m) {
            float sc = __expf(m - dot);
            l *= sc;
            #pragma unroll
            for (int j = 0; j < 32; j++) acc[j] *= sc;
            m = dot;
        }
        float p = __expf(dot - m);
        l += p;
        const float4* vr = (const float4*)&Vs[s][0];
        #pragma unroll
        for (int j4 = 0; j4 < 8; j4++) {
            float4 vv = vr[j4];
            acc[j4*4+0] += p * vv.x; acc[j4*4+1] += p * vv.y;
            acc[j4*4+2] += p * vv.z; acc[j4*4+3] += p * vv.w;
        }
    }

    float inv = 1.f / l;
    float* op = o + ((size_t)(b * Tv) + t) * Dv + hh * HDv;
    #pragma unroll
    for (int j4 = 0; j4 < 8; j4++) {
        float4 vv;
        vv.x = acc[j4*4+0] * inv; vv.y = acc[j4*4+1] * inv;
        vv.z = acc[j4*4+2] * inv; vv.w = acc[j4*4+3] * inv;
        *(float4*)(op + j4 * 4) = vv;
    }
}

// ---------------- launch ----------------------------------------------------
extern "C" void kernel_launch(void* const* d_in, const int* in_sizes, int n_in,
                              void* d_out, int out_size)
{
    const float* x     = (const float*)d_in[0];
    const float* ln1_g = (const float*)d_in[1];
    const float* ln1_b = (const float*)d_in[2];
    const float* Wq    = (const float*)d_in[3];   // [H,HD,D] = [128,128] flat
    const float* Wk    = (const float*)d_in[4];
    const float* Wv    = (const float*)d_in[5];
    const float* Wo    = (const float*)d_in[6];   // [D,D]
    const float* bo    = (const float*)d_in[7];
    const float* ln2_g = (const float*)d_in[8];
    const float* ln2_b = (const float*)d_in[9];
    const float* W1    = (const float*)d_in[10];  // [FF,D]
    const float* b1    = (const float*)d_in[11];
    const float* W2    = (const float*)d_in[12];  // [D,FF]
    const float* b2    = (const float*)d_in[13];

    float *h, *q, *k, *v, *attn, *x2, *h2, *ff1;
    cudaGetSymbolAddress((void**)&h,    g_h);
    cudaGetSymbolAddress((void**)&q,    g_q);
    cudaGetSymbolAddress((void**)&k,    g_k);
    cudaGetSymbolAddress((void**)&v,    g_v);
    cudaGetSymbolAddress((void**)&attn, g_attn);
    cudaGetSymbolAddress((void**)&x2,   g_x2);
    cudaGetSymbolAddress((void**)&h2,   g_h2);
    cudaGetSymbolAddress((void**)&ff1,  g_ff1);

    float* out = (float*)d_out;

    // 1) LN1
    ln_kernel<<<BT, 128>>>(x, ln1_g, ln1_b, h);

    // 2) QKV projections ([BT,128] @ [128,128]^T), output already in
    //    concat-heads layout [B,T,H,HD]
    dim3 gQKV(1, BT / 128);
    gemm_kernel<false,false,false><<<gQKV, 256>>>(h, Wq, nullptr, nullptr, q, BT, Dv, Dv);
    gemm_kernel<false,false,false><<<gQKV, 256>>>(h, Wk, nullptr, nullptr, k, BT, Dv, Dv);
    gemm_kernel<false,false,false><<<gQKV, 256>>>(h, Wv, nullptr, nullptr, v, BT, Dv, Dv);

    // 3) causal attention per (b,head)
    attn_kernel<<<Bv * Hv, 128>>>(q, k, v, attn);

    // 4) output projection + residual: x2 = attn @ Wo^T + bo + x
    gemm_kernel<true,true,false><<<gQKV, 256>>>(attn, Wo, bo, x, x2, BT, Dv, Dv);

    // 5) LN2
    ln_kernel<<<BT, 128>>>(x2, ln2_g, ln2_b, h2);

    // 6) FFN1: relu(h2 @ W1^T + b1)
    dim3 gF1(FFv / 128, BT / 128);
    gemm_kernel<true,false,true><<<gF1, 256>>>(h2, W1, b1, nullptr, ff1, BT, FFv, Dv);

    // 7) FFN2: out = ff1 @ W2^T + b2 + x2
    gemm_kernel<true,true,false><<<gQKV, 256>>>(ff1, W2, b2, x2, out, BT, Dv, FFv);
}

// round 3
// speedup vs baseline: 1.9516x; 1.9516x over previous
#include <cuda_runtime.h>
#include <cstdint>
#include <math.h>

#define Bv   1024
#define Tv   128
#define Dv   128
#define Hv   4
#define HDv  32
#define FFv  512
#define BT   (Bv*Tv)
#define SCALE 0.08838834764831845f   // 128^-0.5

// ---------------- scratch ----------------
__device__ float g_h   [BT*Dv];
__device__ float g_q   [BT*Dv];
__device__ float g_k   [BT*Dv];
__device__ float g_v   [BT*Dv];
__device__ float g_attn[BT*Dv];
__device__ float g_x2  [BT*Dv];
__device__ float g_h2  [BT*Dv];
__device__ float g_ff1 [BT*FFv];

__device__ __forceinline__ uint32_t to_tf32(float f) {
    uint32_t r;
    asm("cvt.rna.tf32.f32 %0, %1;" : "=r"(r) : "f"(f));
    return r;
}

__device__ __forceinline__ void mma_tf32(float c[4],
    uint32_t a0, uint32_t a1, uint32_t a2, uint32_t a3,
    uint32_t b0, uint32_t b1)
{
    asm volatile(
        "mma.sync.aligned.m16n8k8.row.col.f32.tf32.tf32.f32 "
        "{%0,%1,%2,%3}, {%4,%5,%6,%7}, {%8,%9}, {%0,%1,%2,%3};"
        : "+f"(c[0]), "+f"(c[1]), "+f"(c[2]), "+f"(c[3])
        : "r"(a0), "r"(a1), "r"(a2), "r"(a3), "r"(b0), "r"(b1));
}

// ---------------- LayerNorm ----------------
__global__ __launch_bounds__(128) void ln_kernel(
    const float* __restrict__ x, const float* __restrict__ g,
    const float* __restrict__ b, float* __restrict__ out)
{
    int row = blockIdx.x;
    int tid = threadIdx.x;
    float v = x[(size_t)row * Dv + tid];

    __shared__ float ws[4], ws2[4];
    int w = tid >> 5, l = tid & 31;

    float s = v;
    #pragma unroll
    for (int o = 16; o > 0; o >>= 1) s += __shfl_xor_sync(0xffffffffu, s, o);
    if (l == 0) ws[w] = s;
    __syncthreads();
    float mean = (ws[0] + ws[1] + ws[2] + ws[3]) * (1.0f / Dv);

    float d = v - mean;
    float s2 = d * d;
    #pragma unroll
    for (int o = 16; o > 0; o >>= 1) s2 += __shfl_xor_sync(0xffffffffu, s2, o);
    if (l == 0) ws2[w] = s2;
    __syncthreads();
    float var = (ws2[0] + ws2[1] + ws2[2] + ws2[3]) * (1.0f / Dv);

    float r = rsqrtf(var + 1e-5f);
    out[(size_t)row * Dv + tid] = d * r * g[tid] + b[tid];
}

// ---------------- tf32 mma.sync GEMM: C[M,N] = A[M,K] @ W[N,K]^T ----------
// 128x128 CTA tile, BK=32, 256 threads (8 warps, 2x4), warp tile 64x32.
// Register-prefetch double buffering; smem padded to 36 cols (conflict-free).
#define BKg 32
#define LDS_STRIDE 36

template<bool BIAS, bool RES, bool RELU>
__global__ __launch_bounds__(256) void gemm_mma(
    const float* __restrict__ A, const float* __restrict__ W,
    const float* __restrict__ bias, const float* __restrict__ res,
    float* __restrict__ C, int N, int K)
{
    __shared__ uint32_t As[128][LDS_STRIDE];
    __shared__ uint32_t Ws[128][LDS_STRIDE];

    int tid = threadIdx.x;
    int lane = tid & 31;
    int wid = tid >> 5;
    int warpM = wid >> 2, warpN = wid & 3;
    int mBase = warpM * 64, nBase = warpN * 32;
    int lr = lane >> 2, lc = lane & 3;

    int rowBase = blockIdx.y * 128;
    int colBase = blockIdx.x * 128;

    int ldRow = tid >> 3;        // 0..31 (per i-step covers 32 rows? no: see below)
    int ldC4  = tid & 7;         // float4 index within 32-float row

    float c[4][4][4];
    #pragma unroll
    for (int mf = 0; mf < 4; mf++)
        #pragma unroll
        for (int nf = 0; nf < 4; nf++)
            #pragma unroll
            for (int j = 0; j < 4; j++) c[mf][nf][j] = 0.f;

    // prefetch tile 0
    float4 pa[4], pw[4];
    #pragma unroll
    for (int i = 0; i < 4; i++) {
        int idx4 = tid + i * 256;
        int r = idx4 >> 3, c4 = idx4 & 7;
        pa[i] = *(const float4*)(A + (size_t)(rowBase + r) * K + c4 * 4);
        pw[i] = *(const float4*)(W + (size_t)(colBase + r) * K + c4 * 4);
    }

    for (int k0 = 0; k0 < K; k0 += BKg) {
        // store prefetched tile (convert to tf32)
        #pragma unroll
        for (int i = 0; i < 4; i++) {
            int idx4 = tid + i * 256;
            int r = idx4 >> 3, c4 = idx4 & 7;
            As[r][c4*4+0] = to_tf32(pa[i].x); As[r][c4*4+1] = to_tf32(pa[i].y);
            As[r][c4*4+2] = to_tf32(pa[i].z); As[r][c4*4+3] = to_tf32(pa[i].w);
            Ws[r][c4*4+0] = to_tf32(pw[i].x); Ws[r][c4*4+1] = to_tf32(pw[i].y);
            Ws[r][c4*4+2] = to_tf32(pw[i].z); Ws[r][c4*4+3] = to_tf32(pw[i].w);
        }
        __syncthreads();

        if (k0 + BKg < K) {
            #pragma unroll
            for (int i = 0; i < 4; i++) {
                int idx4 = tid + i * 256;
                int r = idx4 >> 3, c4 = idx4 & 7;
                pa[i] = *(const float4*)(A + (size_t)(rowBase + r) * K + k0 + BKg + c4 * 4);
                pw[i] = *(const float4*)(W + (size_t)(colBase + r) * K + k0 + BKg + c4 * 4);
            }
        }

        #pragma unroll
        for (int kk = 0; kk < 4; kk++) {
            int kA = kk * 8 + lc;
            uint32_t af[4][4];
            #pragma unroll
            for (int mf = 0; mf < 4; mf++) {
                int r0 = mBase + mf * 16 + lr;
                af[mf][0] = As[r0    ][kA    ];
                af[mf][1] = As[r0 + 8][kA    ];
                af[mf][2] = As[r0    ][kA + 4];
                af[mf][3] = As[r0 + 8][kA + 4];
            }
            uint32_t bf[4][2];
            #pragma unroll
            for (int nf = 0; nf < 4; nf++) {
                int n0 = nBase + nf * 8 + lr;
                bf[nf][0] = Ws[n0][kA    ];
                bf[nf][1] = Ws[n0][kA + 4];
            }
            #pragma unroll
            for (int mf = 0; mf < 4; mf++)
                #pragma unroll
                for (int nf = 0; nf < 4; nf++)
                    mma_tf32(c[mf][nf], af[mf][0], af[mf][1], af[mf][2], af[mf][3],
                             bf[nf][0], bf[nf][1]);
        }
        __syncthreads();
    }

    // epilogue
    #pragma unroll
    for (int mf = 0; mf < 4; mf++) {
        #pragma unroll
        for (int rr = 0; rr < 2; rr++) {
            int row = rowBase + mBase + mf * 16 + lr + rr * 8;
            #pragma unroll
            for (int nf = 0; nf < 4; nf++) {
                int col = colBase + nBase + nf * 8 + 2 * lc;
                float2 v;
                v.x = c[mf][nf][rr * 2 + 0];
                v.y = c[mf][nf][rr * 2 + 1];
                if (BIAS) {
                    float2 bb = *(const float2*)(bias + col);
                    v.x += bb.x; v.y += bb.y;
                }
                if (RES) {
                    float2 rv = *(const float2*)(res + (size_t)row * N + col);
                    v.x += rv.x; v.y += rv.y;
                }
                if (RELU) {
                    v.x = fmaxf(v.x, 0.f); v.y = fmaxf(v.y, 0.f);
                }
                *(float2*)(C + (size_t)row * N + col) = v;
            }
        }
    }
}

// ---------------- Fused causal attention ----------------
__global__ __launch_bounds__(128) void attn_kernel(
    const float* __restrict__ q, const float* __restrict__ k,
    const float* __restrict__ v, float* __restrict__ o)
{
    int bh  = blockIdx.x;
    int b   = bh >> 2;
    int hh  = bh & 3;
    int tid = threadIdx.x;

    __shared__ float Ks[Tv][HDv];
    __shared__ float Vs[Tv][HDv];

    const float* kb = k + (size_t)b * Tv * Dv + hh * HDv;
    const float* vb = v + (size_t)b * Tv * Dv + hh * HDv;

    #pragma unroll
    for (int i = 0; i < 8; i++) {
        int idx4 = tid + i * 128;
        int row  = idx4 >> 3;
        int cq   = idx4 & 7;
        *(float4*)&Ks[row][cq * 4] = *(const float4*)(kb + (size_t)row * Dv + cq * 4);
        *(float4*)&Vs[row][cq * 4] = *(const float4*)(vb + (size_t)row * Dv + cq * 4);
    }
    __syncthreads();

    int t = tid;
    float qr[32];
    const float* qp = q + ((size_t)(b * Tv) + t) * Dv + hh * HDv;
    #pragma unroll
    for (int i = 0; i < 8; i++) *(float4*)&qr[i * 4] = *(const float4*)(qp + i * 4);

    float m = -1e30f, l = 0.f;
    float acc[32];
    #pragma unroll
    for (int i = 0; i < 32; i++) acc[i] = 0.f;

    for (int s = 0; s <= t; s++) {
        const float4* kr = (const float4*)&Ks[s][0];
        float dot = 0.f;
        #pragma unroll
        for (int j4 = 0; j4 < 8; j4++) {
            float4 kv = kr[j4];
            dot += qr[j4*4+0] * kv.x + qr[j4*4+1] * kv.y
                 + qr[j4*4+2] * kv.z + qr[j4*4+3] * kv.w;
        }
        dot *= SCALE;
        if (dot > m) {
            float sc = __expf(m - dot);
            l *= sc;
            #pragma unroll
            for (int j = 0; j < 32; j++) acc[j] *= sc;
            m = dot;
        }
        float p = __expf(dot - m);
        l += p;
        const float4* vr = (const float4*)&Vs[s][0];
        #pragma unroll
        for (int j4 = 0; j4 < 8; j4++) {
            float4 vv = vr[j4];
            acc[j4*4+0] += p * vv.x; acc[j4*4+1] += p * vv.y;
            acc[j4*4+2] += p * vv.z; acc[j4*4+3] += p * vv.w;
        }
    }

    float inv = 1.f / l;
    float* op = o + ((size_t)(b * Tv) + t) * Dv + hh * HDv;
    #pragma unroll
    for (int j4 = 0; j4 < 8; j4++) {
        float4 vv;
        vv.x = acc[j4*4+0] * inv; vv.y = acc[j4*4+1] * inv;
        vv.z = acc[j4*4+2] * inv; vv.w = acc[j4*4+3] * inv;
        *(float4*)(op + j4 * 4) = vv;
    }
}

// ---------------- launch ----------------
extern "C" void kernel_launch(void* const* d_in, const int* in_sizes, int n_in,
                              void* d_out, int out_size)
{
    const float* x     = (const float*)d_in[0];
    const float* ln1_g = (const float*)d_in[1];
    const float* ln1_b = (const float*)d_in[2];
    const float* Wq    = (const float*)d_in[3];
    const float* Wk    = (const float*)d_in[4];
    const float* Wv    = (const float*)d_in[5];
    const float* Wo    = (const float*)d_in[6];
    const float* bo    = (const float*)d_in[7];
    const float* ln2_g = (const float*)d_in[8];
    const float* ln2_b = (const float*)d_in[9];
    const float* W1    = (const float*)d_in[10];
    const float* b1    = (const float*)d_in[11];
    const float* W2    = (const float*)d_in[12];
    const float* b2    = (const float*)d_in[13];

    float *h, *q, *k, *v, *attn, *x2, *h2, *ff1;
    cudaGetSymbolAddress((void**)&h,    g_h);
    cudaGetSymbolAddress((void**)&q,    g_q);
    cudaGetSymbolAddress((void**)&k,    g_k);
    cudaGetSymbolAddress((void**)&v,    g_v);
    cudaGetSymbolAddress((void**)&attn, g_attn);
    cudaGetSymbolAddress((void**)&x2,   g_x2);
    cudaGetSymbolAddress((void**)&h2,   g_h2);
    cudaGetSymbolAddress((void**)&ff1,  g_ff1);

    float* out = (float*)d_out;

    // 1) LN1
    ln_kernel<<<BT, 128>>>(x, ln1_g, ln1_b, h);

    // 2) QKV projections (output in concat-heads layout [B,T,H,HD])
    dim3 gQKV(1, BT / 128);
    gemm_mma<false,false,false><<<gQKV, 256>>>(h, Wq, nullptr, nullptr, q, Dv, Dv);
    gemm_mma<false,false,false><<<gQKV, 256>>>(h, Wk, nullptr, nullptr, k, Dv, Dv);
    gemm_mma<false,false,false><<<gQKV, 256>>>(h, Wv, nullptr, nullptr, v, Dv, Dv);

    // 3) causal attention per (b,head)
    attn_kernel<<<Bv * Hv, 128>>>(q, k, v, attn);

    // 4) x2 = attn @ Wo^T + bo + x
    gemm_mma<true,true,false><<<gQKV, 256>>>(attn, Wo, bo, x, x2, Dv, Dv);

    // 5) LN2
    ln_kernel<<<BT, 128>>>(x2, ln2_g, ln2_b, h2);

    // 6) FFN1: relu(h2 @ W1^T + b1)
    dim3 gF1(FFv / 128, BT / 128);
    gemm_mma<true,false,true><<<gF1, 256>>>(h2, W1, b1, nullptr, ff1, FFv, Dv);

    // 7) FFN2: out = ff1 @ W2^T + b2 + x2
    gemm_mma<true,true,false><<<gQKV, 256>>>(ff1, W2, b2, x2, out, Dv, FFv);
}

// round 4
// speedup vs baseline: 2.1653x; 1.1095x over previous
#include <cuda_runtime.h>
#include <cstdint>
#include <math.h>

#define Bv   1024
#define Tv   128
#define Dv   128
#define Hv   4
#define HDv  32
#define FFv  512
#define BT   (Bv*Tv)
#define SCALE 0.08838834764831845f   // 128^-0.5

// ---------------- scratch ----------------
__device__ float g_h   [BT*Dv];
__device__ float g_q   [BT*Dv];
__device__ float g_k   [BT*Dv];
__device__ float g_v   [BT*Dv];
__device__ float g_attn[BT*Dv];
__device__ float g_x2  [BT*Dv];
__device__ float g_h2  [BT*Dv];
__device__ float g_ff1 [BT*FFv];

__device__ __forceinline__ uint32_t smem_u32(const void* p) {
    uint32_t a;
    asm("{ .reg .u64 t; cvta.to.shared.u64 t, %1; cvt.u32.u64 %0, t; }" : "=r"(a) : "l"(p));
    return a;
}

__device__ __forceinline__ void mma_tf32(float c[4],
    uint32_t a0, uint32_t a1, uint32_t a2, uint32_t a3,
    uint32_t b0, uint32_t b1)
{
    asm volatile(
        "mma.sync.aligned.m16n8k8.row.col.f32.tf32.tf32.f32 "
        "{%0,%1,%2,%3}, {%4,%5,%6,%7}, {%8,%9}, {%0,%1,%2,%3};"
        : "+f"(c[0]), "+f"(c[1]), "+f"(c[2]), "+f"(c[3])
        : "r"(a0), "r"(a1), "r"(a2), "r"(a3), "r"(b0), "r"(b1));
}

// ---------------- LayerNorm ----------------
__global__ __launch_bounds__(128) void ln_kernel(
    const float* __restrict__ x, const float* __restrict__ g,
    const float* __restrict__ b, float* __restrict__ out)
{
    int row = blockIdx.x;
    int tid = threadIdx.x;
    float v = x[(size_t)row * Dv + tid];

    __shared__ float ws[4], ws2[4];
    int w = tid >> 5, l = tid & 31;

    float s = v;
    #pragma unroll
    for (int o = 16; o > 0; o >>= 1) s += __shfl_xor_sync(0xffffffffu, s, o);
    if (l == 0) ws[w] = s;
    __syncthreads();
    float mean = (ws[0] + ws[1] + ws[2] + ws[3]) * (1.0f / Dv);

    float d = v - mean;
    float s2 = d * d;
    #pragma unroll
    for (int o = 16; o > 0; o >>= 1) s2 += __shfl_xor_sync(0xffffffffu, s2, o);
    if (l == 0) ws2[w] = s2;
    __syncthreads();
    float var = (ws2[0] + ws2[1] + ws2[2] + ws2[3]) * (1.0f / Dv);

    float r = rsqrtf(var + 1e-5f);
    out[(size_t)row * Dv + tid] = d * r * g[tid] + b[tid];
}

// ---------------- cp.async tf32 GEMM body --------------------------------
// C[M,N] = A[M,K] @ W[N,K]^T, 128x128 CTA tile, BK=32, 2-stage cp.async.
// smem layout (dynamic): A stages @0,@18432 ; W stages @36864,@55296 (73728B)
#define GEMM_SMEM 73728

__device__ __forceinline__ void gemm_issue(uint32_t sbase, int stage,
    const float* A, const float* W, int rowBase, int colBase, int K, int k0, int tid)
{
    #pragma unroll
    for (int i = 0; i < 4; i++) {
        int idx4 = tid + i * 256;
        int r = idx4 >> 3, c4 = idx4 & 7;
        uint32_t da = sbase + stage * 18432 + r * 144 + c4 * 16;
        const void* sa = A + (size_t)(rowBase + r) * K + k0 + c4 * 4;
        asm volatile("cp.async.cg.shared.global [%0], [%1], 16;" :: "r"(da), "l"(sa));
        uint32_t dw = sbase + 36864 + stage * 18432 + r * 144 + c4 * 16;
        const void* sw = W + (size_t)(colBase + r) * K + k0 + c4 * 4;
        asm volatile("cp.async.cg.shared.global [%0], [%1], 16;" :: "r"(dw), "l"(sw));
    }
    asm volatile("cp.async.commit_group;" ::: "memory");
}

template<bool BIAS, bool RES, bool RELU>
__device__ __forceinline__ void gemm_body(
    const float* __restrict__ A, const float* __restrict__ W,
    const float* __restrict__ bias, const float* __restrict__ res,
    float* __restrict__ C, int N, int K, int rowBase, int colBase, char* dsm)
{
    uint32_t sbase = smem_u32(dsm);
    int tid = threadIdx.x;
    int lane = tid & 31;
    int wid = tid >> 5;
    int warpM = wid >> 2, warpN = wid & 3;
    int mBase = warpM * 64, nBase = warpN * 32;
    int lr = lane >> 2, lc = lane & 3;

    float c[4][4][4];
    #pragma unroll
    for (int mf = 0; mf < 4; mf++)
        #pragma unroll
        for (int nf = 0; nf < 4; nf++)
            #pragma unroll
            for (int j = 0; j < 4; j++) c[mf][nf][j] = 0.f;

    gemm_issue(sbase, 0, A, W, rowBase, colBase, K, 0, tid);

    int nCh = K >> 5;
    for (int ch = 0; ch < nCh; ch++) {
        int stage = ch & 1;
        if (ch + 1 < nCh) {
            gemm_issue(sbase, stage ^ 1, A, W, rowBase, colBase, K, (ch + 1) << 5, tid);
            asm volatile("cp.async.wait_group 1;" ::: "memory");
        } else {
            asm volatile("cp.async.wait_group 0;" ::: "memory");
        }
        __syncthreads();

        const uint32_t* As = (const uint32_t*)(dsm + stage * 18432);
        const uint32_t* Ws = (const uint32_t*)(dsm + 36864 + stage * 18432);

        #pragma unroll
        for (int kk = 0; kk < 4; kk++) {
            int kA = kk * 8 + lc;
            uint32_t af[4][4];
            #pragma unroll
            for (int mf = 0; mf < 4; mf++) {
                int r0 = mBase + mf * 16 + lr;
                af[mf][0] = As[r0 * 36 + kA];
                af[mf][1] = As[(r0 + 8) * 36 + kA];
                af[mf][2] = As[r0 * 36 + kA + 4];
                af[mf][3] = As[(r0 + 8) * 36 + kA + 4];
            }
            uint32_t bf[4][2];
            #pragma unroll
            for (int nf = 0; nf < 4; nf++) {
                int n0 = nBase + nf * 8 + lr;
                bf[nf][0] = Ws[n0 * 36 + kA];
                bf[nf][1] = Ws[n0 * 36 + kA + 4];
            }
            #pragma unroll
            for (int mf = 0; mf < 4; mf++)
                #pragma unroll
                for (int nf = 0; nf < 4; nf++)
                    mma_tf32(c[mf][nf], af[mf][0], af[mf][1], af[mf][2], af[mf][3],
                             bf[nf][0], bf[nf][1]);
        }
        __syncthreads();
    }

    #pragma unroll
    for (int mf = 0; mf < 4; mf++) {
        #pragma unroll
        for (int rr = 0; rr < 2; rr++) {
            int row = rowBase + mBase + mf * 16 + lr + rr * 8;
            #pragma unroll
            for (int nf = 0; nf < 4; nf++) {
                int col = colBase + nBase + nf * 8 + 2 * lc;
                float2 v;
                v.x = c[mf][nf][rr * 2 + 0];
                v.y = c[mf][nf][rr * 2 + 1];
                if (BIAS) {
                    float2 bb = *(const float2*)(bias + col);
                    v.x += bb.x; v.y += bb.y;
                }
                if (RES) {
                    float2 rv = *(const float2*)(res + (size_t)row * N + col);
                    v.x += rv.x; v.y += rv.y;
                }
                if (RELU) {
                    v.x = fmaxf(v.x, 0.f); v.y = fmaxf(v.y, 0.f);
                }
                *(float2*)(C + (size_t)row * N + col) = v;
            }
        }
    }
}

template<bool BIAS, bool RES, bool RELU>
__global__ __launch_bounds__(256, 2) void gemm_cp(
    const float* __restrict__ A, const float* __restrict__ W,
    const float* __restrict__ bias, const float* __restrict__ res,
    float* __restrict__ C, int N, int K)
{
    extern __shared__ char dsm[];
    gemm_body<BIAS, RES, RELU>(A, W, bias, res, C, N, K,
                               blockIdx.y * 128, blockIdx.x * 128, dsm);
}

// fused QKV: grid (3, BT/128); blockIdx.x selects weight/output
__global__ __launch_bounds__(256, 2) void qkv_gemm(
    const float* __restrict__ A,
    const float* __restrict__ Wq, const float* __restrict__ Wk, const float* __restrict__ Wv,
    float* __restrict__ q, float* __restrict__ k, float* __restrict__ v)
{
    extern __shared__ char dsm[];
    const float* W = (blockIdx.x == 0) ? Wq : (blockIdx.x == 1) ? Wk : Wv;
    float* C       = (blockIdx.x == 0) ? q  : (blockIdx.x == 1) ? k  : v;
    gemm_body<false, false, false>(A, W, nullptr, nullptr, C, Dv, Dv,
                                   blockIdx.y * 128, 0, dsm);
}

// ---------------- Tensor-core causal flash attention ----------------------
// One CTA (256 thr, 8 warps) per (b,head). Warp w owns query rows 16w..16w+15.
// smem: Ks u32[128][36] @0 (18432), Vt u32[32][132] @18432 (16896),
//       Ss f32[128][132] @35328 (67584), ls f32[128] @102912 (512) = 103424B
#define ATTN_SMEM 103424

__global__ __launch_bounds__(256, 2) void attn_tc(
    const float* __restrict__ q, const float* __restrict__ k,
    const float* __restrict__ v, float* __restrict__ o)
{
    extern __shared__ char dsm[];
    uint32_t* Ks = (uint32_t*)dsm;                 // [128][36]
    uint32_t* Vt = (uint32_t*)(dsm + 18432);       // [32][132]
    float*    Ss = (float*)(dsm + 35328);          // [128][132]
    float*    ls = (float*)(dsm + 102912);         // [128]

    int bh = blockIdx.x;
    int b = bh >> 2, hh = bh & 3;
    int tid = threadIdx.x, lane = tid & 31, w = tid >> 5;
    int lr = lane >> 2, lc = lane & 3;

    const float* kg = k + ((size_t)b * Tv) * Dv + hh * HDv;
    const float* vg = v + ((size_t)b * Tv) * Dv + hh * HDv;

    // K tile -> Ks[s][c] (raw fp32 bits, truncated to tf32 by HW)
    #pragma unroll
    for (int i = 0; i < 4; i++) {
        int idx4 = tid + i * 256;
        int s = idx4 >> 3, c4 = idx4 & 7;
        float4 kv = *(const float4*)(kg + (size_t)s * Dv + c4 * 4);
        uint32_t* d = Ks + s * 36 + c4 * 4;
        d[0] = __float_as_uint(kv.x); d[1] = __float_as_uint(kv.y);
        d[2] = __float_as_uint(kv.z); d[3] = __float_as_uint(kv.w);
    }
    // V tile transposed -> Vt[hd][s]
    #pragma unroll
    for (int i = 0; i < 4; i++) {
        int idx = tid + i * 256;
        int s = idx & 127, hd4 = idx >> 7;
        float4 vv = *(const float4*)(vg + (size_t)s * Dv + hd4 * 4);
        Vt[(hd4 * 4 + 0) * 132 + s] = __float_as_uint(vv.x);
        Vt[(hd4 * 4 + 1) * 132 + s] = __float_as_uint(vv.y);
        Vt[(hd4 * 4 + 2) * 132 + s] = __float_as_uint(vv.z);
        Vt[(hd4 * 4 + 3) * 132 + s] = __float_as_uint(vv.w);
    }
    __syncthreads();

    int tq0 = w * 16;
    const float* qg = q + ((size_t)b * Tv) * Dv + hh * HDv;

    // Q A-fragments straight from gmem
    uint32_t qa[4][4];
    #pragma unroll
    for (int st = 0; st < 4; st++) {
        int kA = st * 8 + lc;
        qa[st][0] = __float_as_uint(qg[(size_t)(tq0 + lr) * Dv + kA]);
        qa[st][1] = __float_as_uint(qg[(size_t)(tq0 + 8 + lr) * Dv + kA]);
        qa[st][2] = __float_as_uint(qg[(size_t)(tq0 + lr) * Dv + kA + 4]);
        qa[st][3] = __float_as_uint(qg[(size_t)(tq0 + 8 + lr) * Dv + kA + 4]);
    }

    // S = Q @ K^T (two 64-col halves to cap register pressure)
    #pragma unroll
    for (int half = 0; half < 2; half++) {
        float sacc[8][4];
        #pragma unroll
        for (int cn = 0; cn < 8; cn++)
            #pragma unroll
            for (int j = 0; j < 4; j++) sacc[cn][j] = 0.f;

        #pragma unroll
        for (int st = 0; st < 4; st++) {
            int kA = st * 8 + lc;
            #pragma unroll
            for (int cn = 0; cn < 8; cn++) {
                int n0 = half * 64 + cn * 8;
                uint32_t b0 = Ks[(n0 + lr) * 36 + kA];
                uint32_t b1 = Ks[(n0 + lr) * 36 + kA + 4];
                mma_tf32(sacc[cn], qa[st][0], qa[st][1], qa[st][2], qa[st][3], b0, b1);
            }
        }
        int r0 = tq0 + lr, r1 = r0 + 8;
        #pragma unroll
        for (int cn = 0; cn < 8; cn++) {
            int c0 = half * 64 + cn * 8 + 2 * lc;
            Ss[r0 * 132 + c0]     = (c0     <= r0) ? sacc[cn][0] * SCALE : -1e30f;
            Ss[r0 * 132 + c0 + 1] = (c0 + 1 <= r0) ? sacc[cn][1] * SCALE : -1e30f;
            Ss[r1 * 132 + c0]     = (c0     <= r1) ? sacc[cn][2] * SCALE : -1e30f;
            Ss[r1 * 132 + c0 + 1] = (c0 + 1 <= r1) ? sacc[cn][3] * SCALE : -1e30f;
        }
    }
    __syncwarp();

    // row softmax (warp-wide per row)
    #pragma unroll
    for (int j = 0; j < 16; j++) {
        int row = tq0 + j;
        float4 vv = *(float4*)(Ss + row * 132 + lane * 4);
        float m = fmaxf(fmaxf(vv.x, vv.y), fmaxf(vv.z, vv.w));
        #pragma unroll
        for (int off = 16; off > 0; off >>= 1)
            m = fmaxf(m, __shfl_xor_sync(0xffffffffu, m, off));
        float p0 = __expf(vv.x - m), p1 = __expf(vv.y - m);
        float p2 = __expf(vv.z - m), p3 = __expf(vv.w - m);
        float s = p0 + p1 + p2 + p3;
        #pragma unroll
        for (int off = 16; off > 0; off >>= 1)
            s += __shfl_xor_sync(0xffffffffu, s, off);
        *(float4*)(Ss + row * 132 + lane * 4) = make_float4(p0, p1, p2, p3);
        if (lane == 0) ls[row] = 1.f / s;
    }
    __syncwarp();

    // O = P @ V
    float oacc[4][4];
    #pragma unroll
    for (int cn = 0; cn < 4; cn++)
        #pragma unroll
        for (int j = 0; j < 4; j++) oacc[cn][j] = 0.f;

    #pragma unroll
    for (int ks = 0; ks < 16; ks++) {
        int kA = ks * 8 + lc;
        uint32_t a0 = __float_as_uint(Ss[(tq0 + lr) * 132 + kA]);
        uint32_t a1 = __float_as_uint(Ss[(tq0 + 8 + lr) * 132 + kA]);
        uint32_t a2 = __float_as_uint(Ss[(tq0 + lr) * 132 + kA + 4]);
        uint32_t a3 = __float_as_uint(Ss[(tq0 + 8 + lr) * 132 + kA + 4]);
        #pragma unroll
        for (int cn = 0; cn < 4; cn++) {
            uint32_t b0 = Vt[(cn * 8 + lr) * 132 + kA];
            uint32_t b1 = Vt[(cn * 8 + lr) * 132 + kA + 4];
            mma_tf32(oacc[cn], a0, a1, a2, a3, b0, b1);
        }
    }

    float li0 = ls[tq0 + lr], li1 = ls[tq0 + 8 + lr];
    float* og = o + ((size_t)b * Tv) * Dv + hh * HDv;
    #pragma unroll
    for (int cn = 0; cn < 4; cn++) {
        int c0 = cn * 8 + 2 * lc;
        *(float2*)(og + (size_t)(tq0 + lr) * Dv + c0) =
            make_float2(oacc[cn][0] * li0, oacc[cn][1] * li0);
        *(float2*)(og + (size_t)(tq0 + 8 + lr) * Dv + c0) =
            make_float2(oacc[cn][2] * li1, oacc[cn][3] * li1);
    }
}

// ---------------- launch ----------------
extern "C" void kernel_launch(void* const* d_in, const int* in_sizes, int n_in,
                              void* d_out, int out_size)
{
    const float* x     = (const float*)d_in[0];
    const float* ln1_g = (const float*)d_in[1];
    const float* ln1_b = (const float*)d_in[2];
    const float* Wq    = (const float*)d_in[3];
    const float* Wk    = (const float*)d_in[4];
    const float* Wv    = (const float*)d_in[5];
    const float* Wo    = (const float*)d_in[6];
    const float* bo    = (const float*)d_in[7];
    const float* ln2_g = (const float*)d_in[8];
    const float* ln2_b = (const float*)d_in[9];
    const float* W1    = (const float*)d_in[10];
    const float* b1    = (const float*)d_in[11];
    const float* W2    = (const float*)d_in[12];
    const float* b2    = (const float*)d_in[13];

    float *h, *q, *k, *v, *attn, *x2, *h2, *ff1;
    cudaGetSymbolAddress((void**)&h,    g_h);
    cudaGetSymbolAddress((void**)&q,    g_q);
    cudaGetSymbolAddress((void**)&k,    g_k);
    cudaGetSymbolAddress((void**)&v,    g_v);
    cudaGetSymbolAddress((void**)&attn, g_attn);
    cudaGetSymbolAddress((void**)&x2,   g_x2);
    cudaGetSymbolAddress((void**)&h2,   g_h2);
    cudaGetSymbolAddress((void**)&ff1,  g_ff1);

    float* out = (float*)d_out;

    static bool attrs_set = false;
    if (!attrs_set) {
        cudaFuncSetAttribute(qkv_gemm, cudaFuncAttributeMaxDynamicSharedMemorySize, GEMM_SMEM);
        cudaFuncSetAttribute(gemm_cp<true,true,false>,  cudaFuncAttributeMaxDynamicSharedMemorySize, GEMM_SMEM);
        cudaFuncSetAttribute(gemm_cp<true,false,true>,  cudaFuncAttributeMaxDynamicSharedMemorySize, GEMM_SMEM);
        cudaFuncSetAttribute(attn_tc, cudaFuncAttributeMaxDynamicSharedMemorySize, ATTN_SMEM);
        attrs_set = true;
    }

    // 1) LN1
    ln_kernel<<<BT, 128>>>(x, ln1_g, ln1_b, h);

    // 2) fused QKV projections
    dim3 gQKV3(3, BT / 128);
    qkv_gemm<<<gQKV3, 256, GEMM_SMEM>>>(h, Wq, Wk, Wv, q, k, v);

    // 3) tensor-core causal attention per (b,head)
    attn_tc<<<Bv * Hv, 256, ATTN_SMEM>>>(q, k, v, attn);

    // 4) x2 = attn @ Wo^T + bo + x
    dim3 gD(1, BT / 128);
    gemm_cp<true,true,false><<<gD, 256, GEMM_SMEM>>>(attn, Wo, bo, x, x2, Dv, Dv);

    // 5) LN2
    ln_kernel<<<BT, 128>>>(x2, ln2_g, ln2_b, h2);

    // 6) FFN1: relu(h2 @ W1^T + b1)
    dim3 gF1(FFv / 128, BT / 128);
    gemm_cp<true,false,true><<<gF1, 256, GEMM_SMEM>>>(h2, W1, b1, nullptr, ff1, FFv, Dv);

    // 7) FFN2: out = ff1 @ W2^T + b2 + x2
    gemm_cp<true,true,false><<<gD, 256, GEMM_SMEM>>>(ff1, W2, b2, x2, out, Dv, FFv);
}

// round 5
// speedup vs baseline: 2.8872x; 1.3334x over previous
#include <cuda_runtime.h>
#include <cuda_fp16.h>
#include <cstdint>
#include <math.h>

#define Bv   1024
#define Tv   128
#define Dv   128
#define Hv   4
#define HDv  32
#define FFv  512
#define BT   (Bv*Tv)
#define SCALE 0.08838834764831845f   // 128^-0.5

// ---------------- scratch (device globals) ----------------
__device__ __align__(256) __half g_q16   [BT*Dv];
__device__ __align__(256) __half g_k16   [BT*Dv];
__device__ __align__(256) __half g_v16   [BT*Dv];
__device__ __align__(256) __half g_attn16[BT*Dv];
__device__ __align__(256) __half g_ff16  [BT*FFv];
__device__ __align__(256) float  g_x2    [BT*Dv];
__device__ __align__(256) __half g_wq16[Dv*Dv];
__device__ __align__(256) __half g_wk16[Dv*Dv];
__device__ __align__(256) __half g_wv16[Dv*Dv];
__device__ __align__(256) __half g_wo16[Dv*Dv];
__device__ __align__(256) __half g_w116[FFv*Dv];
__device__ __align__(256) __half g_w216[Dv*FFv];

// ---------------- PTX helpers ----------------
__device__ __forceinline__ uint32_t smem_u32(const void* p) {
    uint32_t a;
    asm("{ .reg .u64 t; cvta.to.shared.u64 t, %1; cvt.u32.u64 %0, t; }" : "=r"(a) : "l"(p));
    return a;
}
__device__ __forceinline__ void cp16(uint32_t dst, const void* src) {
    asm volatile("cp.async.cg.shared.global [%0], [%1], 16;" :: "r"(dst), "l"(src));
}
__device__ __forceinline__ void ldsm4(uint32_t (&r)[4], uint32_t addr) {
    asm volatile("ldmatrix.sync.aligned.m8n8.x4.shared.b16 {%0,%1,%2,%3}, [%4];"
        : "=r"(r[0]), "=r"(r[1]), "=r"(r[2]), "=r"(r[3]) : "r"(addr));
}
__device__ __forceinline__ void mma_f16(float* c,
    uint32_t a0, uint32_t a1, uint32_t a2, uint32_t a3, uint32_t b0, uint32_t b1)
{
    asm volatile(
        "mma.sync.aligned.m16n8k16.row.col.f32.f16.f16.f32 "
        "{%0,%1,%2,%3}, {%4,%5,%6,%7}, {%8,%9}, {%0,%1,%2,%3};"
        : "+f"(c[0]), "+f"(c[1]), "+f"(c[2]), "+f"(c[3])
        : "r"(a0), "r"(a1), "r"(a2), "r"(a3), "r"(b0), "r"(b1));
}

// ---------------- weight fp32 -> fp16 conversion ----------------
__global__ void cvt6(const float* __restrict__ wq, const float* __restrict__ wk,
                     const float* __restrict__ wv, const float* __restrict__ wo,
                     const float* __restrict__ w1, const float* __restrict__ w2)
{
    const float* src; __half* dst; int n;
    switch (blockIdx.y) {
        case 0: src = wq; dst = g_wq16; n = Dv*Dv;  break;
        case 1: src = wk; dst = g_wk16; n = Dv*Dv;  break;
        case 2: src = wv; dst = g_wv16; n = Dv*Dv;  break;
        case 3: src = wo; dst = g_wo16; n = Dv*Dv;  break;
        case 4: src = w1; dst = g_w116; n = FFv*Dv; break;
        default: src = w2; dst = g_w216; n = Dv*FFv; break;
    }
    for (int i = blockIdx.x * blockDim.x + threadIdx.x; i < n; i += gridDim.x * blockDim.x)
        dst[i] = __float2half_rn(src[i]);
}

// ---------------- K=128 fp16 GEMM body -------------------------------------
// C[128,?] = A[128,128] @ W[128,128]^T (+bias)(+res)(relu), optional fused LN on A.
// smem: As half[128][136] @0 (34816B), Ws half[128][136] @34816. Total 69632B.
#define G128_SMEM 69632

template<bool LN, bool BIAS, bool RES, bool RELU, bool OUTHALF>
__device__ __forceinline__ void g128_body(
    const float* __restrict__ Af, const __half* __restrict__ Ah,
    const __half* __restrict__ W,
    const float* __restrict__ lng, const float* __restrict__ lnb,
    const float* __restrict__ bias, const float* __restrict__ res,
    __half* __restrict__ Ch, float* __restrict__ Cf,
    int ldC, int rowBase, int colBase, char* dsm)
{
    uint32_t sb = smem_u32(dsm);
    const uint32_t WOFF = 34816;
    int tid = threadIdx.x, lane = tid & 31, wid = tid >> 5;

    // W tile (fp16, 16B chunks)
    #pragma unroll
    for (int i = 0; i < 8; i++) {
        int idx = tid + i * 256;
        int r = idx >> 4, cc = idx & 15;
        cp16(sb + WOFF + r * 272 + cc * 16, W + (size_t)r * 128 + cc * 8);
    }
    asm volatile("cp.async.commit_group;" ::: "memory");

    if (LN) {
        int row = tid >> 1, hf = tid & 1;
        const float* xr = Af + (size_t)(rowBase + row) * 128 + hf * 64;
        float s = 0.f, s2 = 0.f;
        #pragma unroll
        for (int i = 0; i < 16; i++) {
            float4 v = *(const float4*)(xr + i * 4);
            s  += v.x + v.y + v.z + v.w;
            s2 += v.x * v.x + v.y * v.y + v.z * v.z + v.w * v.w;
        }
        s  += __shfl_xor_sync(0xffffffffu, s, 1);
        s2 += __shfl_xor_sync(0xffffffffu, s2, 1);
        float mu = s * (1.f / 128.f);
        float rstd = rsqrtf(s2 * (1.f / 128.f) - mu * mu + 1e-5f);
        #pragma unroll
        for (int i = 0; i < 16; i++) {
            float4 v = *(const float4*)(xr + i * 4);
            int col = hf * 64 + i * 4;
            float4 gg = *(const float4*)(lng + col);
            float4 bb = *(const float4*)(lnb + col);
            __half2 h0 = __floats2half2_rn((v.x - mu) * rstd * gg.x + bb.x,
                                           (v.y - mu) * rstd * gg.y + bb.y);
            __half2 h1 = __floats2half2_rn((v.z - mu) * rstd * gg.z + bb.z,
                                           (v.w - mu) * rstd * gg.w + bb.w);
            *(__half2*)(dsm + row * 272 + col * 2)     = h0;
            *(__half2*)(dsm + row * 272 + col * 2 + 4) = h1;
        }
    } else {
        #pragma unroll
        for (int i = 0; i < 8; i++) {
            int idx = tid + i * 256;
            int r = idx >> 4, cc = idx & 15;
            cp16(sb + r * 272 + cc * 16, Ah + (size_t)(rowBase + r) * 128 + cc * 8);
        }
        asm volatile("cp.async.commit_group;" ::: "memory");
    }
    asm volatile("cp.async.wait_group 0;" ::: "memory");
    __syncthreads();

    int warpM = wid >> 2, warpN = wid & 3;
    int mBase = warpM * 64, nBase = warpN * 32;
    int g8 = lane & 7, sel = (lane >> 3) & 1, hi = lane >> 4;

    uint32_t aBase = sb + ((mBase + g8 + sel * 8) * 136 + hi * 8) * 2;
    uint32_t bBase = sb + WOFF + ((nBase + g8 + hi * 8) * 136 + sel * 8) * 2;

    float c[4][4][4];
    #pragma unroll
    for (int mf = 0; mf < 4; mf++)
        #pragma unroll
        for (int nf = 0; nf < 4; nf++)
            #pragma unroll
            for (int j = 0; j < 4; j++) c[mf][nf][j] = 0.f;

    #pragma unroll
    for (int ks = 0; ks < 8; ks++) {
        uint32_t a[4][4];
        #pragma unroll
        for (int mf = 0; mf < 4; mf++)
            ldsm4(a[mf], aBase + mf * 4352 + ks * 32);
        uint32_t bq[2][4];
        #pragma unroll
        for (int p = 0; p < 2; p++)
            ldsm4(bq[p], bBase + p * 4352 + ks * 32);
        #pragma unroll
        for (int mf = 0; mf < 4; mf++)
            #pragma unroll
            for (int nf = 0; nf < 4; nf++)
                mma_f16(c[mf][nf], a[mf][0], a[mf][1], a[mf][2], a[mf][3],
                        bq[nf >> 1][(nf & 1) * 2], bq[nf >> 1][(nf & 1) * 2 + 1]);
    }

    int eg = lane >> 2, et = lane & 3;
    #pragma unroll
    for (int mf = 0; mf < 4; mf++) {
        #pragma unroll
        for (int rr = 0; rr < 2; rr++) {
            int row = rowBase + mBase + mf * 16 + eg + rr * 8;
            #pragma unroll
            for (int nf = 0; nf < 4; nf++) {
                int col = colBase + nBase + nf * 8 + 2 * et;
                float v0 = c[mf][nf][rr * 2 + 0];
                float v1 = c[mf][nf][rr * 2 + 1];
                if (BIAS) { v0 += bias[col]; v1 += bias[col + 1]; }
                if (RES) {
                    float2 rv = *(const float2*)(res + (size_t)row * ldC + col);
                    v0 += rv.x; v1 += rv.y;
                }
                if (RELU) { v0 = fmaxf(v0, 0.f); v1 = fmaxf(v1, 0.f); }
                if (OUTHALF)
                    *(__half2*)(Ch + (size_t)row * ldC + col) = __floats2half2_rn(v0, v1);
                else
                    *(float2*)(Cf + (size_t)row * ldC + col) = make_float2(v0, v1);
            }
        }
    }
}

// wrappers
__global__ __launch_bounds__(256, 2) void k_qkv(
    const float* __restrict__ x, const float* __restrict__ g, const float* __restrict__ b)
{
    extern __shared__ char dsm[];
    const __half* W = (blockIdx.x == 0) ? g_wq16 : (blockIdx.x == 1) ? g_wk16 : g_wv16;
    __half* C       = (blockIdx.x == 0) ? g_q16  : (blockIdx.x == 1) ? g_k16  : g_v16;
    g128_body<true, false, false, false, true>(
        x, nullptr, W, g, b, nullptr, nullptr, C, nullptr, 128, blockIdx.y * 128, 0, dsm);
}
__global__ __launch_bounds__(256, 2) void k_wo(
    const float* __restrict__ x, const float* __restrict__ bo)
{
    extern __shared__ char dsm[];
    g128_body<false, true, true, false, false>(
        nullptr, g_attn16, g_wo16, nullptr, nullptr, bo, x, nullptr, g_x2,
        128, blockIdx.y * 128, 0, dsm);
}
__global__ __launch_bounds__(256, 2) void k_ffn1(
    const float* __restrict__ g, const float* __restrict__ b, const float* __restrict__ b1)
{
    extern __shared__ char dsm[];
    int colBase = blockIdx.x * 128;
    g128_body<true, true, false, true, true>(
        g_x2, nullptr, g_w116 + (size_t)colBase * 128, g, b, b1, nullptr,
        g_ff16, nullptr, 512, blockIdx.y * 128, colBase, dsm);
}

// ---------------- FFN2: K=512 chunked fp16 GEMM ----------------------------
// smem: A stages @0,@18432 ; W stages @36864,@55296 (rows padded to 72 halfs)
#define FFN2_SMEM 73728

__device__ __forceinline__ void ffn2_issue(uint32_t sb, int st, int ch, int rowBase, int tid)
{
    #pragma unroll
    for (int i = 0; i < 4; i++) {
        int idx = tid + i * 256;
        int r = idx >> 3, cc = idx & 7;
        cp16(sb + st * 18432 + r * 144 + cc * 16,
             g_ff16 + (size_t)(rowBase + r) * 512 + ch * 64 + cc * 8);
        cp16(sb + 36864 + st * 18432 + r * 144 + cc * 16,
             g_w216 + (size_t)r * 512 + ch * 64 + cc * 8);
    }
    asm volatile("cp.async.commit_group;" ::: "memory");
}

__global__ __launch_bounds__(256, 2) void k_ffn2(
    const float* __restrict__ b2, float* __restrict__ out)
{
    extern __shared__ char dsm[];
    uint32_t sb = smem_u32(dsm);
    int tid = threadIdx.x, lane = tid & 31, wid = tid >> 5;
    int rowBase = blockIdx.y * 128;
    int warpM = wid >> 2, warpN = wid & 3;
    int mBase = warpM * 64, nBase = warpN * 32;
    int g8 = lane & 7, sel = (lane >> 3) & 1, hi = lane >> 4;

    float c[4][4][4];
    #pragma unroll
    for (int mf = 0; mf < 4; mf++)
        #pragma unroll
        for (int nf = 0; nf < 4; nf++)
            #pragma unroll
            for (int j = 0; j < 4; j++) c[mf][nf][j] = 0.f;

    ffn2_issue(sb, 0, 0, rowBase, tid);

    for (int ch = 0; ch < 8; ch++) {
        int st = ch & 1;
        if (ch < 7) {
            ffn2_issue(sb, st ^ 1, ch + 1, rowBase, tid);
            asm volatile("cp.async.wait_group 1;" ::: "memory");
        } else {
            asm volatile("cp.async.wait_group 0;" ::: "memory");
        }
        __syncthreads();

        uint32_t aB = sb + st * 18432 + ((mBase + g8 + sel * 8) * 72 + hi * 8) * 2;
        uint32_t bB = sb + 36864 + st * 18432 + ((nBase + g8 + hi * 8) * 72 + sel * 8) * 2;

        #pragma unroll
        for (int ks = 0; ks < 4; ks++) {
            uint32_t a[4][4];
            #pragma unroll
            for (int mf = 0; mf < 4; mf++)
                ldsm4(a[mf], aB + mf * 2304 + ks * 32);
            uint32_t bq[2][4];
            #pragma unroll
            for (int p = 0; p < 2; p++)
                ldsm4(bq[p], bB + p * 2304 + ks * 32);
            #pragma unroll
            for (int mf = 0; mf < 4; mf++)
                #pragma unroll
                for (int nf = 0; nf < 4; nf++)
                    mma_f16(c[mf][nf], a[mf][0], a[mf][1], a[mf][2], a[mf][3],
                            bq[nf >> 1][(nf & 1) * 2], bq[nf >> 1][(nf & 1) * 2 + 1]);
        }
        __syncthreads();
    }

    int eg = lane >> 2, et = lane & 3;
    #pragma unroll
    for (int mf = 0; mf < 4; mf++) {
        #pragma unroll
        for (int rr = 0; rr < 2; rr++) {
            int row = rowBase + mBase + mf * 16 + eg + rr * 8;
            #pragma unroll
            for (int nf = 0; nf < 4; nf++) {
                int col = nBase + nf * 8 + 2 * et;
                float v0 = c[mf][nf][rr * 2 + 0] + b2[col];
                float v1 = c[mf][nf][rr * 2 + 1] + b2[col + 1];
                float2 rv = *(const float2*)(g_x2 + (size_t)row * 128 + col);
                v0 += rv.x; v1 += rv.y;
                *(float2*)(out + (size_t)row * 128 + col) = make_float2(v0, v1);
            }
        }
    }
}

// ---------------- fp16 tensor-core causal attention ------------------------
// smem: Ks half[128][40] @0 (10240), Vt half[32][136] @10240 (8704),
//       S float[128][132] @18944 (67584), ls float[128] @86528 (512) = 87040
#define ATTN_SMEM 87040

__global__ __launch_bounds__(256, 2) void k_attn()
{
    extern __shared__ char dsm[];
    uint32_t sb = smem_u32(dsm);
    __half* Vt = (__half*)(dsm + 10240);
    float*  S  = (float*)(dsm + 18944);
    float*  ls = (float*)(dsm + 86528);

    int bh = blockIdx.x;
    int b = bh >> 2, hh = bh & 3;
    int tid = threadIdx.x, lane = tid & 31, w = tid >> 5;
    size_t base = (size_t)b * 128 * 128 + hh * 32;

    // K tile via cp.async (rows padded to 40 halfs)
    #pragma unroll
    for (int i = 0; i < 2; i++) {
        int idx = tid + i * 256;
        int r = idx >> 2, cc = idx & 3;
        cp16(sb + r * 80 + cc * 16, g_k16 + base + (size_t)r * 128 + cc * 8);
    }
    asm volatile("cp.async.commit_group;" ::: "memory");

    // V transposed (Vt[hd][s])
    #pragma unroll
    for (int i = 0; i < 8; i++) {
        int idx = tid + i * 256;
        int s = idx & 127, hp = idx >> 7;
        __half2 v2 = *(const __half2*)(g_v16 + base + (size_t)s * 128 + hp * 2);
        Vt[(hp * 2) * 136 + s]     = __low2half(v2);
        Vt[(hp * 2 + 1) * 136 + s] = __high2half(v2);
    }
    asm volatile("cp.async.wait_group 0;" ::: "memory");
    __syncthreads();

    int tq0 = w * 16;
    int g8 = lane & 7, sel = (lane >> 3) & 1, hi = lane >> 4;
    int eg = lane >> 2, et = lane & 3;
    const __half* qb = g_q16 + base;

    // S = Q @ K^T (fp16, 2 k16 slabs), scale + causal mask
    float sacc[16][4];
    #pragma unroll
    for (int cn = 0; cn < 16; cn++)
        #pragma unroll
        for (int j = 0; j < 4; j++) sacc[cn][j] = 0.f;

    #pragma unroll
    for (int ks = 0; ks < 2; ks++) {
        int kc = ks * 16 + 2 * et;
        uint32_t a0 = *(const uint32_t*)(qb + (size_t)(tq0 + eg) * 128 + kc);
        uint32_t a1 = *(const uint32_t*)(qb + (size_t)(tq0 + 8 + eg) * 128 + kc);
        uint32_t a2 = *(const uint32_t*)(qb + (size_t)(tq0 + eg) * 128 + kc + 8);
        uint32_t a3 = *(const uint32_t*)(qb + (size_t)(tq0 + 8 + eg) * 128 + kc + 8);
        #pragma unroll
        for (int p = 0; p < 8; p++) {
            uint32_t bq[4];
            ldsm4(bq, sb + ((p * 16 + g8 + hi * 8) * 40 + sel * 8 + ks * 16) * 2);
            mma_f16(sacc[2 * p],     a0, a1, a2, a3, bq[0], bq[1]);
            mma_f16(sacc[2 * p + 1], a0, a1, a2, a3, bq[2], bq[3]);
        }
    }
    #pragma unroll
    for (int cn = 0; cn < 16; cn++) {
        int c0 = cn * 8 + 2 * et;
        int r0 = tq0 + eg, r1 = r0 + 8;
        S[r0 * 132 + c0]     = (c0     <= r0) ? sacc[cn][0] * SCALE : -1e30f;
        S[r0 * 132 + c0 + 1] = (c0 + 1 <= r0) ? sacc[cn][1] * SCALE : -1e30f;
        S[r1 * 132 + c0]     = (c0     <= r1) ? sacc[cn][2] * SCALE : -1e30f;
        S[r1 * 132 + c0 + 1] = (c0 + 1 <= r1) ? sacc[cn][3] * SCALE : -1e30f;
    }
    __syncwarp();

    // softmax per row; write P as halves into row start of S buffer
    #pragma unroll
    for (int j = 0; j < 16; j++) {
        int row = tq0 + j;
        float4 vv = *(const float4*)(S + row * 132 + lane * 4);
        float m = fmaxf(fmaxf(vv.x, vv.y), fmaxf(vv.z, vv.w));
        #pragma unroll
        for (int off = 16; off > 0; off >>= 1)
            m = fmaxf(m, __shfl_xor_sync(0xffffffffu, m, off));
        float p0 = __expf(vv.x - m), p1 = __expf(vv.y - m);
        float p2 = __expf(vv.z - m), p3 = __expf(vv.w - m);
        float s = p0 + p1 + p2 + p3;
        #pragma unroll
        for (int off = 16; off > 0; off >>= 1)
            s += __shfl_xor_sync(0xffffffffu, s, off);
        __syncwarp();
        char* rb = (char*)(S + row * 132);
        *(__half2*)(rb + lane * 8)     = __floats2half2_rn(p0, p1);
        *(__half2*)(rb + lane * 8 + 4) = __floats2half2_rn(p2, p3);
        if (lane == 0) ls[row] = 1.f / s;
    }
    __syncwarp();

    // O = P @ V  (8 k16 slabs over s)
    float oacc[4][4];
    #pragma unroll
    for (int nf = 0; nf < 4; nf++)
        #pragma unroll
        for (int j = 0; j < 4; j++) oacc[nf][j] = 0.f;

    uint32_t pB = sb + 18944 + (tq0 + g8 + sel * 8) * 528 + hi * 16;
    uint32_t vB = sb + 10240 + ((g8 + hi * 8) * 136 + sel * 8) * 2;
    #pragma unroll
    for (int ks = 0; ks < 8; ks++) {
        uint32_t a[4];
        ldsm4(a, pB + ks * 32);
        #pragma unroll
        for (int p = 0; p < 2; p++) {
            uint32_t bq[4];
            ldsm4(bq, vB + p * 4352 + ks * 32);
            mma_f16(oacc[2 * p],     a[0], a[1], a[2], a[3], bq[0], bq[1]);
            mma_f16(oacc[2 * p + 1], a[0], a[1], a[2], a[3], bq[2], bq[3]);
        }
    }

    float li0 = ls[tq0 + eg], li1 = ls[tq0 + 8 + eg];
    __half* og = g_attn16 + base;
    #pragma unroll
    for (int nf = 0; nf < 4; nf++) {
        int c0 = nf * 8 + 2 * et;
        *(__half2*)(og + (size_t)(tq0 + eg) * 128 + c0) =
            __floats2half2_rn(oacc[nf][0] * li0, oacc[nf][1] * li0);
        *(__half2*)(og + (size_t)(tq0 + 8 + eg) * 128 + c0) =
            __floats2half2_rn(oacc[nf][2] * li1, oacc[nf][3] * li1);
    }
}

// ---------------- launch ----------------
extern "C" void kernel_launch(void* const* d_in, const int* in_sizes, int n_in,
                              void* d_out, int out_size)
{
    const float* x     = (const float*)d_in[0];
    const float* ln1_g = (const float*)d_in[1];
    const float* ln1_b = (const float*)d_in[2];
    const float* Wq    = (const float*)d_in[3];
    const float* Wk    = (const float*)d_in[4];
    const float* Wv    = (const float*)d_in[5];
    const float* Wo    = (const float*)d_in[6];
    const float* bo    = (const float*)d_in[7];
    const float* ln2_g = (const float*)d_in[8];
    const float* ln2_b = (const float*)d_in[9];
    const float* W1    = (const float*)d_in[10];
    const float* b1    = (const float*)d_in[11];
    const float* W2    = (const float*)d_in[12];
    const float* b2    = (const float*)d_in[13];
    float* out = (float*)d_out;

    static bool attrs_set = false;
    if (!attrs_set) {
        cudaFuncSetAttribute(k_qkv,  cudaFuncAttributeMaxDynamicSharedMemorySize, G128_SMEM);
        cudaFuncSetAttribute(k_wo,   cudaFuncAttributeMaxDynamicSharedMemorySize, G128_SMEM);
        cudaFuncSetAttribute(k_ffn1, cudaFuncAttributeMaxDynamicSharedMemorySize, G128_SMEM);
        cudaFuncSetAttribute(k_ffn2, cudaFuncAttributeMaxDynamicSharedMemorySize, FFN2_SMEM);
        cudaFuncSetAttribute(k_attn, cudaFuncAttributeMaxDynamicSharedMemorySize, ATTN_SMEM);
        attrs_set = true;
    }

    // 0) weights -> fp16
    cvt6<<<dim3(32, 6), 256>>>(Wq, Wk, Wv, Wo, W1, W2);

    // 1) LN1 fused + QKV projections (fp16 out, concat-heads layout)
    k_qkv<<<dim3(3, BT / 128), 256, G128_SMEM>>>(x, ln1_g, ln1_b);

    // 2) causal attention per (b,head), fp16 tensor cores
    k_attn<<<Bv * Hv, 256, ATTN_SMEM>>>();

    // 3) x2 = attn @ Wo^T + bo + x  (fp32 out)
    k_wo<<<dim3(1, BT / 128), 256, G128_SMEM>>>(x, bo);

    // 4) LN2 fused + FFN1: ff1 = relu(LN(x2) @ W1^T + b1) (fp16 out)
    k_ffn1<<<dim3(FFv / 128, BT / 128), 256, G128_SMEM>>>(ln2_g, ln2_b, b1);

    // 5) out = ff1 @ W2^T + b2 + x2
    k_ffn2<<<dim3(1, BT / 128), 256, FFN2_SMEM>>>(b2, out);
}

// round 6
// speedup vs baseline: 3.9093x; 1.3540x over previous
#include <cuda_runtime.h>
#include <cuda_fp16.h>
#include <cstdint>
#include <math.h>

#define Bv   1024
#define Tv   128
#define Dv   128
#define Hv   4
#define HDv  32
#define FFv  512
#define BT   (Bv*Tv)
#define SCALE 0.08838834764831845f   // 128^-0.5

// ---------------- scratch (device globals) ----------------
__device__ __align__(256) __half g_q16 [BT*Dv];
__device__ __align__(256) __half g_k16 [BT*Dv];
__device__ __align__(256) __half g_v16 [BT*Dv];
__device__ __align__(256) __half g_ff16[BT*FFv];
__device__ __align__(256) float  g_x2  [BT*Dv];
__device__ __align__(256) __half g_wq16[Dv*Dv];
__device__ __align__(256) __half g_wk16[Dv*Dv];
__device__ __align__(256) __half g_wv16[Dv*Dv];
__device__ __align__(256) __half g_wo16[Dv*Dv];
__device__ __align__(256) __half g_w116[FFv*Dv];
__device__ __align__(256) __half g_w216[Dv*FFv];

// ---------------- PTX helpers ----------------
__device__ __forceinline__ uint32_t smem_u32(const void* p) {
    uint32_t a;
    asm("{ .reg .u64 t; cvta.to.shared.u64 t, %1; cvt.u32.u64 %0, t; }" : "=r"(a) : "l"(p));
    return a;
}
__device__ __forceinline__ void cp16(uint32_t dst, const void* src) {
    asm volatile("cp.async.cg.shared.global [%0], [%1], 16;" :: "r"(dst), "l"(src));
}
__device__ __forceinline__ void ldsm4(uint32_t (&r)[4], uint32_t addr) {
    asm volatile("ldmatrix.sync.aligned.m8n8.x4.shared.b16 {%0,%1,%2,%3}, [%4];"
        : "=r"(r[0]), "=r"(r[1]), "=r"(r[2]), "=r"(r[3]) : "r"(addr));
}
__device__ __forceinline__ void ldsm4t(uint32_t (&r)[4], uint32_t addr) {
    asm volatile("ldmatrix.sync.aligned.m8n8.x4.trans.shared.b16 {%0,%1,%2,%3}, [%4];"
        : "=r"(r[0]), "=r"(r[1]), "=r"(r[2]), "=r"(r[3]) : "r"(addr));
}
__device__ __forceinline__ void mma_f16(float* c,
    uint32_t a0, uint32_t a1, uint32_t a2, uint32_t a3, uint32_t b0, uint32_t b1)
{
    asm volatile(
        "mma.sync.aligned.m16n8k16.row.col.f32.f16.f16.f32 "
        "{%0,%1,%2,%3}, {%4,%5,%6,%7}, {%8,%9}, {%0,%1,%2,%3};"
        : "+f"(c[0]), "+f"(c[1]), "+f"(c[2]), "+f"(c[3])
        : "r"(a0), "r"(a1), "r"(a2), "r"(a3), "r"(b0), "r"(b1));
}
__device__ __forceinline__ uint32_t h2u(float a, float b) {
    __half2 h = __floats2half2_rn(a, b);
    return *(uint32_t*)&h;
}

// ---------------- weight fp32 -> fp16 conversion ----------------
__global__ void cvt6(const float* __restrict__ wq, const float* __restrict__ wk,
                     const float* __restrict__ wv, const float* __restrict__ wo,
                     const float* __restrict__ w1, const float* __restrict__ w2)
{
    const float* src; __half* dst; int n;
    switch (blockIdx.y) {
        case 0: src = wq; dst = g_wq16; n = Dv*Dv;  break;
        case 1: src = wk; dst = g_wk16; n = Dv*Dv;  break;
        case 2: src = wv; dst = g_wv16; n = Dv*Dv;  break;
        case 3: src = wo; dst = g_wo16; n = Dv*Dv;  break;
        case 4: src = w1; dst = g_w116; n = FFv*Dv; break;
        default: src = w2; dst = g_w216; n = Dv*FFv; break;
    }
    for (int i = blockIdx.x * blockDim.x + threadIdx.x; i < n; i += gridDim.x * blockDim.x)
        dst[i] = __float2half_rn(src[i]);
}

// ============ shared K=128 GEMM micro-kernel pieces ============
// smem tiles half[128][136] (row stride 272B). 8 warps as 2x4, warp tile 64x32.

struct Frag { int g8, sel, hi, eg, et, mBase, nBase; };
__device__ __forceinline__ Frag mkfrag(int tid) {
    Frag f;
    int lane = tid & 31, wid = tid >> 5;
    f.g8 = lane & 7; f.sel = (lane >> 3) & 1; f.hi = lane >> 4;
    f.eg = lane >> 2; f.et = lane & 3;
    f.mBase = (wid >> 2) * 64; f.nBase = (wid & 3) * 32;
    return f;
}

// full-K (128) GEMM from As,Ws smem into c[4][4][4]
__device__ __forceinline__ void g128_mma(uint32_t sb, uint32_t woff, const Frag& f,
                                         float c[4][4][4])
{
    uint32_t aBase = sb + ((f.mBase + f.g8 + f.sel * 8) * 136 + f.hi * 8) * 2;
    uint32_t bBase = sb + woff + ((f.nBase + f.g8 + f.hi * 8) * 136 + f.sel * 8) * 2;
    #pragma unroll
    for (int ks = 0; ks < 8; ks++) {
        uint32_t a[4][4];
        #pragma unroll
        for (int mf = 0; mf < 4; mf++)
            ldsm4(a[mf], aBase + mf * 4352 + ks * 32);
        uint32_t bq[2][4];
        #pragma unroll
        for (int p = 0; p < 2; p++)
            ldsm4(bq[p], bBase + p * 4352 + ks * 32);
        #pragma unroll
        for (int mf = 0; mf < 4; mf++)
            #pragma unroll
            for (int nf = 0; nf < 4; nf++)
                mma_f16(c[mf][nf], a[mf][0], a[mf][1], a[mf][2], a[mf][3],
                        bq[nf >> 1][(nf & 1) * 2], bq[nf >> 1][(nf & 1) * 2 + 1]);
    }
}

// LN of 128 fp32 cols into As smem (all 256 threads; 2 threads per row)
__device__ __forceinline__ void ln_to_smem(char* dsm, const float* __restrict__ X,
    const float* __restrict__ lng, const float* __restrict__ lnb, int rowBase, int tid)
{
    int row = tid >> 1, hf = tid & 1;
    const float* xr = X + (size_t)(rowBase + row) * 128 + hf * 64;
    float s = 0.f, s2 = 0.f;
    #pragma unroll
    for (int i = 0; i < 16; i++) {
        float4 v = *(const float4*)(xr + i * 4);
        s  += v.x + v.y + v.z + v.w;
        s2 += v.x * v.x + v.y * v.y + v.z * v.z + v.w * v.w;
    }
    s  += __shfl_xor_sync(0xffffffffu, s, 1);
    s2 += __shfl_xor_sync(0xffffffffu, s2, 1);
    float mu = s * (1.f / 128.f);
    float rstd = rsqrtf(s2 * (1.f / 128.f) - mu * mu + 1e-5f);
    #pragma unroll
    for (int i = 0; i < 16; i++) {
        float4 v = *(const float4*)(xr + i * 4);
        int col = hf * 64 + i * 4;
        float4 gg = *(const float4*)(lng + col);
        float4 bb = *(const float4*)(lnb + col);
        *(uint32_t*)(dsm + row * 272 + col * 2)     = h2u((v.x - mu) * rstd * gg.x + bb.x,
                                                          (v.y - mu) * rstd * gg.y + bb.y);
        *(uint32_t*)(dsm + row * 272 + col * 2 + 4) = h2u((v.z - mu) * rstd * gg.z + bb.z,
                                                          (v.w - mu) * rstd * gg.w + bb.w);
    }
}

__device__ __forceinline__ void issue_w128(uint32_t sb, uint32_t off,
                                           const __half* __restrict__ W, int tid)
{
    #pragma unroll
    for (int i = 0; i < 8; i++) {
        int idx = tid + i * 256;
        int r = idx >> 4, cc = idx & 15;
        cp16(sb + off + r * 272 + cc * 16, W + (size_t)r * 128 + cc * 8);
    }
    asm volatile("cp.async.commit_group;" ::: "memory");
}

// ---------------- fused LN1 + QKV (one pass over x) ------------------------
#define QKV_SMEM 69632
__global__ __launch_bounds__(256, 2) void k_qkv3(
    const float* __restrict__ x, const float* __restrict__ g, const float* __restrict__ b)
{
    extern __shared__ char dsm[];
    uint32_t sb = smem_u32(dsm);
    int tid = threadIdx.x;
    int rowBase = blockIdx.x * 128;
    Frag f = mkfrag(tid);

    issue_w128(sb, 34816, g_wq16, tid);
    ln_to_smem(dsm, x, g, b, rowBase, tid);

    const __half* Ws[3] = { g_wq16, g_wk16, g_wv16 };
    __half* outs[3];
    outs[0] = g_q16; outs[1] = g_k16; outs[2] = g_v16;

    #pragma unroll
    for (int wsel = 0; wsel < 3; wsel++) {
        asm volatile("cp.async.wait_group 0;" ::: "memory");
        __syncthreads();

        float c[4][4][4];
        #pragma unroll
        for (int mf = 0; mf < 4; mf++)
            #pragma unroll
            for (int nf = 0; nf < 4; nf++)
                #pragma unroll
                for (int j = 0; j < 4; j++) c[mf][nf][j] = 0.f;

        g128_mma(sb, 34816, f, c);
        __syncthreads();
        if (wsel < 2) issue_w128(sb, 34816, Ws[wsel + 1], tid);

        __half* C = outs[wsel];
        #pragma unroll
        for (int mf = 0; mf < 4; mf++)
            #pragma unroll
            for (int rr = 0; rr < 2; rr++) {
                int row = rowBase + f.mBase + mf * 16 + f.eg + rr * 8;
                #pragma unroll
                for (int nf = 0; nf < 4; nf++) {
                    int col = f.nBase + nf * 8 + 2 * f.et;
                    *(uint32_t*)(C + (size_t)row * 128 + col) =
                        h2u(c[mf][nf][rr * 2], c[mf][nf][rr * 2 + 1]);
                }
            }
    }
}

// ---------------- fused attention (4 heads) + Wo + residual ----------------
// 1 CTA per batch b. smem: K[128][136]h @0, V[128][136]h @34816, AO @69632.
#define ATTNWO_SMEM 104448
__global__ __launch_bounds__(256, 2) void k_attnwo(
    const float* __restrict__ x, const float* __restrict__ bo)
{
    extern __shared__ char dsm[];
    uint32_t sb = smem_u32(dsm);
    const uint32_t VOFF = 34816, AOFF = 69632;
    int b = blockIdx.x;
    int tid = threadIdx.x, lane = tid & 31, w = tid >> 5;
    int g8 = lane & 7, sel = (lane >> 3) & 1, hi8 = (lane >> 4) * 8;
    int eg = lane >> 2, et = lane & 3;
    int tq0 = w * 16;
    size_t base = (size_t)b * Tv * Dv;

    // load K,V (all heads) via cp.async
    #pragma unroll
    for (int i = 0; i < 8; i++) {
        int idx = tid + i * 256;
        int r = idx >> 4, cc = idx & 15;
        cp16(sb + r * 272 + cc * 16,        g_k16 + base + (size_t)r * 128 + cc * 8);
        cp16(sb + VOFF + r * 272 + cc * 16, g_v16 + base + (size_t)r * 128 + cc * 8);
    }
    asm volatile("cp.async.commit_group;" ::: "memory");
    asm volatile("cp.async.wait_group 0;" ::: "memory");
    __syncthreads();

    const __half* qb = g_q16 + base;
    int r0 = tq0 + eg, r1 = r0 + 8;

    #pragma unroll
    for (int hh = 0; hh < 4; hh++) {
        // ---- S = Q K^T (regs) ----
        float sacc[16][4];
        #pragma unroll
        for (int cn = 0; cn < 16; cn++)
            #pragma unroll
            for (int j = 0; j < 4; j++) sacc[cn][j] = 0.f;

        #pragma unroll
        for (int ks = 0; ks < 2; ks++) {
            int kc = hh * 32 + ks * 16 + 2 * et;
            uint32_t a0 = *(const uint32_t*)(qb + (size_t)r0 * 128 + kc);
            uint32_t a1 = *(const uint32_t*)(qb + (size_t)r1 * 128 + kc);
            uint32_t a2 = *(const uint32_t*)(qb + (size_t)r0 * 128 + kc + 8);
            uint32_t a3 = *(const uint32_t*)(qb + (size_t)r1 * 128 + kc + 8);
            #pragma unroll
            for (int p = 0; p < 8; p++) {
                uint32_t bq[4];
                ldsm4(bq, sb + ((p * 16 + g8 + hi8) * 136 + hh * 32 + sel * 8 + ks * 16) * 2);
                mma_f16(sacc[2 * p],     a0, a1, a2, a3, bq[0], bq[1]);
                mma_f16(sacc[2 * p + 1], a0, a1, a2, a3, bq[2], bq[3]);
            }
        }

        // ---- scale + causal mask ----
        #pragma unroll
        for (int cn = 0; cn < 16; cn++) {
            int c0 = cn * 8 + 2 * et;
            sacc[cn][0] = (c0     <= r0) ? sacc[cn][0] * SCALE : -1e30f;
            sacc[cn][1] = (c0 + 1 <= r0) ? sacc[cn][1] * SCALE : -1e30f;
            sacc[cn][2] = (c0     <= r1) ? sacc[cn][2] * SCALE : -1e30f;
            sacc[cn][3] = (c0 + 1 <= r1) ? sacc[cn][3] * SCALE : -1e30f;
        }

        // ---- softmax in registers (quad shuffles: row lives in 4 lanes) ----
        float m0 = -1e30f, m1 = -1e30f;
        #pragma unroll
        for (int cn = 0; cn < 16; cn++) {
            m0 = fmaxf(m0, fmaxf(sacc[cn][0], sacc[cn][1]));
            m1 = fmaxf(m1, fmaxf(sacc[cn][2], sacc[cn][3]));
        }
        m0 = fmaxf(m0, __shfl_xor_sync(0xffffffffu, m0, 1));
        m0 = fmaxf(m0, __shfl_xor_sync(0xffffffffu, m0, 2));
        m1 = fmaxf(m1, __shfl_xor_sync(0xffffffffu, m1, 1));
        m1 = fmaxf(m1, __shfl_xor_sync(0xffffffffu, m1, 2));

        float l0 = 0.f, l1 = 0.f;
        #pragma unroll
        for (int cn = 0; cn < 16; cn++) {
            sacc[cn][0] = __expf(sacc[cn][0] - m0);
            sacc[cn][1] = __expf(sacc[cn][1] - m0);
            sacc[cn][2] = __expf(sacc[cn][2] - m1);
            sacc[cn][3] = __expf(sacc[cn][3] - m1);
            l0 += sacc[cn][0] + sacc[cn][1];
            l1 += sacc[cn][2] + sacc[cn][3];
        }
        l0 += __shfl_xor_sync(0xffffffffu, l0, 1);
        l0 += __shfl_xor_sync(0xffffffffu, l0, 2);
        l1 += __shfl_xor_sync(0xffffffffu, l1, 1);
        l1 += __shfl_xor_sync(0xffffffffu, l1, 2);
        float inv0 = 1.f / l0, inv1 = 1.f / l1;

        // ---- O = P V : P A-frags packed straight from sacc regs ----
        float oacc[4][4];
        #pragma unroll
        for (int nf = 0; nf < 4; nf++)
            #pragma unroll
            for (int j = 0; j < 4; j++) oacc[nf][j] = 0.f;

        #pragma unroll
        for (int ks = 0; ks < 8; ks++) {
            uint32_t a0 = h2u(sacc[2*ks][0],   sacc[2*ks][1]);
            uint32_t a1 = h2u(sacc[2*ks][2],   sacc[2*ks][3]);
            uint32_t a2 = h2u(sacc[2*ks+1][0], sacc[2*ks+1][1]);
            uint32_t a3 = h2u(sacc[2*ks+1][2], sacc[2*ks+1][3]);
            #pragma unroll
            for (int nb = 0; nb < 2; nb++) {
                uint32_t bq[4];
                ldsm4t(bq, sb + VOFF +
                    ((ks * 16 + g8 + sel * 8) * 136 + hh * 32 + nb * 16 + hi8) * 2);
                mma_f16(oacc[nb * 2],     a0, a1, a2, a3, bq[0], bq[1]);
                mma_f16(oacc[nb * 2 + 1], a0, a1, a2, a3, bq[2], bq[3]);
            }
        }

        // ---- store head output into AO smem (fp16) ----
        #pragma unroll
        for (int nf = 0; nf < 4; nf++) {
            int col = hh * 32 + nf * 8 + 2 * et;
            *(uint32_t*)(dsm + AOFF + ((size_t)r0 * 136 + col) * 2) =
                h2u(oacc[nf][0] * inv0, oacc[nf][1] * inv0);
            *(uint32_t*)(dsm + AOFF + ((size_t)r1 * 136 + col) * 2) =
                h2u(oacc[nf][2] * inv1, oacc[nf][3] * inv1);
        }
    }
    __syncthreads();

    // ---- Wo GEMM: rows 16w..16w+15, all 128 cols. B-frags LDG from g_wo16 (L1) ----
    float c[16][4];
    #pragma unroll
    for (int nf = 0; nf < 16; nf++)
        #pragma unroll
        for (int j = 0; j < 4; j++) c[nf][j] = 0.f;

    uint32_t aB = sb + AOFF + ((tq0 + g8 + sel * 8) * 136 + hi8) * 2;
    #pragma unroll
    for (int ks = 0; ks < 8; ks++) {
        uint32_t a[4];
        ldsm4(a, aB + ks * 32);
        #pragma unroll
        for (int nf = 0; nf < 16; nf++) {
            uint32_t b0 = *(const uint32_t*)(g_wo16 + (size_t)(nf * 8 + eg) * 128 + ks * 16 + 2 * et);
            uint32_t b1 = *(const uint32_t*)(g_wo16 + (size_t)(nf * 8 + eg) * 128 + ks * 16 + 2 * et + 8);
            mma_f16(c[nf], a[0], a[1], a[2], a[3], b0, b1);
        }
    }

    // epilogue: + bo + x -> x2 (fp32)
    int grow0 = b * 128 + r0, grow1 = b * 128 + r1;
    #pragma unroll
    for (int nf = 0; nf < 16; nf++) {
        int col = nf * 8 + 2 * et;
        float2 bb = *(const float2*)(bo + col);
        float2 xv0 = *(const float2*)(x + (size_t)grow0 * 128 + col);
        float2 xv1 = *(const float2*)(x + (size_t)grow1 * 128 + col);
        *(float2*)(g_x2 + (size_t)grow0 * 128 + col) =
            make_float2(c[nf][0] + bb.x + xv0.x, c[nf][1] + bb.y + xv0.y);
        *(float2*)(g_x2 + (size_t)grow1 * 128 + col) =
            make_float2(c[nf][2] + bb.x + xv1.x, c[nf][3] + bb.y + xv1.y);
    }
}

// ---------------- fused LN2 + FFN1 (one pass over x2, 4 W1 blocks) ---------
#define FFN1_SMEM 69632
__global__ __launch_bounds__(256, 2) void k_ffn1(
    const float* __restrict__ g, const float* __restrict__ b, const float* __restrict__ b1)
{
    extern __shared__ char dsm[];
    uint32_t sb = smem_u32(dsm);
    int tid = threadIdx.x;
    int rowBase = blockIdx.x * 128;
    Frag f = mkfrag(tid);

    issue_w128(sb, 34816, g_w116, tid);
    ln_to_smem(dsm, g_x2, g, b, rowBase, tid);

    #pragma unroll
    for (int blk = 0; blk < 4; blk++) {
        asm volatile("cp.async.wait_group 0;" ::: "memory");
        __syncthreads();

        float c[4][4][4];
        #pragma unroll
        for (int mf = 0; mf < 4; mf++)
            #pragma unroll
            for (int nf = 0; nf < 4; nf++)
                #pragma unroll
                for (int j = 0; j < 4; j++) c[mf][nf][j] = 0.f;

        g128_mma(sb, 34816, f, c);
        __syncthreads();
        if (blk < 3) issue_w128(sb, 34816, g_w116 + (size_t)(blk + 1) * 128 * 128, tid);

        #pragma unroll
        for (int mf = 0; mf < 4; mf++)
            #pragma unroll
            for (int rr = 0; rr < 2; rr++) {
                int row = rowBase + f.mBase + mf * 16 + f.eg + rr * 8;
                #pragma unroll
                for (int nf = 0; nf < 4; nf++) {
                    int col = blk * 128 + f.nBase + nf * 8 + 2 * f.et;
                    float2 bb = *(const float2*)(b1 + col);
                    float v0 = fmaxf(c[mf][nf][rr * 2]     + bb.x, 0.f);
                    float v1 = fmaxf(c[mf][nf][rr * 2 + 1] + bb.y, 0.f);
                    *(uint32_t*)(g_ff16 + (size_t)row * 512 + col) = h2u(v0, v1);
                }
            }
    }
}

// ---------------- FFN2: K=512 chunked fp16 GEMM + bias + residual ----------
#define FFN2_SMEM 73728
__device__ __forceinline__ void ffn2_issue(uint32_t sb, int st, int ch, int rowBase, int tid)
{
    #pragma unroll
    for (int i = 0; i < 4; i++) {
        int idx = tid + i * 256;
        int r = idx >> 3, cc = idx & 7;
        cp16(sb + st * 18432 + r * 144 + cc * 16,
             g_ff16 + (size_t)(rowBase + r) * 512 + ch * 64 + cc * 8);
        cp16(sb + 36864 + st * 18432 + r * 144 + cc * 16,
             g_w216 + (size_t)r * 512 + ch * 64 + cc * 8);
    }
    asm volatile("cp.async.commit_group;" ::: "memory");
}

__global__ __launch_bounds__(256, 2) void k_ffn2(
    const float* __restrict__ b2, float* __restrict__ out)
{
    extern __shared__ char dsm[];
    uint32_t sb = smem_u32(dsm);
    int tid = threadIdx.x, lane = tid & 31, wid = tid >> 5;
    int rowBase = blockIdx.x * 128;
    int mBase = (wid >> 2) * 64, nBase = (wid & 3) * 32;
    int g8 = lane & 7, sel = (lane >> 3) & 1, hi = lane >> 4;

    float c[4][4][4];
    #pragma unroll
    for (int mf = 0; mf < 4; mf++)
        #pragma unroll
        for (int nf = 0; nf < 4; nf++)
            #pragma unroll
            for (int j = 0; j < 4; j++) c[mf][nf][j] = 0.f;

    ffn2_issue(sb, 0, 0, rowBase, tid);

    for (int ch = 0; ch < 8; ch++) {
        int st = ch & 1;
        if (ch < 7) {
            ffn2_issue(sb, st ^ 1, ch + 1, rowBase, tid);
            asm volatile("cp.async.wait_group 1;" ::: "memory");
        } else {
            asm volatile("cp.async.wait_group 0;" ::: "memory");
        }
        __syncthreads();

        uint32_t aB = sb + st * 18432 + ((mBase + g8 + sel * 8) * 72 + hi * 8) * 2;
        uint32_t bB = sb + 36864 + st * 18432 + ((nBase + g8 + hi * 8) * 72 + sel * 8) * 2;

        #pragma unroll
        for (int ks = 0; ks < 4; ks++) {
            uint32_t a[4][4];
            #pragma unroll
            for (int mf = 0; mf < 4; mf++)
                ldsm4(a[mf], aB + mf * 2304 + ks * 32);
            uint32_t bq[2][4];
            #pragma unroll
            for (int p = 0; p < 2; p++)
                ldsm4(bq[p], bB + p * 2304 + ks * 32);
            #pragma unroll
            for (int mf = 0; mf < 4; mf++)
                #pragma unroll
                for (int nf = 0; nf < 4; nf++)
                    mma_f16(c[mf][nf], a[mf][0], a[mf][1], a[mf][2], a[mf][3],
                            bq[nf >> 1][(nf & 1) * 2], bq[nf >> 1][(nf & 1) * 2 + 1]);
        }
        __syncthreads();
    }

    int eg = lane >> 2, et = lane & 3;
    #pragma unroll
    for (int mf = 0; mf < 4; mf++)
        #pragma unroll
        for (int rr = 0; rr < 2; rr++) {
            int row = rowBase + mBase + mf * 16 + eg + rr * 8;
            #pragma unroll
            for (int nf = 0; nf < 4; nf++) {
                int col = nBase + nf * 8 + 2 * et;
                float2 bb = *(const float2*)(b2 + col);
                float2 rv = *(const float2*)(g_x2 + (size_t)row * 128 + col);
                *(float2*)(out + (size_t)row * 128 + col) =
                    make_float2(c[mf][nf][rr * 2]     + bb.x + rv.x,
                                c[mf][nf][rr * 2 + 1] + bb.y + rv.y);
            }
        }
}

// ---------------- launch ----------------
extern "C" void kernel_launch(void* const* d_in, const int* in_sizes, int n_in,
                              void* d_out, int out_size)
{
    const float* x     = (const float*)d_in[0];
    const float* ln1_g = (const float*)d_in[1];
    const float* ln1_b = (const float*)d_in[2];
    const float* Wq    = (const float*)d_in[3];
    const float* Wk    = (const float*)d_in[4];
    const float* Wv    = (const float*)d_in[5];
    const float* Wo    = (const float*)d_in[6];
    const float* bo    = (const float*)d_in[7];
    const float* ln2_g = (const float*)d_in[8];
    const float* ln2_b = (const float*)d_in[9];
    const float* W1    = (const float*)d_in[10];
    const float* b1    = (const float*)d_in[11];
    const float* W2    = (const float*)d_in[12];
    const float* b2    = (const float*)d_in[13];
    float* out = (float*)d_out;

    static bool attrs_set = false;
    if (!attrs_set) {
        cudaFuncSetAttribute(k_qkv3,  cudaFuncAttributeMaxDynamicSharedMemorySize, QKV_SMEM);
        cudaFuncSetAttribute(k_attnwo, cudaFuncAttributeMaxDynamicSharedMemorySize, ATTNWO_SMEM);
        cudaFuncSetAttribute(k_ffn1,  cudaFuncAttributeMaxDynamicSharedMemorySize, FFN1_SMEM);
        cudaFuncSetAttribute(k_ffn2,  cudaFuncAttributeMaxDynamicSharedMemorySize, FFN2_SMEM);
        attrs_set = true;
    }

    // 0) weights -> fp16
    cvt6<<<dim3(32, 6), 256>>>(Wq, Wk, Wv, Wo, W1, W2);

    // 1) LN1 + QKV (single pass over x)
    k_qkv3<<<BT / 128, 256, QKV_SMEM>>>(x, ln1_g, ln1_b);

    // 2) attention (4 heads) + Wo + bo + residual -> x2
    k_attnwo<<<Bv, 256, ATTNWO_SMEM>>>(x, bo);

    // 3) LN2 + FFN1 (single pass over x2)
    k_ffn1<<<BT / 128, 256, FFN1_SMEM>>>(ln2_g, ln2_b, b1);

    // 4) out = ff @ W2^T + b2 + x2
    k_ffn2<<<BT / 128, 256, FFN2_SMEM>>>(b2, out);
}

// round 7
// speedup vs baseline: 3.9674x; 1.0149x over previous
#include <cuda_runtime.h>
#include <cuda_fp16.h>
#include <cstdint>
#include <math.h>

#define Bv   1024
#define Tv   128
#define Dv   128
#define Hv   4
#define HDv  32
#define FFv  512
#define BT   (Bv*Tv)
#define SCALE 0.08838834764831845f   // 128^-0.5

// ---------------- scratch (device globals) ----------------
__device__ __align__(256) __half g_q16 [BT*Dv];
__device__ __align__(256) __half g_k16 [BT*Dv];
__device__ __align__(256) __half g_v16 [BT*Dv];
__device__ __align__(256) float  g_x2  [BT*Dv];
__device__ __align__(256) __half g_wq16[Dv*Dv];
__device__ __align__(256) __half g_wk16[Dv*Dv];
__device__ __align__(256) __half g_wv16[Dv*Dv];
__device__ __align__(256) __half g_wo16[Dv*Dv];
__device__ __align__(256) __half g_w116[FFv*Dv];
__device__ __align__(256) __half g_w216[Dv*FFv];

// ---------------- PTX helpers ----------------
__device__ __forceinline__ uint32_t smem_u32(const void* p) {
    uint32_t a;
    asm("{ .reg .u64 t; cvta.to.shared.u64 t, %1; cvt.u32.u64 %0, t; }" : "=r"(a) : "l"(p));
    return a;
}
__device__ __forceinline__ void cp16(uint32_t dst, const void* src) {
    asm volatile("cp.async.cg.shared.global [%0], [%1], 16;" :: "r"(dst), "l"(src));
}
__device__ __forceinline__ void ldsm4(uint32_t (&r)[4], uint32_t addr) {
    asm volatile("ldmatrix.sync.aligned.m8n8.x4.shared.b16 {%0,%1,%2,%3}, [%4];"
        : "=r"(r[0]), "=r"(r[1]), "=r"(r[2]), "=r"(r[3]) : "r"(addr));
}
__device__ __forceinline__ void ldsm4t(uint32_t (&r)[4], uint32_t addr) {
    asm volatile("ldmatrix.sync.aligned.m8n8.x4.trans.shared.b16 {%0,%1,%2,%3}, [%4];"
        : "=r"(r[0]), "=r"(r[1]), "=r"(r[2]), "=r"(r[3]) : "r"(addr));
}
__device__ __forceinline__ void mma_f16(float* c,
    uint32_t a0, uint32_t a1, uint32_t a2, uint32_t a3, uint32_t b0, uint32_t b1)
{
    asm volatile(
        "mma.sync.aligned.m16n8k16.row.col.f32.f16.f16.f32 "
        "{%0,%1,%2,%3}, {%4,%5,%6,%7}, {%8,%9}, {%0,%1,%2,%3};"
        : "+f"(c[0]), "+f"(c[1]), "+f"(c[2]), "+f"(c[3])
        : "r"(a0), "r"(a1), "r"(a2), "r"(a3), "r"(b0), "r"(b1));
}
__device__ __forceinline__ uint32_t h2u(float a, float b) {
    __half2 h = __floats2half2_rn(a, b);
    return *(uint32_t*)&h;
}

// ---------------- weight fp32 -> fp16 conversion ----------------
__global__ void cvt6(const float* __restrict__ wq, const float* __restrict__ wk,
                     const float* __restrict__ wv, const float* __restrict__ wo,
                     const float* __restrict__ w1, const float* __restrict__ w2)
{
    const float* src; __half* dst; int n;
    switch (blockIdx.y) {
        case 0: src = wq; dst = g_wq16; n = Dv*Dv;  break;
        case 1: src = wk; dst = g_wk16; n = Dv*Dv;  break;
        case 2: src = wv; dst = g_wv16; n = Dv*Dv;  break;
        case 3: src = wo; dst = g_wo16; n = Dv*Dv;  break;
        case 4: src = w1; dst = g_w116; n = FFv*Dv; break;
        default: src = w2; dst = g_w216; n = Dv*FFv; break;
    }
    for (int i = blockIdx.x * blockDim.x + threadIdx.x; i < n; i += gridDim.x * blockDim.x)
        dst[i] = __float2half_rn(src[i]);
}

// ============ shared fragments/pieces (tiles half[128][136], stride 272B) ==
struct Frag { int g8, sel, hi, eg, et, mBase, nBase; };
__device__ __forceinline__ Frag mkfrag(int tid) {
    Frag f;
    int lane = tid & 31, wid = tid >> 5;
    f.g8 = lane & 7; f.sel = (lane >> 3) & 1; f.hi = lane >> 4;
    f.eg = lane >> 2; f.et = lane & 3;
    f.mBase = (wid >> 2) * 64; f.nBase = (wid & 3) * 32;
    return f;
}

// full-K(128) warp GEMM from smem A@aoff, W@woff
__device__ __forceinline__ void g128_mma(uint32_t sb, uint32_t aoff, uint32_t woff,
                                         const Frag& f, float c[4][4][4])
{
    uint32_t aBase = sb + aoff + ((f.mBase + f.g8 + f.sel * 8) * 136 + f.hi * 8) * 2;
    uint32_t bBase = sb + woff + ((f.nBase + f.g8 + f.hi * 8) * 136 + f.sel * 8) * 2;
    #pragma unroll
    for (int ks = 0; ks < 8; ks++) {
        uint32_t a[4][4];
        #pragma unroll
        for (int mf = 0; mf < 4; mf++)
            ldsm4(a[mf], aBase + mf * 4352 + ks * 32);
        uint32_t bq[2][4];
        #pragma unroll
        for (int p = 0; p < 2; p++)
            ldsm4(bq[p], bBase + p * 4352 + ks * 32);
        #pragma unroll
        for (int mf = 0; mf < 4; mf++)
            #pragma unroll
            for (int nf = 0; nf < 4; nf++)
                mma_f16(c[mf][nf], a[mf][0], a[mf][1], a[mf][2], a[mf][3],
                        bq[nf >> 1][(nf & 1) * 2], bq[nf >> 1][(nf & 1) * 2 + 1]);
    }
}

// LN of 128 fp32 cols into smem tile @0
__device__ __forceinline__ void ln_to_smem(char* dsm, const float* __restrict__ X,
    const float* __restrict__ lng, const float* __restrict__ lnb, int rowBase, int tid)
{
    int row = tid >> 1, hf = tid & 1;
    const float* xr = X + (size_t)(rowBase + row) * 128 + hf * 64;
    float s = 0.f, s2 = 0.f;
    #pragma unroll
    for (int i = 0; i < 16; i++) {
        float4 v = *(const float4*)(xr + i * 4);
        s  += v.x + v.y + v.z + v.w;
        s2 += v.x * v.x + v.y * v.y + v.z * v.z + v.w * v.w;
    }
    s  += __shfl_xor_sync(0xffffffffu, s, 1);
    s2 += __shfl_xor_sync(0xffffffffu, s2, 1);
    float mu = s * (1.f / 128.f);
    float rstd = rsqrtf(s2 * (1.f / 128.f) - mu * mu + 1e-5f);
    #pragma unroll
    for (int i = 0; i < 16; i++) {
        float4 v = *(const float4*)(xr + i * 4);
        int col = hf * 64 + i * 4;
        float4 gg = *(const float4*)(lng + col);
        float4 bb = *(const float4*)(lnb + col);
        *(uint32_t*)(dsm + row * 272 + col * 2)     = h2u((v.x - mu) * rstd * gg.x + bb.x,
                                                          (v.y - mu) * rstd * gg.y + bb.y);
        *(uint32_t*)(dsm + row * 272 + col * 2 + 4) = h2u((v.z - mu) * rstd * gg.z + bb.z,
                                                          (v.w - mu) * rstd * gg.w + bb.w);
    }
}

// cp.async a 128x128-half tile with arbitrary gmem row stride (halfs)
__device__ __forceinline__ void issue_w(uint32_t sb, uint32_t off,
                                        const __half* __restrict__ W, int ldw, int tid)
{
    #pragma unroll
    for (int i = 0; i < 8; i++) {
        int idx = tid + i * 256;
        int r = idx >> 4, cc = idx & 15;
        cp16(sb + off + r * 272 + cc * 16, W + (size_t)r * ldw + cc * 8);
    }
}

// ---------------- fused LN1 + QKV (double-buffered weights) ----------------
#define QKV_SMEM 104448
__global__ __launch_bounds__(256, 2) void k_qkv3(
    const float* __restrict__ x, const float* __restrict__ g, const float* __restrict__ b)
{
    extern __shared__ char dsm[];
    uint32_t sb = smem_u32(dsm);
    int tid = threadIdx.x;
    int rowBase = blockIdx.x * 128;
    Frag f = mkfrag(tid);

    const uint32_t WST[2] = { 34816u, 69632u };
    issue_w(sb, WST[0], g_wq16, 128, tid);
    asm volatile("cp.async.commit_group;" ::: "memory");
    issue_w(sb, WST[1], g_wk16, 128, tid);
    asm volatile("cp.async.commit_group;" ::: "memory");

    ln_to_smem(dsm, x, g, b, rowBase, tid);

    __half* outs[3];
    outs[0] = g_q16; outs[1] = g_k16; outs[2] = g_v16;

    #pragma unroll
    for (int wsel = 0; wsel < 3; wsel++) {
        if (wsel < 2) asm volatile("cp.async.wait_group 1;" ::: "memory");
        else          asm volatile("cp.async.wait_group 0;" ::: "memory");
        __syncthreads();

        float c[4][4][4];
        #pragma unroll
        for (int mf = 0; mf < 4; mf++)
            #pragma unroll
            for (int nf = 0; nf < 4; nf++)
                #pragma unroll
                for (int j = 0; j < 4; j++) c[mf][nf][j] = 0.f;

        g128_mma(sb, 0, WST[wsel == 1], f, c);
        __syncthreads();
        if (wsel == 0) {
            issue_w(sb, WST[0], g_wv16, 128, tid);
            asm volatile("cp.async.commit_group;" ::: "memory");
        }

        __half* C = outs[wsel];
        #pragma unroll
        for (int mf = 0; mf < 4; mf++)
            #pragma unroll
            for (int rr = 0; rr < 2; rr++) {
                int row = rowBase + f.mBase + mf * 16 + f.eg + rr * 8;
                #pragma unroll
                for (int nf = 0; nf < 4; nf++) {
                    int col = f.nBase + nf * 8 + 2 * f.et;
                    *(uint32_t*)(C + (size_t)row * 128 + col) =
                        h2u(c[mf][nf][rr * 2], c[mf][nf][rr * 2 + 1]);
                }
            }
    }
}

// ---------------- fused attention (4 heads) + Wo + residual ----------------
#define ATTNWO_SMEM 104448
__global__ __launch_bounds__(256, 2) void k_attnwo(
    const float* __restrict__ x, const float* __restrict__ bo)
{
    extern __shared__ char dsm[];
    uint32_t sb = smem_u32(dsm);
    const uint32_t VOFF = 34816, AOFF = 69632;
    int b = blockIdx.x;
    int tid = threadIdx.x, lane = tid & 31, w = tid >> 5;
    int g8 = lane & 7, sel = (lane >> 3) & 1, hi8 = (lane >> 4) * 8;
    int eg = lane >> 2, et = lane & 3;
    int tq0 = w * 16;
    size_t base = (size_t)b * Tv * Dv;

    #pragma unroll
    for (int i = 0; i < 8; i++) {
        int idx = tid + i * 256;
        int r = idx >> 4, cc = idx & 15;
        cp16(sb + r * 272 + cc * 16,        g_k16 + base + (size_t)r * 128 + cc * 8);
        cp16(sb + VOFF + r * 272 + cc * 16, g_v16 + base + (size_t)r * 128 + cc * 8);
    }
    asm volatile("cp.async.commit_group;" ::: "memory");
    asm volatile("cp.async.wait_group 0;" ::: "memory");
    __syncthreads();

    const __half* qb = g_q16 + base;
    int r0 = tq0 + eg, r1 = r0 + 8;

    #pragma unroll
    for (int hh = 0; hh < 4; hh++) {
        float sacc[16][4];
        #pragma unroll
        for (int cn = 0; cn < 16; cn++)
            #pragma unroll
            for (int j = 0; j < 4; j++) sacc[cn][j] = 0.f;

        #pragma unroll
        for (int ks = 0; ks < 2; ks++) {
            int kc = hh * 32 + ks * 16 + 2 * et;
            uint32_t a0 = *(const uint32_t*)(qb + (size_t)r0 * 128 + kc);
            uint32_t a1 = *(const uint32_t*)(qb + (size_t)r1 * 128 + kc);
            uint32_t a2 = *(const uint32_t*)(qb + (size_t)r0 * 128 + kc + 8);
            uint32_t a3 = *(const uint32_t*)(qb + (size_t)r1 * 128 + kc + 8);
            #pragma unroll
            for (int p = 0; p < 8; p++) {
                uint32_t bq[4];
                ldsm4(bq, sb + ((p * 16 + g8 + hi8) * 136 + hh * 32 + sel * 8 + ks * 16) * 2);
                mma_f16(sacc[2 * p],     a0, a1, a2, a3, bq[0], bq[1]);
                mma_f16(sacc[2 * p + 1], a0, a1, a2, a3, bq[2], bq[3]);
            }
        }

        #pragma unroll
        for (int cn = 0; cn < 16; cn++) {
            int c0 = cn * 8 + 2 * et;
            sacc[cn][0] = (c0     <= r0) ? sacc[cn][0] * SCALE : -1e30f;
            sacc[cn][1] = (c0 + 1 <= r0) ? sacc[cn][1] * SCALE : -1e30f;
            sacc[cn][2] = (c0     <= r1) ? sacc[cn][2] * SCALE : -1e30f;
            sacc[cn][3] = (c0 + 1 <= r1) ? sacc[cn][3] * SCALE : -1e30f;
        }

        float m0 = -1e30f, m1 = -1e30f;
        #pragma unroll
        for (int cn = 0; cn < 16; cn++) {
            m0 = fmaxf(m0, fmaxf(sacc[cn][0], sacc[cn][1]));
            m1 = fmaxf(m1, fmaxf(sacc[cn][2], sacc[cn][3]));
        }
        m0 = fmaxf(m0, __shfl_xor_sync(0xffffffffu, m0, 1));
        m0 = fmaxf(m0, __shfl_xor_sync(0xffffffffu, m0, 2));
        m1 = fmaxf(m1, __shfl_xor_sync(0xffffffffu, m1, 1));
        m1 = fmaxf(m1, __shfl_xor_sync(0xffffffffu, m1, 2));

        float l0 = 0.f, l1 = 0.f;
        #pragma unroll
        for (int cn = 0; cn < 16; cn++) {
            sacc[cn][0] = __expf(sacc[cn][0] - m0);
            sacc[cn][1] = __expf(sacc[cn][1] - m0);
            sacc[cn][2] = __expf(sacc[cn][2] - m1);
            sacc[cn][3] = __expf(sacc[cn][3] - m1);
            l0 += sacc[cn][0] + sacc[cn][1];
            l1 += sacc[cn][2] + sacc[cn][3];
        }
        l0 += __shfl_xor_sync(0xffffffffu, l0, 1);
        l0 += __shfl_xor_sync(0xffffffffu, l0, 2);
        l1 += __shfl_xor_sync(0xffffffffu, l1, 1);
        l1 += __shfl_xor_sync(0xffffffffu, l1, 2);
        float inv0 = 1.f / l0, inv1 = 1.f / l1;

        float oacc[4][4];
        #pragma unroll
        for (int nf = 0; nf < 4; nf++)
            #pragma unroll
            for (int j = 0; j < 4; j++) oacc[nf][j] = 0.f;

        #pragma unroll
        for (int ks = 0; ks < 8; ks++) {
            uint32_t a0 = h2u(sacc[2*ks][0],   sacc[2*ks][1]);
            uint32_t a1 = h2u(sacc[2*ks][2],   sacc[2*ks][3]);
            uint32_t a2 = h2u(sacc[2*ks+1][0], sacc[2*ks+1][1]);
            uint32_t a3 = h2u(sacc[2*ks+1][2], sacc[2*ks+1][3]);
            #pragma unroll
            for (int nb = 0; nb < 2; nb++) {
                uint32_t bq[4];
                ldsm4t(bq, sb + VOFF +
                    ((ks * 16 + g8 + sel * 8) * 136 + hh * 32 + nb * 16 + hi8) * 2);
                mma_f16(oacc[nb * 2],     a0, a1, a2, a3, bq[0], bq[1]);
                mma_f16(oacc[nb * 2 + 1], a0, a1, a2, a3, bq[2], bq[3]);
            }
        }

        #pragma unroll
        for (int nf = 0; nf < 4; nf++) {
            int col = hh * 32 + nf * 8 + 2 * et;
            *(uint32_t*)(dsm + AOFF + ((size_t)r0 * 136 + col) * 2) =
                h2u(oacc[nf][0] * inv0, oacc[nf][1] * inv0);
            *(uint32_t*)(dsm + AOFF + ((size_t)r1 * 136 + col) * 2) =
                h2u(oacc[nf][2] * inv1, oacc[nf][3] * inv1);
        }
    }
    __syncthreads();

    float c[16][4];
    #pragma unroll
    for (int nf = 0; nf < 16; nf++)
        #pragma unroll
        for (int j = 0; j < 4; j++) c[nf][j] = 0.f;

    uint32_t aB = sb + AOFF + ((tq0 + g8 + sel * 8) * 136 + hi8) * 2;
    #pragma unroll
    for (int ks = 0; ks < 8; ks++) {
        uint32_t a[4];
        ldsm4(a, aB + ks * 32);
        #pragma unroll
        for (int nf = 0; nf < 16; nf++) {
            uint32_t b0 = *(const uint32_t*)(g_wo16 + (size_t)(nf * 8 + eg) * 128 + ks * 16 + 2 * et);
            uint32_t b1 = *(const uint32_t*)(g_wo16 + (size_t)(nf * 8 + eg) * 128 + ks * 16 + 2 * et + 8);
            mma_f16(c[nf], a[0], a[1], a[2], a[3], b0, b1);
        }
    }

    int grow0 = b * 128 + r0, grow1 = b * 128 + r1;
    #pragma unroll
    for (int nf = 0; nf < 16; nf++) {
        int col = nf * 8 + 2 * et;
        float2 bb = *(const float2*)(bo + col);
        float2 xv0 = *(const float2*)(x + (size_t)grow0 * 128 + col);
        float2 xv1 = *(const float2*)(x + (size_t)grow1 * 128 + col);
        *(float2*)(g_x2 + (size_t)grow0 * 128 + col) =
            make_float2(c[nf][0] + bb.x + xv0.x, c[nf][1] + bb.y + xv0.y);
        *(float2*)(g_x2 + (size_t)grow1 * 128 + col) =
            make_float2(c[nf][2] + bb.x + xv1.x, c[nf][3] + bb.y + xv1.y);
    }
}

// ---------------- fully fused FFN: LN2 + FFN1(relu) + FFN2 + residual ------
// smem: A @0, FF @34816, W1 stages @69632/@104448, W2 stages @139264/@174080.
#define FFN_SMEM 208896
__global__ __launch_bounds__(256, 1) void k_ffn(
    const float* __restrict__ g, const float* __restrict__ b,
    const float* __restrict__ b1, const float* __restrict__ b2,
    float* __restrict__ out)
{
    extern __shared__ char dsm[];
    uint32_t sb = smem_u32(dsm);
    const uint32_t FFO = 34816;
    const uint32_t W1ST[2] = { 69632u, 104448u };
    const uint32_t W2ST[2] = { 139264u, 174080u };
    int tid = threadIdx.x;
    int rowBase = blockIdx.x * 128;
    Frag f = mkfrag(tid);

    // prefetch blk0, blk1 weight pairs
    #pragma unroll
    for (int pb = 0; pb < 2; pb++) {
        issue_w(sb, W1ST[pb], g_w116 + (size_t)pb * 128 * 128, 128, tid);
        issue_w(sb, W2ST[pb], g_w216 + (size_t)pb * 128,       512, tid);
        asm volatile("cp.async.commit_group;" ::: "memory");
    }

    ln_to_smem(dsm, g_x2, g, b, rowBase, tid);

    float c2[4][4][4];
    #pragma unroll
    for (int mf = 0; mf < 4; mf++)
        #pragma unroll
        for (int nf = 0; nf < 4; nf++)
            #pragma unroll
            for (int j = 0; j < 4; j++) c2[mf][nf][j] = 0.f;

    #pragma unroll
    for (int blk = 0; blk < 4; blk++) {
        int st = blk & 1;
        if (blk < 3) asm volatile("cp.async.wait_group 1;" ::: "memory");
        else         asm volatile("cp.async.wait_group 0;" ::: "memory");
        __syncthreads();

        // FFN1 block: c1 = A @ W1[blk]^T
        float c1[4][4][4];
        #pragma unroll
        for (int mf = 0; mf < 4; mf++)
            #pragma unroll
            for (int nf = 0; nf < 4; nf++)
                #pragma unroll
                for (int j = 0; j < 4; j++) c1[mf][nf][j] = 0.f;
        g128_mma(sb, 0, W1ST[st], f, c1);
        __syncthreads();   // prev-iter FF reads all done

        // relu(c1 + b1) -> FF smem (fp16)
        #pragma unroll
        for (int mf = 0; mf < 4; mf++)
            #pragma unroll
            for (int rr = 0; rr < 2; rr++) {
                int row = f.mBase + mf * 16 + f.eg + rr * 8;
                #pragma unroll
                for (int nf = 0; nf < 4; nf++) {
                    int col = f.nBase + nf * 8 + 2 * f.et;
                    float2 bb = *(const float2*)(b1 + blk * 128 + col);
                    float v0 = fmaxf(c1[mf][nf][rr * 2]     + bb.x, 0.f);
                    float v1 = fmaxf(c1[mf][nf][rr * 2 + 1] + bb.y, 0.f);
                    *(uint32_t*)(dsm + FFO + (row * 136 + col) * 2) = h2u(v0, v1);
                }
            }
        __syncthreads();

        // FFN2 partial: c2 += FF @ W2[:,blk]^T
        g128_mma(sb, FFO, W2ST[st], f, c2);
        __syncthreads();   // all reads of stage st done before overwrite

        if (blk < 2) {
            issue_w(sb, W1ST[st], g_w116 + (size_t)(blk + 2) * 128 * 128, 128, tid);
            issue_w(sb, W2ST[st], g_w216 + (size_t)(blk + 2) * 128,       512, tid);
            asm volatile("cp.async.commit_group;" ::: "memory");
        }
    }

    // epilogue: + b2 + x2 residual -> out
    #pragma unroll
    for (int mf = 0; mf < 4; mf++)
        #pragma unroll
        for (int rr = 0; rr < 2; rr++) {
            int row = rowBase + f.mBase + mf * 16 + f.eg + rr * 8;
            #pragma unroll
            for (int nf = 0; nf < 4; nf++) {
                int col = f.nBase + nf * 8 + 2 * f.et;
                float2 bb = *(const float2*)(b2 + col);
                float2 rv = *(const float2*)(g_x2 + (size_t)row * 128 + col);
                *(float2*)(out + (size_t)row * 128 + col) =
                    make_float2(c2[mf][nf][rr * 2]     + bb.x + rv.x,
                                c2[mf][nf][rr * 2 + 1] + bb.y + rv.y);
            }
        }
}

// ---------------- launch ----------------
extern "C" void kernel_launch(void* const* d_in, const int* in_sizes, int n_in,
                              void* d_out, int out_size)
{
    const float* x     = (const float*)d_in[0];
    const float* ln1_g = (const float*)d_in[1];
    const float* ln1_b = (const float*)d_in[2];
    const float* Wq    = (const float*)d_in[3];
    const float* Wk    = (const float*)d_in[4];
    const float* Wv    = (const float*)d_in[5];
    const float* Wo    = (const float*)d_in[6];
    const float* bo    = (const float*)d_in[7];
    const float* ln2_g = (const float*)d_in[8];
    const float* ln2_b = (const float*)d_in[9];
    const float* W1    = (const float*)d_in[10];
    const float* b1    = (const float*)d_in[11];
    const float* W2    = (const float*)d_in[12];
    const float* b2    = (const float*)d_in[13];
    float* out = (float*)d_out;

    static bool attrs_set = false;
    if (!attrs_set) {
        cudaFuncSetAttribute(k_qkv3,   cudaFuncAttributeMaxDynamicSharedMemorySize, QKV_SMEM);
        cudaFuncSetAttribute(k_attnwo, cudaFuncAttributeMaxDynamicSharedMemorySize, ATTNWO_SMEM);
        cudaFuncSetAttribute(k_ffn,    cudaFuncAttributeMaxDynamicSharedMemorySize, FFN_SMEM);
        attrs_set = true;
    }

    // 0) weights -> fp16
    cvt6<<<dim3(32, 6), 256>>>(Wq, Wk, Wv, Wo, W1, W2);

    // 1) LN1 + QKV (single pass over x, double-buffered weights)
    k_qkv3<<<BT / 128, 256, QKV_SMEM>>>(x, ln1_g, ln1_b);

    // 2) attention (4 heads) + Wo + bo + residual -> x2
    k_attnwo<<<Bv, 256, ATTNWO_SMEM>>>(x, bo);

    // 3) LN2 + FFN1 + FFN2 + residual (fully fused)
    k_ffn<<<BT / 128, 256, FFN_SMEM>>>(ln2_g, ln2_b, b1, b2, out);
}

// round 8
// speedup vs baseline: 4.1894x; 1.0560x over previous
#include <cuda_runtime.h>
#include <cuda_fp16.h>
#include <cstdint>
#include <math.h>

#define Bv   1024
#define Tv   128
#define Dv   128
#define Hv   4
#define HDv  32
#define FFv  512
#define BT   (Bv*Tv)
#define SCALE 0.08838834764831845f   // 128^-0.5

// ---------------- scratch (device globals) ----------------
__device__ __align__(256) __half g_q16 [BT*Dv];
__device__ __align__(256) __half g_k16 [BT*Dv];
__device__ __align__(256) __half g_v16 [BT*Dv];
__device__ __align__(256) __half g_ff16[BT*FFv];
__device__ __align__(256) float  g_x2  [BT*Dv];
__device__ __align__(256) __half g_wq16[Dv*Dv];
__device__ __align__(256) __half g_wk16[Dv*Dv];
__device__ __align__(256) __half g_wv16[Dv*Dv];
__device__ __align__(256) __half g_wo16[Dv*Dv];
__device__ __align__(256) __half g_w116[FFv*Dv];
__device__ __align__(256) __half g_w216[Dv*FFv];

// ---------------- PTX helpers ----------------
__device__ __forceinline__ uint32_t smem_u32(const void* p) {
    uint32_t a;
    asm("{ .reg .u64 t; cvta.to.shared.u64 t, %1; cvt.u32.u64 %0, t; }" : "=r"(a) : "l"(p));
    return a;
}
__device__ __forceinline__ void cp16(uint32_t dst, const void* src) {
    asm volatile("cp.async.cg.shared.global [%0], [%1], 16;" :: "r"(dst), "l"(src));
}
__device__ __forceinline__ void ldsm4(uint32_t (&r)[4], uint32_t addr) {
    asm volatile("ldmatrix.sync.aligned.m8n8.x4.shared.b16 {%0,%1,%2,%3}, [%4];"
        : "=r"(r[0]), "=r"(r[1]), "=r"(r[2]), "=r"(r[3]) : "r"(addr));
}
__device__ __forceinline__ void ldsm4t(uint32_t (&r)[4], uint32_t addr) {
    asm volatile("ldmatrix.sync.aligned.m8n8.x4.trans.shared.b16 {%0,%1,%2,%3}, [%4];"
        : "=r"(r[0]), "=r"(r[1]), "=r"(r[2]), "=r"(r[3]) : "r"(addr));
}
__device__ __forceinline__ void mma_f16(float* c,
    uint32_t a0, uint32_t a1, uint32_t a2, uint32_t a3, uint32_t b0, uint32_t b1)
{
    asm volatile(
        "mma.sync.aligned.m16n8k16.row.col.f32.f16.f16.f32 "
        "{%0,%1,%2,%3}, {%4,%5,%6,%7}, {%8,%9}, {%0,%1,%2,%3};"
        : "+f"(c[0]), "+f"(c[1]), "+f"(c[2]), "+f"(c[3])
        : "r"(a0), "r"(a1), "r"(a2), "r"(a3), "r"(b0), "r"(b1));
}
__device__ __forceinline__ uint32_t h2u(float a, float b) {
    __half2 h = __floats2half2_rn(a, b);
    return *(uint32_t*)&h;
}

// ---------------- weight fp32 -> fp16 conversion ----------------
__global__ void cvt6(const float* __restrict__ wq, const float* __restrict__ wk,
                     const float* __restrict__ wv, const float* __restrict__ wo,
                     const float* __restrict__ w1, const float* __restrict__ w2)
{
    const float* src; __half* dst; int n;
    switch (blockIdx.y) {
        case 0: src = wq; dst = g_wq16; n = Dv*Dv;  break;
        case 1: src = wk; dst = g_wk16; n = Dv*Dv;  break;
        case 2: src = wv; dst = g_wv16; n = Dv*Dv;  break;
        case 3: src = wo; dst = g_wo16; n = Dv*Dv;  break;
        case 4: src = w1; dst = g_w116; n = FFv*Dv; break;
        default: src = w2; dst = g_w216; n = Dv*FFv; break;
    }
    for (int i = blockIdx.x * blockDim.x + threadIdx.x; i < n; i += gridDim.x * blockDim.x)
        dst[i] = __float2half_rn(src[i]);
}

// ============ shared fragments/pieces (tiles half[128][136], stride 272B) ==
struct Frag { int g8, sel, hi, eg, et, mBase, nBase; };
__device__ __forceinline__ Frag mkfrag(int tid) {
    Frag f;
    int lane = tid & 31, wid = tid >> 5;
    f.g8 = lane & 7; f.sel = (lane >> 3) & 1; f.hi = lane >> 4;
    f.eg = lane >> 2; f.et = lane & 3;
    f.mBase = (wid >> 2) * 64; f.nBase = (wid & 3) * 32;
    return f;
}

__device__ __forceinline__ void g128_mma(uint32_t sb, uint32_t aoff, uint32_t woff,
                                         const Frag& f, float c[4][4][4])
{
    uint32_t aBase = sb + aoff + ((f.mBase + f.g8 + f.sel * 8) * 136 + f.hi * 8) * 2;
    uint32_t bBase = sb + woff + ((f.nBase + f.g8 + f.hi * 8) * 136 + f.sel * 8) * 2;
    #pragma unroll
    for (int ks = 0; ks < 8; ks++) {
        uint32_t a[4][4];
        #pragma unroll
        for (int mf = 0; mf < 4; mf++)
            ldsm4(a[mf], aBase + mf * 4352 + ks * 32);
        uint32_t bq[2][4];
        #pragma unroll
        for (int p = 0; p < 2; p++)
            ldsm4(bq[p], bBase + p * 4352 + ks * 32);
        #pragma unroll
        for (int mf = 0; mf < 4; mf++)
            #pragma unroll
            for (int nf = 0; nf < 4; nf++)
                mma_f16(c[mf][nf], a[mf][0], a[mf][1], a[mf][2], a[mf][3],
                        bq[nf >> 1][(nf & 1) * 2], bq[nf >> 1][(nf & 1) * 2 + 1]);
    }
}

__device__ __forceinline__ void ln_to_smem(char* dsm, const float* __restrict__ X,
    const float* __restrict__ lng, const float* __restrict__ lnb, int rowBase, int tid)
{
    int row = tid >> 1, hf = tid & 1;
    const float* xr = X + (size_t)(rowBase + row) * 128 + hf * 64;
    float s = 0.f, s2 = 0.f;
    #pragma unroll
    for (int i = 0; i < 16; i++) {
        float4 v = *(const float4*)(xr + i * 4);
        s  += v.x + v.y + v.z + v.w;
        s2 += v.x * v.x + v.y * v.y + v.z * v.z + v.w * v.w;
    }
    s  += __shfl_xor_sync(0xffffffffu, s, 1);
    s2 += __shfl_xor_sync(0xffffffffu, s2, 1);
    float mu = s * (1.f / 128.f);
    float rstd = rsqrtf(s2 * (1.f / 128.f) - mu * mu + 1e-5f);
    #pragma unroll
    for (int i = 0; i < 16; i++) {
        float4 v = *(const float4*)(xr + i * 4);
        int col = hf * 64 + i * 4;
        float4 gg = *(const float4*)(lng + col);
        float4 bb = *(const float4*)(lnb + col);
        *(uint32_t*)(dsm + row * 272 + col * 2)     = h2u((v.x - mu) * rstd * gg.x + bb.x,
                                                          (v.y - mu) * rstd * gg.y + bb.y);
        *(uint32_t*)(dsm + row * 272 + col * 2 + 4) = h2u((v.z - mu) * rstd * gg.z + bb.z,
                                                          (v.w - mu) * rstd * gg.w + bb.w);
    }
}

__device__ __forceinline__ void issue_w(uint32_t sb, uint32_t off,
                                        const __half* __restrict__ W, int ldw, int tid)
{
    #pragma unroll
    for (int i = 0; i < 8; i++) {
        int idx = tid + i * 256;
        int r = idx >> 4, cc = idx & 15;
        cp16(sb + off + r * 272 + cc * 16, W + (size_t)r * ldw + cc * 8);
    }
}

// ---------------- fused LN1 + QKV (double-buffered weights) ----------------
#define QKV_SMEM 104448
__global__ __launch_bounds__(256, 2) void k_qkv3(
    const float* __restrict__ x, const float* __restrict__ g, const float* __restrict__ b)
{
    extern __shared__ char dsm[];
    uint32_t sb = smem_u32(dsm);
    int tid = threadIdx.x;
    int rowBase = blockIdx.x * 128;
    Frag f = mkfrag(tid);

    const uint32_t WST[2] = { 34816u, 69632u };
    issue_w(sb, WST[0], g_wq16, 128, tid);
    asm volatile("cp.async.commit_group;" ::: "memory");
    issue_w(sb, WST[1], g_wk16, 128, tid);
    asm volatile("cp.async.commit_group;" ::: "memory");

    ln_to_smem(dsm, x, g, b, rowBase, tid);

    __half* outs[3];
    outs[0] = g_q16; outs[1] = g_k16; outs[2] = g_v16;

    #pragma unroll
    for (int wsel = 0; wsel < 3; wsel++) {
        if (wsel < 2) asm volatile("cp.async.wait_group 1;" ::: "memory");
        else          asm volatile("cp.async.wait_group 0;" ::: "memory");
        __syncthreads();

        float c[4][4][4];
        #pragma unroll
        for (int mf = 0; mf < 4; mf++)
            #pragma unroll
            for (int nf = 0; nf < 4; nf++)
                #pragma unroll
                for (int j = 0; j < 4; j++) c[mf][nf][j] = 0.f;

        g128_mma(sb, 0, WST[wsel == 1], f, c);
        __syncthreads();
        if (wsel == 0) {
            issue_w(sb, WST[0], g_wv16, 128, tid);
            asm volatile("cp.async.commit_group;" ::: "memory");
        }

        __half* C = outs[wsel];
        #pragma unroll
        for (int mf = 0; mf < 4; mf++)
            #pragma unroll
            for (int rr = 0; rr < 2; rr++) {
                int row = rowBase + f.mBase + mf * 16 + f.eg + rr * 8;
                #pragma unroll
                for (int nf = 0; nf < 4; nf++) {
                    int col = f.nBase + nf * 8 + 2 * f.et;
                    *(uint32_t*)(C + (size_t)row * 128 + col) =
                        h2u(c[mf][nf][rr * 2], c[mf][nf][rr * 2 + 1]);
                }
            }
    }
}

// ---------------- fused attention (4 heads) + Wo + residual ----------------
// 1 CTA per batch. smem: K@0, V@34816, AO@69632. Wo reuses K region at end.
#define ATTNWO_SMEM 104448
__global__ __launch_bounds__(256, 2) void k_attnwo(
    const float* __restrict__ x, const float* __restrict__ bo)
{
    extern __shared__ char dsm[];
    uint32_t sb = smem_u32(dsm);
    const uint32_t VOFF = 34816, AOFF = 69632;
    int b = blockIdx.x;
    int tid = threadIdx.x, lane = tid & 31, w = tid >> 5;
    int g8 = lane & 7, sel = (lane >> 3) & 1, hi8 = (lane >> 4) * 8;
    int eg = lane >> 2, et = lane & 3;
    int tq0 = w * 16;
    size_t base = (size_t)b * Tv * Dv;

    #pragma unroll
    for (int i = 0; i < 8; i++) {
        int idx = tid + i * 256;
        int r = idx >> 4, cc = idx & 15;
        cp16(sb + r * 272 + cc * 16,        g_k16 + base + (size_t)r * 128 + cc * 8);
        cp16(sb + VOFF + r * 272 + cc * 16, g_v16 + base + (size_t)r * 128 + cc * 8);
    }
    asm volatile("cp.async.commit_group;" ::: "memory");
    asm volatile("cp.async.wait_group 0;" ::: "memory");
    __syncthreads();

    const __half* qb = g_q16 + base;
    int r0 = tq0 + eg, r1 = r0 + 8;

    #pragma unroll
    for (int hh = 0; hh < 4; hh++) {
        float sacc[16][4];
        #pragma unroll
        for (int cn = 0; cn < 16; cn++)
            #pragma unroll
            for (int j = 0; j < 4; j++) sacc[cn][j] = 0.f;

        #pragma unroll
        for (int ks = 0; ks < 2; ks++) {
            int kc = hh * 32 + ks * 16 + 2 * et;
            uint32_t a0 = *(const uint32_t*)(qb + (size_t)r0 * 128 + kc);
            uint32_t a1 = *(const uint32_t*)(qb + (size_t)r1 * 128 + kc);
            uint32_t a2 = *(const uint32_t*)(qb + (size_t)r0 * 128 + kc + 8);
            uint32_t a3 = *(const uint32_t*)(qb + (size_t)r1 * 128 + kc + 8);
            #pragma unroll
            for (int p = 0; p < 8; p++) {
                uint32_t bq[4];
                ldsm4(bq, sb + ((p * 16 + g8 + hi8) * 136 + hh * 32 + sel * 8 + ks * 16) * 2);
                mma_f16(sacc[2 * p],     a0, a1, a2, a3, bq[0], bq[1]);
                mma_f16(sacc[2 * p + 1], a0, a1, a2, a3, bq[2], bq[3]);
            }
        }

        #pragma unroll
        for (int cn = 0; cn < 16; cn++) {
            int c0 = cn * 8 + 2 * et;
            sacc[cn][0] = (c0     <= r0) ? sacc[cn][0] * SCALE : -1e30f;
            sacc[cn][1] = (c0 + 1 <= r0) ? sacc[cn][1] * SCALE : -1e30f;
            sacc[cn][2] = (c0     <= r1) ? sacc[cn][2] * SCALE : -1e30f;
            sacc[cn][3] = (c0 + 1 <= r1) ? sacc[cn][3] * SCALE : -1e30f;
        }

        float m0 = -1e30f, m1 = -1e30f;
        #pragma unroll
        for (int cn = 0; cn < 16; cn++) {
            m0 = fmaxf(m0, fmaxf(sacc[cn][0], sacc[cn][1]));
            m1 = fmaxf(m1, fmaxf(sacc[cn][2], sacc[cn][3]));
        }
        m0 = fmaxf(m0, __shfl_xor_sync(0xffffffffu, m0, 1));
        m0 = fmaxf(m0, __shfl_xor_sync(0xffffffffu, m0, 2));
        m1 = fmaxf(m1, __shfl_xor_sync(0xffffffffu, m1, 1));
        m1 = fmaxf(m1, __shfl_xor_sync(0xffffffffu, m1, 2));

        float l0 = 0.f, l1 = 0.f;
        #pragma unroll
        for (int cn = 0; cn < 16; cn++) {
            sacc[cn][0] = __expf(sacc[cn][0] - m0);
            sacc[cn][1] = __expf(sacc[cn][1] - m0);
            sacc[cn][2] = __expf(sacc[cn][2] - m1);
            sacc[cn][3] = __expf(sacc[cn][3] - m1);
            l0 += sacc[cn][0] + sacc[cn][1];
            l1 += sacc[cn][2] + sacc[cn][3];
        }
        l0 += __shfl_xor_sync(0xffffffffu, l0, 1);
        l0 += __shfl_xor_sync(0xffffffffu, l0, 2);
        l1 += __shfl_xor_sync(0xffffffffu, l1, 1);
        l1 += __shfl_xor_sync(0xffffffffu, l1, 2);
        float inv0 = 1.f / l0, inv1 = 1.f / l1;

        float oacc[4][4];
        #pragma unroll
        for (int nf = 0; nf < 4; nf++)
            #pragma unroll
            for (int j = 0; j < 4; j++) oacc[nf][j] = 0.f;

        #pragma unroll
        for (int ks = 0; ks < 8; ks++) {
            uint32_t a0 = h2u(sacc[2*ks][0],   sacc[2*ks][1]);
            uint32_t a1 = h2u(sacc[2*ks][2],   sacc[2*ks][3]);
            uint32_t a2 = h2u(sacc[2*ks+1][0], sacc[2*ks+1][1]);
            uint32_t a3 = h2u(sacc[2*ks+1][2], sacc[2*ks+1][3]);
            #pragma unroll
            for (int nb = 0; nb < 2; nb++) {
                uint32_t bq[4];
                ldsm4t(bq, sb + VOFF +
                    ((ks * 16 + g8 + sel * 8) * 136 + hh * 32 + nb * 16 + hi8) * 2);
                mma_f16(oacc[nb * 2],     a0, a1, a2, a3, bq[0], bq[1]);
                mma_f16(oacc[nb * 2 + 1], a0, a1, a2, a3, bq[2], bq[3]);
            }
        }

        #pragma unroll
        for (int nf = 0; nf < 4; nf++) {
            int col = hh * 32 + nf * 8 + 2 * et;
            *(uint32_t*)(dsm + AOFF + ((size_t)r0 * 136 + col) * 2) =
                h2u(oacc[nf][0] * inv0, oacc[nf][1] * inv0);
            *(uint32_t*)(dsm + AOFF + ((size_t)r1 * 136 + col) * 2) =
                h2u(oacc[nf][2] * inv1, oacc[nf][3] * inv1);
        }
    }
    __syncthreads();   // K dead everywhere; AO visible

    // load Wo into K region, read B-frags via ldmatrix (not 256 LDGs)
    #pragma unroll
    for (int i = 0; i < 8; i++) {
        int idx = tid + i * 256;
        int r = idx >> 4, cc = idx & 15;
        cp16(sb + r * 272 + cc * 16, g_wo16 + (size_t)r * 128 + cc * 8);
    }
    asm volatile("cp.async.commit_group;" ::: "memory");
    asm volatile("cp.async.wait_group 0;" ::: "memory");
    __syncthreads();

    float c[16][4];
    #pragma unroll
    for (int nf = 0; nf < 16; nf++)
        #pragma unroll
        for (int j = 0; j < 4; j++) c[nf][j] = 0.f;

    uint32_t aB = sb + AOFF + ((tq0 + g8 + sel * 8) * 136 + hi8) * 2;
    uint32_t bB = sb + ((g8 + hi8) * 136 + sel * 8) * 2;
    #pragma unroll
    for (int ks = 0; ks < 8; ks++) {
        uint32_t a[4];
        ldsm4(a, aB + ks * 32);
        #pragma unroll
        for (int p = 0; p < 8; p++) {
            uint32_t bq[4];
            ldsm4(bq, bB + p * 4352 + ks * 32);
            mma_f16(c[2 * p],     a[0], a[1], a[2], a[3], bq[0], bq[1]);
            mma_f16(c[2 * p + 1], a[0], a[1], a[2], a[3], bq[2], bq[3]);
        }
    }

    int grow0 = b * 128 + r0, grow1 = b * 128 + r1;
    #pragma unroll
    for (int nf = 0; nf < 16; nf++) {
        int col = nf * 8 + 2 * et;
        float2 bb = *(const float2*)(bo + col);
        float2 xv0 = *(const float2*)(x + (size_t)grow0 * 128 + col);
        float2 xv1 = *(const float2*)(x + (size_t)grow1 * 128 + col);
        *(float2*)(g_x2 + (size_t)grow0 * 128 + col) =
            make_float2(c[nf][0] + bb.x + xv0.x, c[nf][1] + bb.y + xv0.y);
        *(float2*)(g_x2 + (size_t)grow1 * 128 + col) =
            make_float2(c[nf][2] + bb.x + xv1.x, c[nf][3] + bb.y + xv1.y);
    }
}

// ---------------- LN2 + FFN1 (double-buffered W1, occ 2) -------------------
#define FFN1_SMEM 104448
__global__ __launch_bounds__(256, 2) void k_ffn1(
    const float* __restrict__ g, const float* __restrict__ b, const float* __restrict__ b1)
{
    extern __shared__ char dsm[];
    uint32_t sb = smem_u32(dsm);
    int tid = threadIdx.x;
    int rowBase = blockIdx.x * 128;
    Frag f = mkfrag(tid);

    const uint32_t WST[2] = { 34816u, 69632u };
    issue_w(sb, WST[0], g_w116, 128, tid);
    asm volatile("cp.async.commit_group;" ::: "memory");
    issue_w(sb, WST[1], g_w116 + 128 * 128, 128, tid);
    asm volatile("cp.async.commit_group;" ::: "memory");

    ln_to_smem(dsm, g_x2, g, b, rowBase, tid);

    #pragma unroll
    for (int blk = 0; blk < 4; blk++) {
        if (blk < 3) asm volatile("cp.async.wait_group 1;" ::: "memory");
        else         asm volatile("cp.async.wait_group 0;" ::: "memory");
        __syncthreads();

        float c[4][4][4];
        #pragma unroll
        for (int mf = 0; mf < 4; mf++)
            #pragma unroll
            for (int nf = 0; nf < 4; nf++)
                #pragma unroll
                for (int j = 0; j < 4; j++) c[mf][nf][j] = 0.f;

        g128_mma(sb, 0, WST[blk & 1], f, c);
        __syncthreads();
        if (blk < 2) {
            issue_w(sb, WST[blk & 1], g_w116 + (size_t)(blk + 2) * 128 * 128, 128, tid);
            asm volatile("cp.async.commit_group;" ::: "memory");
        }

        #pragma unroll
        for (int mf = 0; mf < 4; mf++)
            #pragma unroll
            for (int rr = 0; rr < 2; rr++) {
                int row = rowBase + f.mBase + mf * 16 + f.eg + rr * 8;
                #pragma unroll
                for (int nf = 0; nf < 4; nf++) {
                    int col = blk * 128 + f.nBase + nf * 8 + 2 * f.et;
                    float2 bb = *(const float2*)(b1 + col);
                    float v0 = fmaxf(c[mf][nf][rr * 2]     + bb.x, 0.f);
                    float v1 = fmaxf(c[mf][nf][rr * 2 + 1] + bb.y, 0.f);
                    *(uint32_t*)(g_ff16 + (size_t)row * 512 + col) = h2u(v0, v1);
                }
            }
    }
}

// ---------------- FFN2: K=512 chunked fp16 GEMM + bias + residual ----------
#define FFN2_SMEM 73728
__device__ __forceinline__ void ffn2_issue(uint32_t sb, int st, int ch, int rowBase, int tid)
{
    #pragma unroll
    for (int i = 0; i < 4; i++) {
        int idx = tid + i * 256;
        int r = idx >> 3, cc = idx & 7;
        cp16(sb + st * 18432 + r * 144 + cc * 16,
             g_ff16 + (size_t)(rowBase + r) * 512 + ch * 64 + cc * 8);
        cp16(sb + 36864 + st * 18432 + r * 144 + cc * 16,
             g_w216 + (size_t)r * 512 + ch * 64 + cc * 8);
    }
    asm volatile("cp.async.commit_group;" ::: "memory");
}

__global__ __launch_bounds__(256, 2) void k_ffn2(
    const float* __restrict__ b2, float* __restrict__ out)
{
    extern __shared__ char dsm[];
    uint32_t sb = smem_u32(dsm);
    int tid = threadIdx.x, lane = tid & 31, wid = tid >> 5;
    int rowBase = blockIdx.x * 128;
    int mBase = (wid >> 2) * 64, nBase = (wid & 3) * 32;
    int g8 = lane & 7, sel = (lane >> 3) & 1, hi = lane >> 4;

    float c[4][4][4];
    #pragma unroll
    for (int mf = 0; mf < 4; mf++)
        #pragma unroll
        for (int nf = 0; nf < 4; nf++)
            #pragma unroll
            for (int j = 0; j < 4; j++) c[mf][nf][j] = 0.f;

    ffn2_issue(sb, 0, 0, rowBase, tid);

    for (int ch = 0; ch < 8; ch++) {
        int st = ch & 1;
        if (ch < 7) {
            ffn2_issue(sb, st ^ 1, ch + 1, rowBase, tid);
            asm volatile("cp.async.wait_group 1;" ::: "memory");
        } else {
            asm volatile("cp.async.wait_group 0;" ::: "memory");
        }
        __syncthreads();

        uint32_t aB = sb + st * 18432 + ((mBase + g8 + sel * 8) * 72 + hi * 8) * 2;
        uint32_t bB = sb + 36864 + st * 18432 + ((nBase + g8 + hi * 8) * 72 + sel * 8) * 2;

        #pragma unroll
        for (int ks = 0; ks < 4; ks++) {
            uint32_t a[4][4];
            #pragma unroll
            for (int mf = 0; mf < 4; mf++)
                ldsm4(a[mf], aB + mf * 2304 + ks * 32);
            uint32_t bq[2][4];
            #pragma unroll
            for (int p = 0; p < 2; p++)
                ldsm4(bq[p], bB + p * 2304 + ks * 32);
            #pragma unroll
            for (int mf = 0; mf < 4; mf++)
                #pragma unroll
                for (int nf = 0; nf < 4; nf++)
                    mma_f16(c[mf][nf], a[mf][0], a[mf][1], a[mf][2], a[mf][3],
                            bq[nf >> 1][(nf & 1) * 2], bq[nf >> 1][(nf & 1) * 2 + 1]);
        }
        __syncthreads();
    }

    int eg = lane >> 2, et = lane & 3;
    #pragma unroll
    for (int mf = 0; mf < 4; mf++)
        #pragma unroll
        for (int rr = 0; rr < 2; rr++) {
            int row = rowBase + mBase + mf * 16 + eg + rr * 8;
            #pragma unroll
            for (int nf = 0; nf < 4; nf++) {
                int col = nBase + nf * 8 + 2 * et;
                float2 bb = *(const float2*)(b2 + col);
                float2 rv = *(const float2*)(g_x2 + (size_t)row * 128 + col);
                *(float2*)(out + (size_t)row * 128 + col) =
                    make_float2(c[mf][nf][rr * 2]     + bb.x + rv.x,
                                c[mf][nf][rr * 2 + 1] + bb.y + rv.y);
            }
        }
}

// ---------------- launch ----------------
extern "C" void kernel_launch(void* const* d_in, const int* in_sizes, int n_in,
                              void* d_out, int out_size)
{
    const float* x     = (const float*)d_in[0];
    const float* ln1_g = (const float*)d_in[1];
    const float* ln1_b = (const float*)d_in[2];
    const float* Wq    = (const float*)d_in[3];
    const float* Wk    = (const float*)d_in[4];
    const float* Wv    = (const float*)d_in[5];
    const float* Wo    = (const float*)d_in[6];
    const float* bo    = (const float*)d_in[7];
    const float* ln2_g = (const float*)d_in[8];
    const float* ln2_b = (const float*)d_in[9];
    const float* W1    = (const float*)d_in[10];
    const float* b1    = (const float*)d_in[11];
    const float* W2    = (const float*)d_in[12];
    const float* b2    = (const float*)d_in[13];
    float* out = (float*)d_out;

    static bool attrs_set = false;
    if (!attrs_set) {
        cudaFuncSetAttribute(k_qkv3,   cudaFuncAttributeMaxDynamicSharedMemorySize, QKV_SMEM);
        cudaFuncSetAttribute(k_attnwo, cudaFuncAttributeMaxDynamicSharedMemorySize, ATTNWO_SMEM);
        cudaFuncSetAttribute(k_ffn1,   cudaFuncAttributeMaxDynamicSharedMemorySize, FFN1_SMEM);
        cudaFuncSetAttribute(k_ffn2,   cudaFuncAttributeMaxDynamicSharedMemorySize, FFN2_SMEM);
        attrs_set = true;
    }

    // 0) weights -> fp16
    cvt6<<<dim3(32, 6), 256>>>(Wq, Wk, Wv, Wo, W1, W2);

    // 1) LN1 + QKV
    k_qkv3<<<BT / 128, 256, QKV_SMEM>>>(x, ln1_g, ln1_b);

    // 2) attention (4 heads) + Wo + bo + residual -> x2
    k_attnwo<<<Bv, 256, ATTNWO_SMEM>>>(x, bo);

    // 3) LN2 + FFN1 (double-buffered weights)
    k_ffn1<<<BT / 128, 256, FFN1_SMEM>>>(ln2_g, ln2_b, b1);

    // 4) out = ff @ W2^T + b2 + x2
    k_ffn2<<<BT / 128, 256, FFN2_SMEM>>>(b2, out);
}

// round 10
// speedup vs baseline: 4.4553x; 1.0635x over previous
#include <cuda_runtime.h>
#include <cuda_fp16.h>
#include <cstdint>
#include <math.h>

#define Bv   1024
#define Tv   128
#define Dv   128
#define Hv   4
#define HDv  32
#define FFv  512
#define BT   (Bv*Tv)
#define SCALE 0.08838834764831845f   // 128^-0.5

// ---------------- scratch (device globals) ----------------
__device__ __align__(256) __half g_q16 [BT*Dv];
__device__ __align__(256) __half g_k16 [BT*Dv];
__device__ __align__(256) __half g_v16 [BT*Dv];
__device__ __align__(256) __half g_ff16[BT*FFv];
__device__ __align__(256) float  g_x2  [BT*Dv];
__device__ __align__(256) __half g_wq16[Dv*Dv];
__device__ __align__(256) __half g_wk16[Dv*Dv];
__device__ __align__(256) __half g_wv16[Dv*Dv];
__device__ __align__(256) __half g_wo16[Dv*Dv];
__device__ __align__(256) __half g_w116[FFv*Dv];
__device__ __align__(256) __half g_w216[Dv*FFv];

// ---------------- PTX helpers ----------------
__device__ __forceinline__ uint32_t smem_u32(const void* p) {
    uint32_t a;
    asm("{ .reg .u64 t; cvta.to.shared.u64 t, %1; cvt.u32.u64 %0, t; }" : "=r"(a) : "l"(p));
    return a;
}
__device__ __forceinline__ void cp16(uint32_t dst, const void* src) {
    asm volatile("cp.async.cg.shared.global [%0], [%1], 16;" :: "r"(dst), "l"(src));
}
__device__ __forceinline__ void ldsm4(uint32_t (&r)[4], uint32_t addr) {
    asm volatile("ldmatrix.sync.aligned.m8n8.x4.shared.b16 {%0,%1,%2,%3}, [%4];"
        : "=r"(r[0]), "=r"(r[1]), "=r"(r[2]), "=r"(r[3]) : "r"(addr));
}
__device__ __forceinline__ void ldsm4t(uint32_t (&r)[4], uint32_t addr) {
    asm volatile("ldmatrix.sync.aligned.m8n8.x4.trans.shared.b16 {%0,%1,%2,%3}, [%4];"
        : "=r"(r[0]), "=r"(r[1]), "=r"(r[2]), "=r"(r[3]) : "r"(addr));
}
__device__ __forceinline__ void stsm4(uint32_t addr, uint32_t r0, uint32_t r1,
                                      uint32_t r2, uint32_t r3) {
    asm volatile("stmatrix.sync.aligned.m8n8.x4.shared.b16 [%0], {%1,%2,%3,%4};"
        :: "r"(addr), "r"(r0), "r"(r1), "r"(r2), "r"(r3) : "memory");
}
__device__ __forceinline__ void mma_f16(float* c,
    uint32_t a0, uint32_t a1, uint32_t a2, uint32_t a3, uint32_t b0, uint32_t b1)
{
    asm volatile(
        "mma.sync.aligned.m16n8k16.row.col.f32.f16.f16.f32 "
        "{%0,%1,%2,%3}, {%4,%5,%6,%7}, {%8,%9}, {%0,%1,%2,%3};"
        : "+f"(c[0]), "+f"(c[1]), "+f"(c[2]), "+f"(c[3])
        : "r"(a0), "r"(a1), "r"(a2), "r"(a3), "r"(b0), "r"(b1));
}
__device__ __forceinline__ uint32_t h2u(float a, float b) {
    __half2 h = __floats2half2_rn(a, b);
    return *(uint32_t*)&h;
}

// epilogue functors (no extended-lambda)
struct OpNone {
    __device__ __forceinline__ void operator()(float&, float&, float&, float&, int) const {}
};
struct OpBiasRelu {
    const float* b1b;
    __device__ __forceinline__ void operator()(float& v0, float& v1, float& v2,
                                               float& v3, int col) const {
        float2 bb = *(const float2*)(b1b + col);
        v0 = fmaxf(v0 + bb.x, 0.f); v1 = fmaxf(v1 + bb.y, 0.f);
        v2 = fmaxf(v2 + bb.x, 0.f); v3 = fmaxf(v3 + bb.y, 0.f);
    }
};

// ---------------- weight fp32 -> fp16 conversion ----------------
__global__ void cvt6(const float* __restrict__ wq, const float* __restrict__ wk,
                     const float* __restrict__ wv, const float* __restrict__ wo,
                     const float* __restrict__ w1, const float* __restrict__ w2)
{
    const float* src; __half* dst; int n;
    switch (blockIdx.y) {
        case 0: src = wq; dst = g_wq16; n = Dv*Dv;  break;
        case 1: src = wk; dst = g_wk16; n = Dv*Dv;  break;
        case 2: src = wv; dst = g_wv16; n = Dv*Dv;  break;
        case 3: src = wo; dst = g_wo16; n = Dv*Dv;  break;
        case 4: src = w1; dst = g_w116; n = FFv*Dv; break;
        default: src = w2; dst = g_w216; n = Dv*FFv; break;
    }
    for (int i = blockIdx.x * blockDim.x + threadIdx.x; i < n; i += gridDim.x * blockDim.x)
        dst[i] = __float2half_rn(src[i]);
}

// ============ shared pieces (tiles half[128][136], row stride 272B) ========
struct Frag { int g8, sel, hi, eg, et, mBase, nBase; };
__device__ __forceinline__ Frag mkfrag(int tid) {
    Frag f;
    int lane = tid & 31, wid = tid >> 5;
    f.g8 = lane & 7; f.sel = (lane >> 3) & 1; f.hi = lane >> 4;
    f.eg = lane >> 2; f.et = lane & 3;
    f.mBase = (wid >> 2) * 64; f.nBase = (wid & 3) * 32;
    return f;
}

__device__ __forceinline__ void g128_mma(uint32_t sb, uint32_t aoff, uint32_t woff,
                                         const Frag& f, float c[4][4][4])
{
    uint32_t aBase = sb + aoff + ((f.mBase + f.g8 + f.sel * 8) * 136 + f.hi * 8) * 2;
    uint32_t bBase = sb + woff + ((f.nBase + f.g8 + f.hi * 8) * 136 + f.sel * 8) * 2;
    #pragma unroll
    for (int ks = 0; ks < 8; ks++) {
        uint32_t a[4][4];
        #pragma unroll
        for (int mf = 0; mf < 4; mf++)
            ldsm4(a[mf], aBase + mf * 4352 + ks * 32);
        uint32_t bq[2][4];
        #pragma unroll
        for (int p = 0; p < 2; p++)
            ldsm4(bq[p], bBase + p * 4352 + ks * 32);
        #pragma unroll
        for (int mf = 0; mf < 4; mf++)
            #pragma unroll
            for (int nf = 0; nf < 4; nf++)
                mma_f16(c[mf][nf], a[mf][0], a[mf][1], a[mf][2], a[mf][3],
                        bq[nf >> 1][(nf & 1) * 2], bq[nf >> 1][(nf & 1) * 2 + 1]);
    }
}

__device__ __forceinline__ void ln_to_smem(char* dsm, const float* __restrict__ X,
    const float* __restrict__ lng, const float* __restrict__ lnb, int rowBase, int tid)
{
    int row = tid >> 1, hf = tid & 1;
    const float* xr = X + (size_t)(rowBase + row) * 128 + hf * 64;
    float s = 0.f, s2 = 0.f;
    #pragma unroll
    for (int i = 0; i < 16; i++) {
        float4 v = *(const float4*)(xr + i * 4);
        s  += v.x + v.y + v.z + v.w;
        s2 += v.x * v.x + v.y * v.y + v.z * v.z + v.w * v.w;
    }
    s  += __shfl_xor_sync(0xffffffffu, s, 1);
    s2 += __shfl_xor_sync(0xffffffffu, s2, 1);
    float mu = s * (1.f / 128.f);
    float rstd = rsqrtf(s2 * (1.f / 128.f) - mu * mu + 1e-5f);
    #pragma unroll
    for (int i = 0; i < 16; i++) {
        float4 v = *(const float4*)(xr + i * 4);
        int col = hf * 64 + i * 4;
        float4 gg = *(const float4*)(lng + col);
        float4 bb = *(const float4*)(lnb + col);
        *(uint32_t*)(dsm + row * 272 + col * 2)     = h2u((v.x - mu) * rstd * gg.x + bb.x,
                                                          (v.y - mu) * rstd * gg.y + bb.y);
        *(uint32_t*)(dsm + row * 272 + col * 2 + 4) = h2u((v.z - mu) * rstd * gg.z + bb.z,
                                                          (v.w - mu) * rstd * gg.w + bb.w);
    }
}

__device__ __forceinline__ void issue_w(uint32_t sb, uint32_t off,
                                        const __half* __restrict__ W, int ldw, int tid)
{
    #pragma unroll
    for (int i = 0; i < 8; i++) {
        int idx = tid + i * 256;
        int r = idx >> 4, cc = idx & 15;
        cp16(sb + off + r * 272 + cc * 16, W + (size_t)r * ldw + cc * 8);
    }
}

// stmatrix the 64x32 warp tile (after per-element op) into stage buffer
template<typename OP>
__device__ __forceinline__ void stage_tile(uint32_t sb, uint32_t stoff, const Frag& f,
                                           float c[4][4][4], OP op)
{
    uint32_t base = sb + stoff + ((f.mBase + f.g8 + f.sel * 8) * 136 + f.nBase + f.hi * 8) * 2;
    #pragma unroll
    for (int mf = 0; mf < 4; mf++) {
        uint32_t pk[4][2];
        #pragma unroll
        for (int nf = 0; nf < 4; nf++) {
            float v0 = c[mf][nf][0], v1 = c[mf][nf][1];
            float v2 = c[mf][nf][2], v3 = c[mf][nf][3];
            op(v0, v1, v2, v3, f.nBase + nf * 8 + 2 * f.et);
            pk[nf][0] = h2u(v0, v1);
            pk[nf][1] = h2u(v2, v3);
        }
        #pragma unroll
        for (int jj = 0; jj < 2; jj++)
            stsm4(base + mf * 4352 + jj * 32,
                  pk[2*jj][0], pk[2*jj][1], pk[2*jj+1][0], pk[2*jj+1][1]);
    }
}

// ---------------- fused LN1 + QKV (stmatrix epilogue, W-load overlap) ------
// smem: A @0, W @34816, STAGE @69632  (104448 total, occ 2)
#define QKV_SMEM 104448
__global__ __launch_bounds__(256, 2) void k_qkv3(
    const float* __restrict__ x, const float* __restrict__ g, const float* __restrict__ b)
{
    extern __shared__ char dsm[];
    uint32_t sb = smem_u32(dsm);
    const uint32_t WOFF = 34816, STOFF = 69632;
    int tid = threadIdx.x;
    int rowBase = blockIdx.x * 128;
    Frag f = mkfrag(tid);

    issue_w(sb, WOFF, g_wq16, 128, tid);
    asm volatile("cp.async.commit_group;" ::: "memory");

    ln_to_smem(dsm, x, g, b, rowBase, tid);

    const __half* Wn[2] = { g_wk16, g_wv16 };
    __half* outs[3];
    outs[0] = g_q16; outs[1] = g_k16; outs[2] = g_v16;

    #pragma unroll
    for (int wsel = 0; wsel < 3; wsel++) {
        asm volatile("cp.async.wait_group 0;" ::: "memory");
        __syncthreads();

        float c[4][4][4];
        #pragma unroll
        for (int mf = 0; mf < 4; mf++)
            #pragma unroll
            for (int nf = 0; nf < 4; nf++)
                #pragma unroll
                for (int j = 0; j < 4; j++) c[mf][nf][j] = 0.f;

        g128_mma(sb, 0, WOFF, f, c);
        __syncthreads();                       // all W reads done
        if (wsel < 2) {
            issue_w(sb, WOFF, Wn[wsel], 128, tid);   // overlaps store phase
            asm volatile("cp.async.commit_group;" ::: "memory");
        }

        stage_tile(sb, STOFF, f, c, OpNone());
        __syncthreads();

        __half* C = outs[wsel];
        #pragma unroll
        for (int i = 0; i < 8; i++) {
            int idx = tid + i * 256;
            int r = idx >> 4, c16 = idx & 15;
            uint4 v = *(const uint4*)(dsm + STOFF + r * 272 + c16 * 16);
            *(uint4*)(C + (size_t)(rowBase + r) * 128 + c16 * 8) = v;
        }
    }
}

// ---------------- fused attention (4 heads) + Wo + residual ----------------
#define ATTNWO_SMEM 104448
__global__ __launch_bounds__(256, 2) void k_attnwo(
    const float* __restrict__ x, const float* __restrict__ bo)
{
    extern __shared__ char dsm[];
    uint32_t sb = smem_u32(dsm);
    const uint32_t VOFF = 34816, AOFF = 69632;
    int b = blockIdx.x;
    int tid = threadIdx.x, lane = tid & 31, w = tid >> 5;
    int g8 = lane & 7, sel = (lane >> 3) & 1, hi8 = (lane >> 4) * 8;
    int eg = lane >> 2, et = lane & 3;
    int tq0 = w * 16;
    size_t base = (size_t)b * Tv * Dv;

    #pragma unroll
    for (int i = 0; i < 8; i++) {
        int idx = tid + i * 256;
        int r = idx >> 4, cc = idx & 15;
        cp16(sb + r * 272 + cc * 16,        g_k16 + base + (size_t)r * 128 + cc * 8);
        cp16(sb + VOFF + r * 272 + cc * 16, g_v16 + base + (size_t)r * 128 + cc * 8);
    }
    asm volatile("cp.async.commit_group;" ::: "memory");
    asm volatile("cp.async.wait_group 0;" ::: "memory");
    __syncthreads();

    const __half* qb = g_q16 + base;
    int r0 = tq0 + eg, r1 = r0 + 8;

    #pragma unroll
    for (int hh = 0; hh < 4; hh++) {
        float sacc[16][4];
        #pragma unroll
        for (int cn = 0; cn < 16; cn++)
            #pragma unroll
            for (int j = 0; j < 4; j++) sacc[cn][j] = 0.f;

        #pragma unroll
        for (int ks = 0; ks < 2; ks++) {
            int kc = hh * 32 + ks * 16 + 2 * et;
            uint32_t a0 = *(const uint32_t*)(qb + (size_t)r0 * 128 + kc);
            uint32_t a1 = *(const uint32_t*)(qb + (size_t)r1 * 128 + kc);
            uint32_t a2 = *(const uint32_t*)(qb + (size_t)r0 * 128 + kc + 8);
            uint32_t a3 = *(const uint32_t*)(qb + (size_t)r1 * 128 + kc + 8);
            #pragma unroll
            for (int p = 0; p < 8; p++) {
                uint32_t bq[4];
                ldsm4(bq, sb + ((p * 16 + g8 + hi8) * 136 + hh * 32 + sel * 8 + ks * 16) * 2);
                mma_f16(sacc[2 * p],     a0, a1, a2, a3, bq[0], bq[1]);
                mma_f16(sacc[2 * p + 1], a0, a1, a2, a3, bq[2], bq[3]);
            }
        }

        #pragma unroll
        for (int cn = 0; cn < 16; cn++) {
            int c0 = cn * 8 + 2 * et;
            sacc[cn][0] = (c0     <= r0) ? sacc[cn][0] * SCALE : -1e30f;
            sacc[cn][1] = (c0 + 1 <= r0) ? sacc[cn][1] * SCALE : -1e30f;
            sacc[cn][2] = (c0     <= r1) ? sacc[cn][2] * SCALE : -1e30f;
            sacc[cn][3] = (c0 + 1 <= r1) ? sacc[cn][3] * SCALE : -1e30f;
        }

        float m0 = -1e30f, m1 = -1e30f;
        #pragma unroll
        for (int cn = 0; cn < 16; cn++) {
            m0 = fmaxf(m0, fmaxf(sacc[cn][0], sacc[cn][1]));
            m1 = fmaxf(m1, fmaxf(sacc[cn][2], sacc[cn][3]));
        }
        m0 = fmaxf(m0, __shfl_xor_sync(0xffffffffu, m0, 1));
        m0 = fmaxf(m0, __shfl_xor_sync(0xffffffffu, m0, 2));
        m1 = fmaxf(m1, __shfl_xor_sync(0xffffffffu, m1, 1));
        m1 = fmaxf(m1, __shfl_xor_sync(0xffffffffu, m1, 2));

        float l0 = 0.f, l1 = 0.f;
        #pragma unroll
        for (int cn = 0; cn < 16; cn++) {
            sacc[cn][0] = __expf(sacc[cn][0] - m0);
            sacc[cn][1] = __expf(sacc[cn][1] - m0);
            sacc[cn][2] = __expf(sacc[cn][2] - m1);
            sacc[cn][3] = __expf(sacc[cn][3] - m1);
            l0 += sacc[cn][0] + sacc[cn][1];
            l1 += sacc[cn][2] + sacc[cn][3];
        }
        l0 += __shfl_xor_sync(0xffffffffu, l0, 1);
        l0 += __shfl_xor_sync(0xffffffffu, l0, 2);
        l1 += __shfl_xor_sync(0xffffffffu, l1, 1);
        l1 += __shfl_xor_sync(0xffffffffu, l1, 2);
        float inv0 = 1.f / l0, inv1 = 1.f / l1;

        float oacc[4][4];
        #pragma unroll
        for (int nf = 0; nf < 4; nf++)
            #pragma unroll
            for (int j = 0; j < 4; j++) oacc[nf][j] = 0.f;

        #pragma unroll
        for (int ks = 0; ks < 8; ks++) {
            uint32_t a0 = h2u(sacc[2*ks][0],   sacc[2*ks][1]);
            uint32_t a1 = h2u(sacc[2*ks][2],   sacc[2*ks][3]);
            uint32_t a2 = h2u(sacc[2*ks+1][0], sacc[2*ks+1][1]);
            uint32_t a3 = h2u(sacc[2*ks+1][2], sacc[2*ks+1][3]);
            #pragma unroll
            for (int nb = 0; nb < 2; nb++) {
                uint32_t bq[4];
                ldsm4t(bq, sb + VOFF +
                    ((ks * 16 + g8 + sel * 8) * 136 + hh * 32 + nb * 16 + hi8) * 2);
                mma_f16(oacc[nb * 2],     a0, a1, a2, a3, bq[0], bq[1]);
                mma_f16(oacc[nb * 2 + 1], a0, a1, a2, a3, bq[2], bq[3]);
            }
        }

        #pragma unroll
        for (int nf = 0; nf < 4; nf++) {
            int col = hh * 32 + nf * 8 + 2 * et;
            *(uint32_t*)(dsm + AOFF + ((size_t)r0 * 136 + col) * 2) =
                h2u(oacc[nf][0] * inv0, oacc[nf][1] * inv0);
            *(uint32_t*)(dsm + AOFF + ((size_t)r1 * 136 + col) * 2) =
                h2u(oacc[nf][2] * inv1, oacc[nf][3] * inv1);
        }
    }
    __syncthreads();

    #pragma unroll
    for (int i = 0; i < 8; i++) {
        int idx = tid + i * 256;
        int r = idx >> 4, cc = idx & 15;
        cp16(sb + r * 272 + cc * 16, g_wo16 + (size_t)r * 128 + cc * 8);
    }
    asm volatile("cp.async.commit_group;" ::: "memory");
    asm volatile("cp.async.wait_group 0;" ::: "memory");
    __syncthreads();

    float c[16][4];
    #pragma unroll
    for (int nf = 0; nf < 16; nf++)
        #pragma unroll
        for (int j = 0; j < 4; j++) c[nf][j] = 0.f;

    uint32_t aB = sb + AOFF + ((tq0 + g8 + sel * 8) * 136 + hi8) * 2;
    uint32_t bB = sb + ((g8 + hi8) * 136 + sel * 8) * 2;
    #pragma unroll
    for (int ks = 0; ks < 8; ks++) {
        uint32_t a[4];
        ldsm4(a, aB + ks * 32);
        #pragma unroll
        for (int p = 0; p < 8; p++) {
            uint32_t bq[4];
            ldsm4(bq, bB + p * 4352 + ks * 32);
            mma_f16(c[2 * p],     a[0], a[1], a[2], a[3], bq[0], bq[1]);
            mma_f16(c[2 * p + 1], a[0], a[1], a[2], a[3], bq[2], bq[3]);
        }
    }

    int grow0 = b * 128 + r0, grow1 = b * 128 + r1;
    #pragma unroll
    for (int nf = 0; nf < 16; nf++) {
        int col = nf * 8 + 2 * et;
        float2 bb = *(const float2*)(bo + col);
        float2 xv0 = *(const float2*)(x + (size_t)grow0 * 128 + col);
        float2 xv1 = *(const float2*)(x + (size_t)grow1 * 128 + col);
        *(float2*)(g_x2 + (size_t)grow0 * 128 + col) =
            make_float2(c[nf][0] + bb.x + xv0.x, c[nf][1] + bb.y + xv0.y);
        *(float2*)(g_x2 + (size_t)grow1 * 128 + col) =
            make_float2(c[nf][2] + bb.x + xv1.x, c[nf][3] + bb.y + xv1.y);
    }
}

// ---------------- LN2 + FFN1 (stmatrix epilogue, W-load overlap) -----------
#define FFN1_SMEM 104448
__global__ __launch_bounds__(256, 2) void k_ffn1(
    const float* __restrict__ g, const float* __restrict__ b, const float* __restrict__ b1)
{
    extern __shared__ char dsm[];
    uint32_t sb = smem_u32(dsm);
    const uint32_t WOFF = 34816, STOFF = 69632;
    int tid = threadIdx.x;
    int rowBase = blockIdx.x * 128;
    Frag f = mkfrag(tid);

    issue_w(sb, WOFF, g_w116, 128, tid);
    asm volatile("cp.async.commit_group;" ::: "memory");

    ln_to_smem(dsm, g_x2, g, b, rowBase, tid);

    #pragma unroll
    for (int blk = 0; blk < 4; blk++) {
        asm volatile("cp.async.wait_group 0;" ::: "memory");
        __syncthreads();

        float c[4][4][4];
        #pragma unroll
        for (int mf = 0; mf < 4; mf++)
            #pragma unroll
            for (int nf = 0; nf < 4; nf++)
                #pragma unroll
                for (int j = 0; j < 4; j++) c[mf][nf][j] = 0.f;

        g128_mma(sb, 0, WOFF, f, c);
        __syncthreads();
        if (blk < 3) {
            issue_w(sb, WOFF, g_w116 + (size_t)(blk + 1) * 128 * 128, 128, tid);
            asm volatile("cp.async.commit_group;" ::: "memory");
        }

        OpBiasRelu op; op.b1b = b1 + blk * 128;
        stage_tile(sb, STOFF, f, c, op);
        __syncthreads();

        #pragma unroll
        for (int i = 0; i < 8; i++) {
            int idx = tid + i * 256;
            int r = idx >> 4, c16 = idx & 15;
            uint4 v = *(const uint4*)(dsm + STOFF + r * 272 + c16 * 16);
            *(uint4*)(g_ff16 + (size_t)(rowBase + r) * 512 + blk * 128 + c16 * 8) = v;
        }
    }
}

// ---------------- FFN2: K=512 chunked fp16 GEMM + bias + residual ----------
#define FFN2_SMEM 73728
__device__ __forceinline__ void ffn2_issue(uint32_t sb, int st, int ch, int rowBase, int tid)
{
    #pragma unroll
    for (int i = 0; i < 4; i++) {
        int idx = tid + i * 256;
        int r = idx >> 3, cc = idx & 7;
        cp16(sb + st * 18432 + r * 144 + cc * 16,
             g_ff16 + (size_t)(rowBase + r) * 512 + ch * 64 + cc * 8);
        cp16(sb + 36864 + st * 18432 + r * 144 + cc * 16,
             g_w216 + (size_t)r * 512 + ch * 64 + cc * 8);
    }
    asm volatile("cp.async.commit_group;" ::: "memory");
}

__global__ __launch_bounds__(256, 2) void k_ffn2(
    const float* __restrict__ b2, float* __restrict__ out)
{
    extern __shared__ char dsm[];
    uint32_t sb = smem_u32(dsm);
    int tid = threadIdx.x, lane = tid & 31, wid = tid >> 5;
    int rowBase = blockIdx.x * 128;
    int mBase = (wid >> 2) * 64, nBase = (wid & 3) * 32;
    int g8 = lane & 7, sel = (lane >> 3) & 1, hi = lane >> 4;

    float c[4][4][4];
    #pragma unroll
    for (int mf = 0; mf < 4; mf++)
        #pragma unroll
        for (int nf = 0; nf < 4; nf++)
            #pragma unroll
            for (int j = 0; j < 4; j++) c[mf][nf][j] = 0.f;

    ffn2_issue(sb, 0, 0, rowBase, tid);

    for (int ch = 0; ch < 8; ch++) {
        int st = ch & 1;
        if (ch < 7) {
            ffn2_issue(sb, st ^ 1, ch + 1, rowBase, tid);
            asm volatile("cp.async.wait_group 1;" ::: "memory");
        } else {
            asm volatile("cp.async.wait_group 0;" ::: "memory");
        }
        __syncthreads();

        uint32_t aB = sb + st * 18432 + ((mBase + g8 + sel * 8) * 72 + hi * 8) * 2;
        uint32_t bB = sb + 36864 + st * 18432 + ((nBase + g8 + hi * 8) * 72 + sel * 8) * 2;

        #pragma unroll
        for (int ks = 0; ks < 4; ks++) {
            uint32_t a[4][4];
            #pragma unroll
            for (int mf = 0; mf < 4; mf++)
                ldsm4(a[mf], aB + mf * 2304 + ks * 32);
            uint32_t bq[2][4];
            #pragma unroll
            for (int p = 0; p < 2; p++)
                ldsm4(bq[p], bB + p * 2304 + ks * 32);
            #pragma unroll
            for (int mf = 0; mf < 4; mf++)
                #pragma unroll
                for (int nf = 0; nf < 4; nf++)
                    mma_f16(c[mf][nf], a[mf][0], a[mf][1], a[mf][2], a[mf][3],
                            bq[nf >> 1][(nf & 1) * 2], bq[nf >> 1][(nf & 1) * 2 + 1]);
        }
        __syncthreads();
    }

    int eg = lane >> 2, et = lane & 3;
    #pragma unroll
    for (int mf = 0; mf < 4; mf++)
        #pragma unroll
        for (int rr = 0; rr < 2; rr++) {
            int row = rowBase + mBase + mf * 16 + eg + rr * 8;
            #pragma unroll
            for (int nf = 0; nf < 4; nf++) {
                int col = nBase + nf * 8 + 2 * et;
                float2 bb = *(const float2*)(b2 + col);
                float2 rv = *(const float2*)(g_x2 + (size_t)row * 128 + col);
                *(float2*)(out + (size_t)row * 128 + col) =
                    make_float2(c[mf][nf][rr * 2]     + bb.x + rv.x,
                                c[mf][nf][rr * 2 + 1] + bb.y + rv.y);
            }
        }
}

// ---------------- launch ----------------
extern "C" void kernel_launch(void* const* d_in, const int* in_sizes, int n_in,
                              void* d_out, int out_size)
{
    const float* x     = (const float*)d_in[0];
    const float* ln1_g = (const float*)d_in[1];
    const float* ln1_b = (const float*)d_in[2];
    const float* Wq    = (const float*)d_in[3];
    const float* Wk    = (const float*)d_in[4];
    const float* Wv    = (const float*)d_in[5];
    const float* Wo    = (const float*)d_in[6];
    const float* bo    = (const float*)d_in[7];
    const float* ln2_g = (const float*)d_in[8];
    const float* ln2_b = (const float*)d_in[9];
    const float* W1    = (const float*)d_in[10];
    const float* b1    = (const float*)d_in[11];
    const float* W2    = (const float*)d_in[12];
    const float* b2    = (const float*)d_in[13];
    float* out = (float*)d_out;

    static bool attrs_set = false;
    if (!attrs_set) {
        cudaFuncSetAttribute(k_qkv3,   cudaFuncAttributeMaxDynamicSharedMemorySize, QKV_SMEM);
        cudaFuncSetAttribute(k_attnwo, cudaFuncAttributeMaxDynamicSharedMemorySize, ATTNWO_SMEM);
        cudaFuncSetAttribute(k_ffn1,   cudaFuncAttributeMaxDynamicSharedMemorySize, FFN1_SMEM);
        cudaFuncSetAttribute(k_ffn2,   cudaFuncAttributeMaxDynamicSharedMemorySize, FFN2_SMEM);
        attrs_set = true;
    }

    // 0) weights -> fp16
    cvt6<<<dim3(32, 6), 256>>>(Wq, Wk, Wv, Wo, W1, W2);

    // 1) LN1 + QKV
    k_qkv3<<<BT / 128, 256, QKV_SMEM>>>(x, ln1_g, ln1_b);

    // 2) attention (4 heads) + Wo + bo + residual -> x2
    k_attnwo<<<Bv, 256, ATTNWO_SMEM>>>(x, bo);

    // 3) LN2 + FFN1
    k_ffn1<<<BT / 128, 256, FFN1_SMEM>>>(ln2_g, ln2_b, b1);

    // 4) out = ff @ W2^T + b2 + x2
    k_ffn2<<<BT / 128, 256, FFN2_SMEM>>>(b2, out);
}

// round 11
// speedup vs baseline: 4.7587x; 1.0681x over previous
#include <cuda_runtime.h>
#include <cuda_fp16.h>
#include <cstdint>
#include <math.h>

#define Bv   1024
#define Tv   128
#define Dv   128
#define Hv   4
#define HDv  32
#define FFv  512
#define BT   (Bv*Tv)
#define SCALE 0.08838834764831845f   // 128^-0.5

// ---------------- scratch (device globals) ----------------
__device__ __align__(256) __half g_q16 [BT*Dv];
__device__ __align__(256) __half g_k16 [BT*Dv];
__device__ __align__(256) __half g_v16 [BT*Dv];
__device__ __align__(256) float  g_x2  [BT*Dv];
__device__ __align__(256) __half g_wq16[Dv*Dv];
__device__ __align__(256) __half g_wk16[Dv*Dv];
__device__ __align__(256) __half g_wv16[Dv*Dv];
__device__ __align__(256) __half g_wo16[Dv*Dv];
__device__ __align__(256) __half g_w116[FFv*Dv];
__device__ __align__(256) __half g_w216[Dv*FFv];

// ---------------- PTX helpers ----------------
__device__ __forceinline__ uint32_t smem_u32(const void* p) {
    uint32_t a;
    asm("{ .reg .u64 t; cvta.to.shared.u64 t, %1; cvt.u32.u64 %0, t; }" : "=r"(a) : "l"(p));
    return a;
}
__device__ __forceinline__ void cp16(uint32_t dst, const void* src) {
    asm volatile("cp.async.cg.shared.global [%0], [%1], 16;" :: "r"(dst), "l"(src));
}
__device__ __forceinline__ void ldsm4(uint32_t (&r)[4], uint32_t addr) {
    asm volatile("ldmatrix.sync.aligned.m8n8.x4.shared.b16 {%0,%1,%2,%3}, [%4];"
        : "=r"(r[0]), "=r"(r[1]), "=r"(r[2]), "=r"(r[3]) : "r"(addr));
}
__device__ __forceinline__ void ldsm4t(uint32_t (&r)[4], uint32_t addr) {
    asm volatile("ldmatrix.sync.aligned.m8n8.x4.trans.shared.b16 {%0,%1,%2,%3}, [%4];"
        : "=r"(r[0]), "=r"(r[1]), "=r"(r[2]), "=r"(r[3]) : "r"(addr));
}
__device__ __forceinline__ void stsm4(uint32_t addr, uint32_t r0, uint32_t r1,
                                      uint32_t r2, uint32_t r3) {
    asm volatile("stmatrix.sync.aligned.m8n8.x4.shared.b16 [%0], {%1,%2,%3,%4};"
        :: "r"(addr), "r"(r0), "r"(r1), "r"(r2), "r"(r3) : "memory");
}
__device__ __forceinline__ void mma_f16(float* c,
    uint32_t a0, uint32_t a1, uint32_t a2, uint32_t a3, uint32_t b0, uint32_t b1)
{
    asm volatile(
        "mma.sync.aligned.m16n8k16.row.col.f32.f16.f16.f32 "
        "{%0,%1,%2,%3}, {%4,%5,%6,%7}, {%8,%9}, {%0,%1,%2,%3};"
        : "+f"(c[0]), "+f"(c[1]), "+f"(c[2]), "+f"(c[3])
        : "r"(a0), "r"(a1), "r"(a2), "r"(a3), "r"(b0), "r"(b1));
}
__device__ __forceinline__ uint32_t h2u(float a, float b) {
    __half2 h = __floats2half2_rn(a, b);
    return *(uint32_t*)&h;
}

// epilogue functors
struct OpNone {
    __device__ __forceinline__ void operator()(float&, float&, float&, float&, int) const {}
};
struct OpBiasRelu {
    const float* b1b;
    __device__ __forceinline__ void operator()(float& v0, float& v1, float& v2,
                                               float& v3, int col) const {
        float2 bb = *(const float2*)(b1b + col);
        v0 = fmaxf(v0 + bb.x, 0.f); v1 = fmaxf(v1 + bb.y, 0.f);
        v2 = fmaxf(v2 + bb.x, 0.f); v3 = fmaxf(v3 + bb.y, 0.f);
    }
};

// ---------------- weight fp32 -> fp16 conversion ----------------
__global__ void cvt6(const float* __restrict__ wq, const float* __restrict__ wk,
                     const float* __restrict__ wv, const float* __restrict__ wo,
                     const float* __restrict__ w1, const float* __restrict__ w2)
{
    const float* src; __half* dst; int n;
    switch (blockIdx.y) {
        case 0: src = wq; dst = g_wq16; n = Dv*Dv;  break;
        case 1: src = wk; dst = g_wk16; n = Dv*Dv;  break;
        case 2: src = wv; dst = g_wv16; n = Dv*Dv;  break;
        case 3: src = wo; dst = g_wo16; n = Dv*Dv;  break;
        case 4: src = w1; dst = g_w116; n = FFv*Dv; break;
        default: src = w2; dst = g_w216; n = Dv*FFv; break;
    }
    for (int i = blockIdx.x * blockDim.x + threadIdx.x; i < n; i += gridDim.x * blockDim.x)
        dst[i] = __float2half_rn(src[i]);
}

// ============ shared pieces (tiles half[.][136], row stride 272B) ==========
struct Frag { int g8, sel, hi, eg, et, mBase, nBase; };
__device__ __forceinline__ Frag mkfrag(int tid) {          // 128-row layout
    Frag f;
    int lane = tid & 31, wid = tid >> 5;
    f.g8 = lane & 7; f.sel = (lane >> 3) & 1; f.hi = lane >> 4;
    f.eg = lane >> 2; f.et = lane & 3;
    f.mBase = (wid >> 2) * 64; f.nBase = (wid & 3) * 32;
    return f;
}
__device__ __forceinline__ Frag mkfrag64(int tid) {        // 64-row layout
    Frag f;
    int lane = tid & 31, wid = tid >> 5;
    f.g8 = lane & 7; f.sel = (lane >> 3) & 1; f.hi = lane >> 4;
    f.eg = lane >> 2; f.et = lane & 3;
    f.mBase = (wid >> 2) * 32; f.nBase = (wid & 3) * 32;
    return f;
}

__device__ __forceinline__ void g128_mma(uint32_t sb, uint32_t aoff, uint32_t woff,
                                         const Frag& f, float c[4][4][4])
{
    uint32_t aBase = sb + aoff + ((f.mBase + f.g8 + f.sel * 8) * 136 + f.hi * 8) * 2;
    uint32_t bBase = sb + woff + ((f.nBase + f.g8 + f.hi * 8) * 136 + f.sel * 8) * 2;
    #pragma unroll
    for (int ks = 0; ks < 8; ks++) {
        uint32_t a[4][4];
        #pragma unroll
        for (int mf = 0; mf < 4; mf++)
            ldsm4(a[mf], aBase + mf * 4352 + ks * 32);
        uint32_t bq[2][4];
        #pragma unroll
        for (int p = 0; p < 2; p++)
            ldsm4(bq[p], bBase + p * 4352 + ks * 32);
        #pragma unroll
        for (int mf = 0; mf < 4; mf++)
            #pragma unroll
            for (int nf = 0; nf < 4; nf++)
                mma_f16(c[mf][nf], a[mf][0], a[mf][1], a[mf][2], a[mf][3],
                        bq[nf >> 1][(nf & 1) * 2], bq[nf >> 1][(nf & 1) * 2 + 1]);
    }
}

// 64-row × 128-col × K=128 warp GEMM (warp tile 32x32)
__device__ __forceinline__ void g64_mma(uint32_t sb, uint32_t aoff, uint32_t woff,
                                        const Frag& f, float c[2][4][4])
{
    uint32_t aBase = sb + aoff + ((f.mBase + f.g8 + f.sel * 8) * 136 + f.hi * 8) * 2;
    uint32_t bBase = sb + woff + ((f.nBase + f.g8 + f.hi * 8) * 136 + f.sel * 8) * 2;
    #pragma unroll
    for (int ks = 0; ks < 8; ks++) {
        uint32_t a[2][4];
        #pragma unroll
        for (int mf = 0; mf < 2; mf++)
            ldsm4(a[mf], aBase + mf * 4352 + ks * 32);
        uint32_t bq[2][4];
        #pragma unroll
        for (int p = 0; p < 2; p++)
            ldsm4(bq[p], bBase + p * 4352 + ks * 32);
        #pragma unroll
        for (int mf = 0; mf < 2; mf++)
            #pragma unroll
            for (int nf = 0; nf < 4; nf++)
                mma_f16(c[mf][nf], a[mf][0], a[mf][1], a[mf][2], a[mf][3],
                        bq[nf >> 1][(nf & 1) * 2], bq[nf >> 1][(nf & 1) * 2 + 1]);
    }
}

// LN of 128 fp32 cols into smem tile @0 (128 rows, 2 thr/row)
__device__ __forceinline__ void ln_to_smem(char* dsm, const float* __restrict__ X,
    const float* __restrict__ lng, const float* __restrict__ lnb, int rowBase, int tid)
{
    int row = tid >> 1, hf = tid & 1;
    const float* xr = X + (size_t)(rowBase + row) * 128 + hf * 64;
    float s = 0.f, s2 = 0.f;
    #pragma unroll
    for (int i = 0; i < 16; i++) {
        float4 v = *(const float4*)(xr + i * 4);
        s  += v.x + v.y + v.z + v.w;
        s2 += v.x * v.x + v.y * v.y + v.z * v.z + v.w * v.w;
    }
    s  += __shfl_xor_sync(0xffffffffu, s, 1);
    s2 += __shfl_xor_sync(0xffffffffu, s2, 1);
    float mu = s * (1.f / 128.f);
    float rstd = rsqrtf(s2 * (1.f / 128.f) - mu * mu + 1e-5f);
    #pragma unroll
    for (int i = 0; i < 16; i++) {
        float4 v = *(const float4*)(xr + i * 4);
        int col = hf * 64 + i * 4;
        float4 gg = *(const float4*)(lng + col);
        float4 bb = *(const float4*)(lnb + col);
        *(uint32_t*)(dsm + row * 272 + col * 2)     = h2u((v.x - mu) * rstd * gg.x + bb.x,
                                                          (v.y - mu) * rstd * gg.y + bb.y);
        *(uint32_t*)(dsm + row * 272 + col * 2 + 4) = h2u((v.z - mu) * rstd * gg.z + bb.z,
                                                          (v.w - mu) * rstd * gg.w + bb.w);
    }
}

// LN for a 64-row tile (4 thr/row)
__device__ __forceinline__ void ln64_to_smem(char* dsm, const float* __restrict__ X,
    const float* __restrict__ lng, const float* __restrict__ lnb, int rowBase, int tid)
{
    int row = tid >> 2, qt = tid & 3;
    const float* xr = X + (size_t)(rowBase + row) * 128 + qt * 32;
    float s = 0.f, s2 = 0.f;
    #pragma unroll
    for (int i = 0; i < 8; i++) {
        float4 v = *(const float4*)(xr + i * 4);
        s  += v.x + v.y + v.z + v.w;
        s2 += v.x * v.x + v.y * v.y + v.z * v.z + v.w * v.w;
    }
    s  += __shfl_xor_sync(0xffffffffu, s, 1);
    s  += __shfl_xor_sync(0xffffffffu, s, 2);
    s2 += __shfl_xor_sync(0xffffffffu, s2, 1);
    s2 += __shfl_xor_sync(0xffffffffu, s2, 2);
    float mu = s * (1.f / 128.f);
    float rstd = rsqrtf(s2 * (1.f / 128.f) - mu * mu + 1e-5f);
    #pragma unroll
    for (int i = 0; i < 8; i++) {
        float4 v = *(const float4*)(xr + i * 4);
        int col = qt * 32 + i * 4;
        float4 gg = *(const float4*)(lng + col);
        float4 bb = *(const float4*)(lnb + col);
        *(uint32_t*)(dsm + row * 272 + col * 2)     = h2u((v.x - mu) * rstd * gg.x + bb.x,
                                                          (v.y - mu) * rstd * gg.y + bb.y);
        *(uint32_t*)(dsm + row * 272 + col * 2 + 4) = h2u((v.z - mu) * rstd * gg.z + bb.z,
                                                          (v.w - mu) * rstd * gg.w + bb.w);
    }
}

__device__ __forceinline__ void issue_w(uint32_t sb, uint32_t off,
                                        const __half* __restrict__ W, int ldw, int tid)
{
    #pragma unroll
    for (int i = 0; i < 8; i++) {
        int idx = tid + i * 256;
        int r = idx >> 4, cc = idx & 15;
        cp16(sb + off + r * 272 + cc * 16, W + (size_t)r * ldw + cc * 8);
    }
}

// stmatrix a 128-row (4 mf) or 64-row (2 mf) warp tile into stage buffer
template<int MF, typename OP>
__device__ __forceinline__ void stage_tile(uint32_t sb, uint32_t stoff, const Frag& f,
                                           float c[MF][4][4], OP op)
{
    uint32_t base = sb + stoff + ((f.mBase + f.g8 + f.sel * 8) * 136 + f.nBase + f.hi * 8) * 2;
    #pragma unroll
    for (int mf = 0; mf < MF; mf++) {
        uint32_t pk[4][2];
        #pragma unroll
        for (int nf = 0; nf < 4; nf++) {
            float v0 = c[mf][nf][0], v1 = c[mf][nf][1];
            float v2 = c[mf][nf][2], v3 = c[mf][nf][3];
            op(v0, v1, v2, v3, f.nBase + nf * 8 + 2 * f.et);
            pk[nf][0] = h2u(v0, v1);
            pk[nf][1] = h2u(v2, v3);
        }
        #pragma unroll
        for (int jj = 0; jj < 2; jj++)
            stsm4(base + mf * 4352 + jj * 32,
                  pk[2*jj][0], pk[2*jj][1], pk[2*jj+1][0], pk[2*jj+1][1]);
    }
}

// ---------------- fused LN1 + QKV (unchanged from R10) ---------------------
#define QKV_SMEM 104448
__global__ __launch_bounds__(256, 2) void k_qkv3(
    const float* __restrict__ x, const float* __restrict__ g, const float* __restrict__ b)
{
    extern __shared__ char dsm[];
    uint32_t sb = smem_u32(dsm);
    const uint32_t WOFF = 34816, STOFF = 69632;
    int tid = threadIdx.x;
    int rowBase = blockIdx.x * 128;
    Frag f = mkfrag(tid);

    issue_w(sb, WOFF, g_wq16, 128, tid);
    asm volatile("cp.async.commit_group;" ::: "memory");

    ln_to_smem(dsm, x, g, b, rowBase, tid);

    const __half* Wn[2] = { g_wk16, g_wv16 };
    __half* outs[3];
    outs[0] = g_q16; outs[1] = g_k16; outs[2] = g_v16;

    #pragma unroll
    for (int wsel = 0; wsel < 3; wsel++) {
        asm volatile("cp.async.wait_group 0;" ::: "memory");
        __syncthreads();

        float c[4][4][4];
        #pragma unroll
        for (int mf = 0; mf < 4; mf++)
            #pragma unroll
            for (int nf = 0; nf < 4; nf++)
                #pragma unroll
                for (int j = 0; j < 4; j++) c[mf][nf][j] = 0.f;

        g128_mma(sb, 0, WOFF, f, c);
        __syncthreads();
        if (wsel < 2) {
            issue_w(sb, WOFF, Wn[wsel], 128, tid);
            asm volatile("cp.async.commit_group;" ::: "memory");
        }

        stage_tile<4>(sb, STOFF, f, c, OpNone());
        __syncthreads();

        __half* C = outs[wsel];
        #pragma unroll
        for (int i = 0; i < 8; i++) {
            int idx = tid + i * 256;
            int r = idx >> 4, c16 = idx & 15;
            uint4 v = *(const uint4*)(dsm + STOFF + r * 272 + c16 * 16);
            *(uint4*)(C + (size_t)(rowBase + r) * 128 + c16 * 8) = v;
        }
    }
}

// ---------------- fused attention (4 heads) + Wo + residual (unchanged) ----
#define ATTNWO_SMEM 104448
__global__ __launch_bounds__(256, 2) void k_attnwo(
    const float* __restrict__ x, const float* __restrict__ bo)
{
    extern __shared__ char dsm[];
    uint32_t sb = smem_u32(dsm);
    const uint32_t VOFF = 34816, AOFF = 69632;
    int b = blockIdx.x;
    int tid = threadIdx.x, lane = tid & 31, w = tid >> 5;
    int g8 = lane & 7, sel = (lane >> 3) & 1, hi8 = (lane >> 4) * 8;
    int eg = lane >> 2, et = lane & 3;
    int tq0 = w * 16;
    size_t base = (size_t)b * Tv * Dv;

    #pragma unroll
    for (int i = 0; i < 8; i++) {
        int idx = tid + i * 256;
        int r = idx >> 4, cc = idx & 15;
        cp16(sb + r * 272 + cc * 16,        g_k16 + base + (size_t)r * 128 + cc * 8);
        cp16(sb + VOFF + r * 272 + cc * 16, g_v16 + base + (size_t)r * 128 + cc * 8);
    }
    asm volatile("cp.async.commit_group;" ::: "memory");
    asm volatile("cp.async.wait_group 0;" ::: "memory");
    __syncthreads();

    const __half* qb = g_q16 + base;
    int r0 = tq0 + eg, r1 = r0 + 8;

    #pragma unroll
    for (int hh = 0; hh < 4; hh++) {
        float sacc[16][4];
        #pragma unroll
        for (int cn = 0; cn < 16; cn++)
            #pragma unroll
            for (int j = 0; j < 4; j++) sacc[cn][j] = 0.f;

        #pragma unroll
        for (int ks = 0; ks < 2; ks++) {
            int kc = hh * 32 + ks * 16 + 2 * et;
            uint32_t a0 = *(const uint32_t*)(qb + (size_t)r0 * 128 + kc);
            uint32_t a1 = *(const uint32_t*)(qb + (size_t)r1 * 128 + kc);
            uint32_t a2 = *(const uint32_t*)(qb + (size_t)r0 * 128 + kc + 8);
            uint32_t a3 = *(const uint32_t*)(qb + (size_t)r1 * 128 + kc + 8);
            #pragma unroll
            for (int p = 0; p < 8; p++) {
                uint32_t bq[4];
                ldsm4(bq, sb + ((p * 16 + g8 + hi8) * 136 + hh * 32 + sel * 8 + ks * 16) * 2);
                mma_f16(sacc[2 * p],     a0, a1, a2, a3, bq[0], bq[1]);
                mma_f16(sacc[2 * p + 1], a0, a1, a2, a3, bq[2], bq[3]);
            }
        }

        #pragma unroll
        for (int cn = 0; cn < 16; cn++) {
            int c0 = cn * 8 + 2 * et;
            sacc[cn][0] = (c0     <= r0) ? sacc[cn][0] * SCALE : -1e30f;
            sacc[cn][1] = (c0 + 1 <= r0) ? sacc[cn][1] * SCALE : -1e30f;
            sacc[cn][2] = (c0     <= r1) ? sacc[cn][2] * SCALE : -1e30f;
            sacc[cn][3] = (c0 + 1 <= r1) ? sacc[cn][3] * SCALE : -1e30f;
        }

        float m0 = -1e30f, m1 = -1e30f;
        #pragma unroll
        for (int cn = 0; cn < 16; cn++) {
            m0 = fmaxf(m0, fmaxf(sacc[cn][0], sacc[cn][1]));
            m1 = fmaxf(m1, fmaxf(sacc[cn][2], sacc[cn][3]));
        }
        m0 = fmaxf(m0, __shfl_xor_sync(0xffffffffu, m0, 1));
        m0 = fmaxf(m0, __shfl_xor_sync(0xffffffffu, m0, 2));
        m1 = fmaxf(m1, __shfl_xor_sync(0xffffffffu, m1, 1));
        m1 = fmaxf(m1, __shfl_xor_sync(0xffffffffu, m1, 2));

        float l0 = 0.f, l1 = 0.f;
        #pragma unroll
        for (int cn = 0; cn < 16; cn++) {
            sacc[cn][0] = __expf(sacc[cn][0] - m0);
            sacc[cn][1] = __expf(sacc[cn][1] - m0);
            sacc[cn][2] = __expf(sacc[cn][2] - m1);
            sacc[cn][3] = __expf(sacc[cn][3] - m1);
            l0 += sacc[cn][0] + sacc[cn][1];
            l1 += sacc[cn][2] + sacc[cn][3];
        }
        l0 += __shfl_xor_sync(0xffffffffu, l0, 1);
        l0 += __shfl_xor_sync(0xffffffffu, l0, 2);
        l1 += __shfl_xor_sync(0xffffffffu, l1, 1);
        l1 += __shfl_xor_sync(0xffffffffu, l1, 2);
        float inv0 = 1.f / l0, inv1 = 1.f / l1;

        float oacc[4][4];
        #pragma unroll
        for (int nf = 0; nf < 4; nf++)
            #pragma unroll
            for (int j = 0; j < 4; j++) oacc[nf][j] = 0.f;

        #pragma unroll
        for (int ks = 0; ks < 8; ks++) {
            uint32_t a0 = h2u(sacc[2*ks][0],   sacc[2*ks][1]);
            uint32_t a1 = h2u(sacc[2*ks][2],   sacc[2*ks][3]);
            uint32_t a2 = h2u(sacc[2*ks+1][0], sacc[2*ks+1][1]);
            uint32_t a3 = h2u(sacc[2*ks+1][2], sacc[2*ks+1][3]);
            #pragma unroll
            for (int nb = 0; nb < 2; nb++) {
                uint32_t bq[4];
                ldsm4t(bq, sb + VOFF +
                    ((ks * 16 + g8 + sel * 8) * 136 + hh * 32 + nb * 16 + hi8) * 2);
                mma_f16(oacc[nb * 2],     a0, a1, a2, a3, bq[0], bq[1]);
                mma_f16(oacc[nb * 2 + 1], a0, a1, a2, a3, bq[2], bq[3]);
            }
        }

        #pragma unroll
        for (int nf = 0; nf < 4; nf++) {
            int col = hh * 32 + nf * 8 + 2 * et;
            *(uint32_t*)(dsm + AOFF + ((size_t)r0 * 136 + col) * 2) =
                h2u(oacc[nf][0] * inv0, oacc[nf][1] * inv0);
            *(uint32_t*)(dsm + AOFF + ((size_t)r1 * 136 + col) * 2) =
                h2u(oacc[nf][2] * inv1, oacc[nf][3] * inv1);
        }
    }
    __syncthreads();

    #pragma unroll
    for (int i = 0; i < 8; i++) {
        int idx = tid + i * 256;
        int r = idx >> 4, cc = idx & 15;
        cp16(sb + r * 272 + cc * 16, g_wo16 + (size_t)r * 128 + cc * 8);
    }
    asm volatile("cp.async.commit_group;" ::: "memory");
    asm volatile("cp.async.wait_group 0;" ::: "memory");
    __syncthreads();

    float c[16][4];
    #pragma unroll
    for (int nf = 0; nf < 16; nf++)
        #pragma unroll
        for (int j = 0; j < 4; j++) c[nf][j] = 0.f;

    uint32_t aB = sb + AOFF + ((tq0 + g8 + sel * 8) * 136 + hi8) * 2;
    uint32_t bB = sb + ((g8 + hi8) * 136 + sel * 8) * 2;
    #pragma unroll
    for (int ks = 0; ks < 8; ks++) {
        uint32_t a[4];
        ldsm4(a, aB + ks * 32);
        #pragma unroll
        for (int p = 0; p < 8; p++) {
            uint32_t bq[4];
            ldsm4(bq, bB + p * 4352 + ks * 32);
            mma_f16(c[2 * p],     a[0], a[1], a[2], a[3], bq[0], bq[1]);
            mma_f16(c[2 * p + 1], a[0], a[1], a[2], a[3], bq[2], bq[3]);
        }
    }

    int grow0 = b * 128 + r0, grow1 = b * 128 + r1;
    #pragma unroll
    for (int nf = 0; nf < 16; nf++) {
        int col = nf * 8 + 2 * et;
        float2 bb = *(const float2*)(bo + col);
        float2 xv0 = *(const float2*)(x + (size_t)grow0 * 128 + col);
        float2 xv1 = *(const float2*)(x + (size_t)grow1 * 128 + col);
        *(float2*)(g_x2 + (size_t)grow0 * 128 + col) =
            make_float2(c[nf][0] + bb.x + xv0.x, c[nf][1] + bb.y + xv0.y);
        *(float2*)(g_x2 + (size_t)grow1 * 128 + col) =
            make_float2(c[nf][2] + bb.x + xv1.x, c[nf][3] + bb.y + xv1.y);
    }
}

// ---------------- fused FFN (M=64 tile, occ 2, no gmem ff round trip) ------
// smem: A @0 (17408), FF @17408 (17408), W1 @34816 (34816), W2 @69632 (34816)
#define FFN_SMEM 104448
__global__ __launch_bounds__(256, 2) void k_ffn64(
    const float* __restrict__ g, const float* __restrict__ b,
    const float* __restrict__ b1, const float* __restrict__ b2,
    float* __restrict__ out)
{
    extern __shared__ char dsm[];
    uint32_t sb = smem_u32(dsm);
    const uint32_t FFO = 17408, W1OFF = 34816, W2OFF = 69632;
    int tid = threadIdx.x;
    int rowBase = blockIdx.x * 64;
    Frag f = mkfrag64(tid);

    // prefetch W1(0), W2(0) as two groups
    issue_w(sb, W1OFF, g_w116, 128, tid);
    asm volatile("cp.async.commit_group;" ::: "memory");
    issue_w(sb, W2OFF, g_w216, 512, tid);
    asm volatile("cp.async.commit_group;" ::: "memory");

    ln64_to_smem(dsm, g_x2, g, b, rowBase, tid);

    float c2[2][4][4];
    #pragma unroll
    for (int mf = 0; mf < 2; mf++)
        #pragma unroll
        for (int nf = 0; nf < 4; nf++)
            #pragma unroll
            for (int j = 0; j < 4; j++) c2[mf][nf][j] = 0.f;

    #pragma unroll
    for (int blk = 0; blk < 4; blk++) {
        // need W1(blk): oldest outstanding; allow W2(blk) in flight
        asm volatile("cp.async.wait_group 1;" ::: "memory");
        __syncthreads();

        float c1[2][4][4];
        #pragma unroll
        for (int mf = 0; mf < 2; mf++)
            #pragma unroll
            for (int nf = 0; nf < 4; nf++)
                #pragma unroll
                for (int j = 0; j < 4; j++) c1[mf][nf][j] = 0.f;
        g64_mma(sb, 0, W1OFF, f, c1);
        __syncthreads();                 // W1 buffer free, prev FF consumed

        if (blk < 3) {
            issue_w(sb, W1OFF, g_w116 + (size_t)(blk + 1) * 128 * 128, 128, tid);
            asm volatile("cp.async.commit_group;" ::: "memory");
        }

        OpBiasRelu op; op.b1b = b1 + blk * 128;
        stage_tile<2>(sb, FFO, f, c1, op);

        // need W2(blk): allow W1(blk+1) in flight
        if (blk < 3) asm volatile("cp.async.wait_group 1;" ::: "memory");
        else         asm volatile("cp.async.wait_group 0;" ::: "memory");
        __syncthreads();                 // FF visible + W2 ready

        g64_mma(sb, FFO, W2OFF, f, c2);  // accumulate FFN2 partial
        __syncthreads();                 // W2 buffer free

        if (blk < 3) {
            issue_w(sb, W2OFF, g_w216 + (size_t)(blk + 1) * 128, 512, tid);
            asm volatile("cp.async.commit_group;" ::: "memory");
        }
    }

    // epilogue: + b2 + x2 residual -> out (fp32)
    #pragma unroll
    for (int mf = 0; mf < 2; mf++)
        #pragma unroll
        for (int rr = 0; rr < 2; rr++) {
            int row = rowBase + f.mBase + mf * 16 + f.eg + rr * 8;
            #pragma unroll
            for (int nf = 0; nf < 4; nf++) {
                int col = f.nBase + nf * 8 + 2 * f.et;
                float2 bb = *(const float2*)(b2 + col);
                float2 rv = *(const float2*)(g_x2 + (size_t)row * 128 + col);
                *(float2*)(out + (size_t)row * 128 + col) =
                    make_float2(c2[mf][nf][rr * 2]     + bb.x + rv.x,
                                c2[mf][nf][rr * 2 + 1] + bb.y + rv.y);
            }
        }
}

// ---------------- launch ----------------
extern "C" void kernel_launch(void* const* d_in, const int* in_sizes, int n_in,
                              void* d_out, int out_size)
{
    const float* x     = (const float*)d_in[0];
    const float* ln1_g = (const float*)d_in[1];
    const float* ln1_b = (const float*)d_in[2];
    const float* Wq    = (const float*)d_in[3];
    const float* Wk    = (const float*)d_in[4];
    const float* Wv    = (const float*)d_in[5];
    const float* Wo    = (const float*)d_in[6];
    const float* bo    = (const float*)d_in[7];
    const float* ln2_g = (const float*)d_in[8];
    const float* ln2_b = (const float*)d_in[9];
    const float* W1    = (const float*)d_in[10];
    const float* b1    = (const float*)d_in[11];
    const float* W2    = (const float*)d_in[12];
    const float* b2    = (const float*)d_in[13];
    float* out = (float*)d_out;

    static bool attrs_set = false;
    if (!attrs_set) {
        cudaFuncSetAttribute(k_qkv3,   cudaFuncAttributeMaxDynamicSharedMemorySize, QKV_SMEM);
        cudaFuncSetAttribute(k_attnwo, cudaFuncAttributeMaxDynamicSharedMemorySize, ATTNWO_SMEM);
        cudaFuncSetAttribute(k_ffn64,  cudaFuncAttributeMaxDynamicSharedMemorySize, FFN_SMEM);
        attrs_set = true;
    }

    // 0) weights -> fp16
    cvt6<<<dim3(32, 6), 256>>>(Wq, Wk, Wv, Wo, W1, W2);

    // 1) LN1 + QKV
    k_qkv3<<<BT / 128, 256, QKV_SMEM>>>(x, ln1_g, ln1_b);

    // 2) attention (4 heads) + Wo + bo + residual -> x2
    k_attnwo<<<Bv, 256, ATTNWO_SMEM>>>(x, bo);

    // 3) LN2 + FFN1 + FFN2 + residual, fully fused at occ 2
    k_ffn64<<<BT / 64, 256, FFN_SMEM>>>(ln2_g, ln2_b, b1, b2, out);
}